// round 9
// baseline (speedup 1.0000x reference)
#include <cuda_runtime.h>
#include <cuda_bf16.h>
#include <cuda_fp16.h>
#include <math.h>
#include <stdint.h>

#define S_LEN 2048
#define EMB   2048
#define NHEAD 16
#define HDIM  128

// ---------------- scratch (no cudaMalloc allowed) ----------------
// packed fp16 GEMM operands (stage-contiguous, swizzled)
__device__ __align__(256) __half g_px [S_LEN * EMB];
__device__ __align__(256) __half g_pao[S_LEN * EMB];
__device__ __align__(256) __half g_pwq[EMB * EMB];
__device__ __align__(256) __half g_pwk[EMB * EMB];
__device__ __align__(256) __half g_pwv[EMB * EMB];
__device__ __align__(256) __half g_pwo[EMB * EMB];

// attention operands (bf16 hi/lo)
__device__ __nv_bfloat16 g_qh [S_LEN * EMB];
__device__ __nv_bfloat16 g_ql [S_LEN * EMB];
__device__ __nv_bfloat16 g_kh [S_LEN * EMB];
__device__ __nv_bfloat16 g_kl [S_LEN * EMB];
__device__ __nv_bfloat16 g_vth[NHEAD * HDIM * S_LEN];   // [h][d][s]
__device__ __nv_bfloat16 g_vtl[NHEAD * HDIM * S_LEN];

// ================= helpers (baseline PTX only) ==============
__device__ __forceinline__ uint32_t s2u(const void* p) {
    uint32_t a;
    asm("{ .reg .u64 t; cvta.to.shared.u64 t, %1; cvt.u32.u64 %0, t; }"
        : "=r"(a) : "l"(p));
    return a;
}

__device__ __forceinline__ void cpa16(uint32_t dst, const void* src) {
    asm volatile("cp.async.cg.shared.global [%0], [%1], 16;" :: "r"(dst), "l"(src));
}
#define CPA_COMMIT() asm volatile("cp.async.commit_group;" ::: "memory")
#define CPA_WAIT1()  asm volatile("cp.async.wait_group 1;" ::: "memory")

__device__ __forceinline__ void ldsm4(uint32_t addr, uint32_t& r0, uint32_t& r1,
                                      uint32_t& r2, uint32_t& r3) {
    asm volatile("ldmatrix.sync.aligned.m8n8.x4.shared.b16 {%0,%1,%2,%3}, [%4];"
                 : "=r"(r0), "=r"(r1), "=r"(r2), "=r"(r3) : "r"(addr));
}

__device__ __forceinline__ void mma_bf16(float* d, const uint32_t* a,
                                         uint32_t b0, uint32_t b1) {
    asm volatile(
        "mma.sync.aligned.m16n8k16.row.col.f32.bf16.bf16.f32 "
        "{%0,%1,%2,%3}, {%4,%5,%6,%7}, {%8,%9}, {%0,%1,%2,%3};"
        : "+f"(d[0]), "+f"(d[1]), "+f"(d[2]), "+f"(d[3])
        : "r"(a[0]), "r"(a[1]), "r"(a[2]), "r"(a[3]), "r"(b0), "r"(b1));
}

__device__ __forceinline__ void mma_f16(float* d, const uint32_t* a,
                                        uint32_t b0, uint32_t b1) {
    asm volatile(
        "mma.sync.aligned.m16n8k16.row.col.f32.f16.f16.f32 "
        "{%0,%1,%2,%3}, {%4,%5,%6,%7}, {%8,%9}, {%0,%1,%2,%3};"
        : "+f"(d[0]), "+f"(d[1]), "+f"(d[2]), "+f"(d[3])
        : "r"(a[0]), "r"(a[1]), "r"(a[2]), "r"(a[3]), "r"(b0), "r"(b1));
}

__device__ __forceinline__ uint32_t b2u(__nv_bfloat162 v) {
    return *reinterpret_cast<uint32_t*>(&v);
}

// ---- mbarrier / bulk-copy (sm_90 baseline PTX) ----
#define MBAR_INIT(mbar, cnt) \
    asm volatile("mbarrier.init.shared.b64 [%0], %1;" \
                 :: "r"((uint32_t)(mbar)), "r"((uint32_t)(cnt)) : "memory")
#define MBAR_EXPECT_TX(mbar, bytes) \
    asm volatile("mbarrier.arrive.expect_tx.shared.b64 _, [%0], %1;" \
                 :: "r"((uint32_t)(mbar)), "r"((uint32_t)(bytes)) : "memory")
#define MBAR_ARRIVE(mbar) \
    asm volatile("mbarrier.arrive.shared.b64 _, [%0];" \
                 :: "r"((uint32_t)(mbar)) : "memory")

__device__ __forceinline__ void mbar_wait(uint32_t mbar, uint32_t phase) {
    asm volatile(
        "{\n\t.reg .pred P1;\n\t"
        "WAIT_LOOP_%=:\n\t"
        "mbarrier.try_wait.parity.acquire.cta.shared::cta.b64 P1, [%0], %1, 0x989680;\n\t"
        "@P1 bra.uni WAIT_DONE_%=;\n\t"
        "bra.uni WAIT_LOOP_%=;\n\t"
        "WAIT_DONE_%=:\n\t}"
        :: "r"(mbar), "r"(phase) : "memory");
}

__device__ __forceinline__ void bulkcp(uint32_t dst, const void* src,
                                       uint32_t bytes, uint32_t mbar) {
    asm volatile(
        "cp.async.bulk.shared::cluster.global.mbarrier::complete_tx::bytes "
        "[%0], [%1], %2, [%3];"
        :: "r"(dst), "l"(src), "r"(bytes), "r"(mbar) : "memory");
}

// ================= repack fp32 -> fp16, stage-contiguous + XOR swizzle ====
__device__ __forceinline__ void pack_row(
    const float* __restrict__ src, __half* __restrict__ dst,
    int r, int t, int blkrows)
{
    const int ks  = t >> 3;
    const int cs  = t & 7;
    const int rin = r & (blkrows - 1);
    const int blk = r / blkrows;
    const int c   = cs ^ (rin & 7);

    const float* s = src + (size_t)r * EMB + ks * 64 + c * 8;
    float4 v0 = *(const float4*)(s);
    float4 v1 = *(const float4*)(s + 4);

    __half2 h0 = __floats2half2_rn(v0.x, v0.y);
    __half2 h1 = __floats2half2_rn(v0.z, v0.w);
    __half2 h2 = __floats2half2_rn(v1.x, v1.y);
    __half2 h3 = __floats2half2_rn(v1.z, v1.w);

    size_t chunk = ((size_t)(blk * 32 + ks) * blkrows + rin) * 8 + cs;
    uint4 out;
    out.x = *reinterpret_cast<uint32_t*>(&h0);
    out.y = *reinterpret_cast<uint32_t*>(&h1);
    out.z = *reinterpret_cast<uint32_t*>(&h2);
    out.w = *reinterpret_cast<uint32_t*>(&h3);
    *(reinterpret_cast<uint4*>(dst) + chunk) = out;
}

__global__ __launch_bounds__(256) void conv_pack(
    const float* __restrict__ src, __half* __restrict__ dst, int blkrows)
{
    pack_row(src, dst, blockIdx.x, threadIdx.x, blkrows);
}

__global__ __launch_bounds__(256) void conv_pack_w4(
    const float* __restrict__ w0, const float* __restrict__ w1,
    const float* __restrict__ w2, const float* __restrict__ w3,
    __half* __restrict__ d0, __half* __restrict__ d1,
    __half* __restrict__ d2, __half* __restrict__ d3)
{
    const float* s;
    __half* d;
    switch (blockIdx.y) {
        case 0: s = w0; d = d0; break;
        case 1: s = w1; d = d1; break;
        case 2: s = w2; d = d2; break;
        default: s = w3; d = d3; break;
    }
    pack_row(s, d, blockIdx.x, threadIdx.x, 256);
}

// ================= TMA-bulk fp16 GEMM mainloop (round-7 proven config) ====
// CTA tile 128x256, 8 warps (2x4), warp tile 64x64. K staged 64; 3-slot ring.
#define GB_A_BYTES 16384
#define GB_B_BYTES 32768
#define GB_STAGE   49152
#define GB_SMEM    (3 * GB_STAGE + 128)

// Computes acc for tile (bx, by). Leaves result in acc[4][8][4].
__device__ __forceinline__ void gemm_main(
    const __half* __restrict__ Ap, const __half* __restrict__ Bp,
    int bx, int by, float acc[4][8][4])
{
    extern __shared__ char smraw[];
    const uint32_t sbase = s2u(smraw);
    const uint32_t mb    = sbase + 3 * GB_STAGE;

    const int tid  = threadIdx.x;
    const int lane = tid & 31;
    const int wid  = tid >> 5;
    const int wm   = wid & 1;
    const int wn   = wid >> 1;

    const int l8 = lane & 7;
    const int mt = lane >> 3;

    int rA[4], rB[4];
#pragma unroll
    for (int i = 0; i < 4; i++)
        rA[i] = wm * 64 + i * 16 + (mt & 1) * 8 + l8;
#pragma unroll
    for (int j = 0; j < 4; j++)
        rB[j] = wn * 64 + j * 16 + (mt >> 1) * 8 + l8;
    const int hcA = mt >> 1;
    const int hcB = mt & 1;

#pragma unroll
    for (int i = 0; i < 4; i++)
#pragma unroll
        for (int j = 0; j < 8; j++)
#pragma unroll
            for (int t = 0; t < 4; t++) acc[i][j][t] = 0.f;

    if (tid == 0) {
#pragma unroll
        for (int i = 0; i < 3; i++) {
            MBAR_INIT(mb + i * 16, 1);
            MBAR_INIT(mb + i * 16 + 8, 8);
        }
    }
    __syncthreads();

    const __half* Asrc = Ap + (size_t)by * 32 * 128 * 64;
    const __half* Bsrc = Bp + (size_t)bx * 32 * 256 * 64;

    if (tid == 0) {
#pragma unroll
        for (int i = 0; i < 3; i++) {
            MBAR_EXPECT_TX(mb + i * 16, GB_STAGE);
            bulkcp(sbase + i * GB_STAGE, Asrc + (size_t)i * 128 * 64,
                   GB_A_BYTES, mb + i * 16);
            bulkcp(sbase + i * GB_STAGE + GB_A_BYTES, Bsrc + (size_t)i * 256 * 64,
                   GB_B_BYTES, mb + i * 16);
        }
    }

    const int NST = EMB / 64;
    for (int s = 0; s < NST; s++) {
        const int sl = s - (s / 3) * 3;
        const uint32_t ph = (uint32_t)((s / 3) & 1);
        const uint32_t slot = sbase + sl * GB_STAGE;

        mbar_wait(mb + sl * 16, ph);

#pragma unroll
        for (int ks = 0; ks < 4; ks++) {
            uint32_t a[4][4];
#pragma unroll
            for (int i = 0; i < 4; i++) {
                uint32_t ch = (uint32_t)((2 * ks + hcA) ^ (rA[i] & 7));
                ldsm4(slot + rA[i] * 128 + ch * 16,
                      a[i][0], a[i][1], a[i][2], a[i][3]);
            }
            uint32_t b[4][4];
#pragma unroll
            for (int j = 0; j < 4; j++) {
                uint32_t ch = (uint32_t)((2 * ks + hcB) ^ (rB[j] & 7));
                ldsm4(slot + GB_A_BYTES + rB[j] * 128 + ch * 16,
                      b[j][0], b[j][1], b[j][2], b[j][3]);
            }
#pragma unroll
            for (int i = 0; i < 4; i++)
#pragma unroll
                for (int j = 0; j < 4; j++) {
                    mma_f16(acc[i][j * 2 + 0], a[i], b[j][0], b[j][1]);
                    mma_f16(acc[i][j * 2 + 1], a[i], b[j][2], b[j][3]);
                }
        }

        if (lane == 0) MBAR_ARRIVE(mb + sl * 16 + 8);

        if (tid == 0 && s + 3 < NST) {
            mbar_wait(mb + sl * 16 + 8, ph);
            MBAR_EXPECT_TX(mb + sl * 16, GB_STAGE);
            bulkcp(slot, Asrc + (size_t)(s + 3) * 128 * 64,
                   GB_A_BYTES, mb + sl * 16);
            bulkcp(slot + GB_A_BYTES, Bsrc + (size_t)(s + 3) * 256 * 64,
                   GB_B_BYTES, mb + sl * 16);
        }
    }
}

// ---- Wo GEMM: plain fp32 epilogue ----
__global__ __launch_bounds__(256, 1) void gemm_bulk(
    const __half* __restrict__ Ap, const __half* __restrict__ Bp,
    float* __restrict__ C)
{
    float acc[4][8][4];
    gemm_main(Ap, Bp, blockIdx.x, blockIdx.y, acc);

    const int tid  = threadIdx.x;
    const int lane = tid & 31;
    const int wid  = tid >> 5;
    const int wm   = wid & 1;
    const int wn   = wid >> 1;
    const int bm   = blockIdx.y * 128;
    const int bn   = blockIdx.x * 256;
    const int g = lane >> 2;
    const int q = (lane & 3) * 2;
#pragma unroll
    for (int i = 0; i < 4; i++) {
#pragma unroll
        for (int j = 0; j < 8; j++) {
            int row = bm + wm * 64 + i * 16 + g;
            int col = bn + wn * 64 + j * 8 + q;
            *(float2*)(C + (size_t)row * EMB + col) =
                make_float2(acc[i][j][0], acc[i][j][1]);
            *(float2*)(C + (size_t)(row + 8) * EMB + col) =
                make_float2(acc[i][j][2], acc[i][j][3]);
        }
    }
}

// ---- fused QKV GEMM: epilogue applies RoPE+split (Q,K) / transpose+split (V)
#define EP_STRIDE 265   // floats; %32 == 9 -> conflict-free column reads

__global__ __launch_bounds__(256, 1) void gemm_qkv_fused(
    const __half* __restrict__ Ap,
    const __half* __restrict__ Bq, const __half* __restrict__ Bk,
    const __half* __restrict__ Bv,
    const float* __restrict__ cosb, const float* __restrict__ sinb,
    __nv_bfloat16* __restrict__ qh, __nv_bfloat16* __restrict__ ql,
    __nv_bfloat16* __restrict__ kh, __nv_bfloat16* __restrict__ kl,
    __nv_bfloat16* __restrict__ vth, __nv_bfloat16* __restrict__ vtl)
{
    const int z = blockIdx.z;
    const __half* Bp = (z == 0) ? Bq : (z == 1) ? Bk : Bv;

    float acc[4][8][4];
    gemm_main(Ap, Bp, blockIdx.x, blockIdx.y, acc);

    extern __shared__ char smraw[];
    float* smf = reinterpret_cast<float*>(smraw);

    const int tid  = threadIdx.x;
    const int lane = tid & 31;
    const int wid  = tid >> 5;
    const int wm   = wid & 1;
    const int wn   = wid >> 1;
    const int bm   = blockIdx.y * 128;
    const int bn   = blockIdx.x * 256;
    const int g = lane >> 2;
    const int q = (lane & 3) * 2;

    __syncthreads();   // all warps out of mainloop before overwriting smem

    // phase 1: stage acc in smem [128][EP_STRIDE]
#pragma unroll
    for (int i = 0; i < 4; i++) {
#pragma unroll
        for (int j = 0; j < 8; j++) {
            int row = wm * 64 + i * 16 + g;
            int col = wn * 64 + j * 8 + q;
            smf[row * EP_STRIDE + col]           = acc[i][j][0];
            smf[row * EP_STRIDE + col + 1]       = acc[i][j][1];
            smf[(row + 8) * EP_STRIDE + col]     = acc[i][j][2];
            smf[(row + 8) * EP_STRIDE + col + 1] = acc[i][j][3];
        }
    }
    __syncthreads();

    if (z < 2) {
        // RoPE + bf16 hi/lo split. thread -> column c; loop rows.
        __nv_bfloat16* dh = (z == 0) ? qh : kh;
        __nv_bfloat16* dl = (z == 0) ? ql : kl;
        const float sc = (z == 0) ? 0.088388347648318447f : 1.f;
        const int c  = tid;            // 0..255
        const int hd = c & 127;
        const bool low = hd < 64;
#pragma unroll 4
        for (int s = 0; s < 128; s++) {
            float a = smf[s * EP_STRIDE + c];
            float b = smf[s * EP_STRIDE + (c ^ 64)];
            int srow = bm + s;
            float cv = cosb[srow * HDIM + hd];
            float sv = sinb[srow * HDIM + hd];
            float out = low ? (a * cv - b * sv) : (a * cv + b * sv);
            out *= sc;
            __nv_bfloat16 hi = __float2bfloat16(out);
            size_t off = (size_t)srow * EMB + bn + c;
            dh[off] = hi;
            dl[off] = __float2bfloat16(out - __bfloat162float(hi));
        }
    } else {
        // V: transpose + bf16 hi/lo split. warp owns 32 columns; lane -> s.
        const int c0 = wid * 32;
#pragma unroll 2
        for (int cc = 0; cc < 32; cc++) {
            int col  = c0 + cc;
            int hloc = col >> 7;
            int d    = col & 127;
            size_t rowbase = ((size_t)((blockIdx.x * 2 + hloc) * HDIM + d)) * S_LEN + bm;
#pragma unroll
            for (int s4 = 0; s4 < 4; s4++) {
                int s = s4 * 32 + lane;
                float val = smf[s * EP_STRIDE + col];
                __nv_bfloat16 hi = __float2bfloat16(val);
                vth[rowbase + s] = hi;
                vtl[rowbase + s] = __float2bfloat16(val - __bfloat162float(hi));
            }
        }
    }
}

// ---------------- Flash attention (mma.sync, bf16x3) ----------------------
#define QB_ROW  272
#define KB_ROW  272
#define VB_ROW  144
#define SM_QPL  (128 * QB_ROW)
#define SM_Q    (2 * SM_QPL)
#define SM_KPL  (64 * KB_ROW)
#define SM_VPL  (128 * VB_ROW)
#define SM_KV   (2 * SM_KPL + 2 * SM_VPL)
#define FA_SMEM (SM_Q + 2 * SM_KV)

__global__ __launch_bounds__(256, 1) void flash_mma(
    const __nv_bfloat16* __restrict__ qh, const __nv_bfloat16* __restrict__ ql,
    const __nv_bfloat16* __restrict__ kh, const __nv_bfloat16* __restrict__ kl,
    const __nv_bfloat16* __restrict__ vth, const __nv_bfloat16* __restrict__ vtl,
    __half* __restrict__ pao)
{
    extern __shared__ char smraw[];
    const uint32_t sQ = s2u(smraw);

    const int tid  = threadIdx.x;
    const int lane = tid & 31;
    const int w    = tid >> 5;
    const int g    = lane >> 2;
    const int qd   = lane & 3;
    const int l8   = lane & 7;
    const int mt   = lane >> 3;
    const int qbi  = gridDim.x - 1 - blockIdx.x;   // heaviest CTAs first
    const int h    = blockIdx.y;

    const uint32_t offAq = (uint32_t)((w * 16 + (mt & 1) * 8 + l8) * QB_ROW + (mt >> 1) * 16);
    uint32_t offBk[4], offBv[8];
#pragma unroll
    for (int j = 0; j < 4; j++)
        offBk[j] = (uint32_t)((j * 16 + (mt >> 1) * 8 + l8) * KB_ROW + (mt & 1) * 16);
#pragma unroll
    for (int j = 0; j < 8; j++)
        offBv[j] = (uint32_t)((j * 16 + (mt >> 1) * 8 + l8) * VB_ROW + (mt & 1) * 16);

#pragma unroll
    for (int i = 0; i < 16; i++) {
        int e = tid + i * 256;
        int p = e >> 11;
        int r = (e >> 4) & 127;
        int c = e & 15;
        const __nv_bfloat16* s = (p ? ql : qh) + (size_t)(qbi * 128 + r) * EMB + h * HDIM + c * 8;
        cpa16(sQ + p * SM_QPL + r * QB_ROW + c * 16, s);
    }

    auto load_kv = [&](int buf, int kb) {
        uint32_t kvb = sQ + SM_Q + buf * SM_KV;
#pragma unroll
        for (int i = 0; i < 8; i++) {
            int e = tid + i * 256;
            int p = e >> 10;
            int r = (e >> 4) & 63;
            int c = e & 15;
            const __nv_bfloat16* s = (p ? kl : kh) + (size_t)(kb * 64 + r) * EMB + h * HDIM + c * 8;
            cpa16(kvb + p * SM_KPL + r * KB_ROW + c * 16, s);
        }
#pragma unroll
        for (int i = 0; i < 8; i++) {
            int e = tid + i * 256;
            int p = e >> 10;
            int r = (e >> 3) & 127;
            int c = e & 7;
            const __nv_bfloat16* s = (p ? vtl : vth) + (size_t)(h * HDIM + r) * S_LEN + kb * 64 + c * 8;
            cpa16(kvb + 2 * SM_KPL + p * SM_VPL + r * VB_ROW + c * 16, s);
        }
    };

    const int nkb = 2 * qbi + 2;
    load_kv(0, 0);
    CPA_COMMIT();

    float acco[16][4];
#pragma unroll
    for (int j = 0; j < 16; j++)
#pragma unroll
        for (int t = 0; t < 4; t++) acco[j][t] = 0.f;
    float m0 = -1e30f, m8 = -1e30f, l0 = 0.f, lsum8 = 0.f;

    const int row0 = qbi * 128 + w * 16 + g;
    const int row8 = row0 + 8;

    for (int kb = 0; kb < nkb; kb++) {
        if (kb + 1 < nkb) load_kv((kb + 1) & 1, kb + 1);
        CPA_COMMIT();
        CPA_WAIT1();
        __syncthreads();

        const uint32_t kvb = sQ + SM_Q + (kb & 1) * SM_KV;

        float accs[8][4];
#pragma unroll
        for (int j = 0; j < 8; j++)
#pragma unroll
            for (int t = 0; t < 4; t++) accs[j][t] = 0.f;

        const uint32_t qoff[3] = {0u, 0u, (uint32_t)SM_QPL};
        const uint32_t koff[3] = {0u, (uint32_t)SM_KPL, 0u};
#pragma unroll
        for (int p = 0; p < 3; p++) {
#pragma unroll
            for (int ks = 0; ks < 8; ks++) {
                uint32_t a[4];
                ldsm4(sQ + qoff[p] + offAq + ks * 32, a[0], a[1], a[2], a[3]);
#pragma unroll
                for (int j = 0; j < 4; j++) {
                    uint32_t b0, b1, b2, b3;
                    ldsm4(kvb + koff[p] + offBk[j] + ks * 32, b0, b1, b2, b3);
                    mma_bf16(accs[j * 2 + 0], a, b0, b1);
                    mma_bf16(accs[j * 2 + 1], a, b2, b3);
                }
            }
        }

        if (kb >= 2 * qbi) {
#pragma unroll
            for (int jt = 0; jt < 8; jt++) {
                int col = kb * 64 + jt * 8 + 2 * qd;
                if (col     > row0) accs[jt][0] = -1e30f;
                if (col + 1 > row0) accs[jt][1] = -1e30f;
                if (col     > row8) accs[jt][2] = -1e30f;
                if (col + 1 > row8) accs[jt][3] = -1e30f;
            }
        }

        float mx0 = -1e30f, mx8 = -1e30f;
#pragma unroll
        for (int jt = 0; jt < 8; jt++) {
            mx0 = fmaxf(mx0, fmaxf(accs[jt][0], accs[jt][1]));
            mx8 = fmaxf(mx8, fmaxf(accs[jt][2], accs[jt][3]));
        }
        mx0 = fmaxf(mx0, __shfl_xor_sync(0xffffffffu, mx0, 1));
        mx0 = fmaxf(mx0, __shfl_xor_sync(0xffffffffu, mx0, 2));
        mx8 = fmaxf(mx8, __shfl_xor_sync(0xffffffffu, mx8, 1));
        mx8 = fmaxf(mx8, __shfl_xor_sync(0xffffffffu, mx8, 2));

        float nm0 = fmaxf(m0, mx0), nm8 = fmaxf(m8, mx8);
        float al0 = __expf(m0 - nm0), al8 = __expf(m8 - nm8);
        m0 = nm0; m8 = nm8;

        float s0 = 0.f, s8 = 0.f;
#pragma unroll
        for (int jt = 0; jt < 8; jt++) {
            accs[jt][0] = __expf(accs[jt][0] - nm0);
            accs[jt][1] = __expf(accs[jt][1] - nm0);
            accs[jt][2] = __expf(accs[jt][2] - nm8);
            accs[jt][3] = __expf(accs[jt][3] - nm8);
            s0 += accs[jt][0] + accs[jt][1];
            s8 += accs[jt][2] + accs[jt][3];
        }
        s0 += __shfl_xor_sync(0xffffffffu, s0, 1);
        s0 += __shfl_xor_sync(0xffffffffu, s0, 2);
        s8 += __shfl_xor_sync(0xffffffffu, s8, 1);
        s8 += __shfl_xor_sync(0xffffffffu, s8, 2);
        l0 = l0 * al0 + s0;
        lsum8 = lsum8 * al8 + s8;

#pragma unroll
        for (int j = 0; j < 16; j++) {
            acco[j][0] *= al0; acco[j][1] *= al0;
            acco[j][2] *= al8; acco[j][3] *= al8;
        }

        uint32_t phh[8][2], pll[8][2];
#pragma unroll
        for (int jt = 0; jt < 8; jt++) {
            __nv_bfloat162 h2 = __floats2bfloat162_rn(accs[jt][0], accs[jt][1]);
            float2 hf = __bfloat1622float2(h2);
            phh[jt][0] = b2u(h2);
            pll[jt][0] = b2u(__floats2bfloat162_rn(accs[jt][0] - hf.x, accs[jt][1] - hf.y));
            h2 = __floats2bfloat162_rn(accs[jt][2], accs[jt][3]);
            hf = __bfloat1622float2(h2);
            phh[jt][1] = b2u(h2);
            pll[jt][1] = b2u(__floats2bfloat162_rn(accs[jt][2] - hf.x, accs[jt][3] - hf.y));
        }

        const uint32_t vbase = kvb + 2 * SM_KPL;
#pragma unroll
        for (int p = 0; p < 3; p++) {
            const uint32_t voff = (p == 1) ? (uint32_t)SM_VPL : 0u;
#pragma unroll
            for (int t = 0; t < 4; t++) {
                uint32_t a[4];
                if (p == 2) {
                    a[0] = pll[2 * t][0]; a[1] = pll[2 * t][1];
                    a[2] = pll[2 * t + 1][0]; a[3] = pll[2 * t + 1][1];
                } else {
                    a[0] = phh[2 * t][0]; a[1] = phh[2 * t][1];
                    a[2] = phh[2 * t + 1][0]; a[3] = phh[2 * t + 1][1];
                }
#pragma unroll
                for (int jn = 0; jn < 8; jn++) {
                    uint32_t b0, b1, b2, b3;
                    ldsm4(vbase + voff + offBv[jn] + t * 32, b0, b1, b2, b3);
                    mma_bf16(acco[jn * 2 + 0], a, b0, b1);
                    mma_bf16(acco[jn * 2 + 1], a, b2, b3);
                }
            }
        }
        __syncthreads();
    }

    // ---- epilogue: write packed fp16 directly (layout consumed by Wo GEMM)
    float inv0 = 1.f / l0, inv8 = 1.f / lsum8;
    const int blk  = qbi;            // row block (rows 128-aligned)
    const int rin0 = w * 16 + g;     // row0 & 127
    const int rin8 = rin0 + 8;
#pragma unroll
    for (int jt = 0; jt < 16; jt++) {
        int ks = h * 2 + (jt >> 3);
        int c8 = jt & 7;
        size_t chunk0 = ((size_t)(blk * 32 + ks) * 128 + rin0) * 8 + (c8 ^ (rin0 & 7));
        size_t chunk8 = ((size_t)(blk * 32 + ks) * 128 + rin8) * 8 + (c8 ^ (rin8 & 7));
        __half2 v0 = __floats2half2_rn(acco[jt][0] * inv0, acco[jt][1] * inv0);
        __half2 v8 = __floats2half2_rn(acco[jt][2] * inv8, acco[jt][3] * inv8);
        *reinterpret_cast<__half2*>(pao + chunk0 * 8 + qd * 2) = v0;
        *reinterpret_cast<__half2*>(pao + chunk8 * 8 + qd * 2) = v8;
    }
}

// ---------------- launch ----------------
extern "C" void kernel_launch(void* const* d_in, const int* in_sizes, int n_in,
                              void* d_out, int out_size)
{
    const float* x  = (const float*)d_in[0];
    const float* rc = (const float*)d_in[1];
    const float* rs = (const float*)d_in[2];
    const float* Wq = (const float*)d_in[3];
    const float* Wk = (const float*)d_in[4];
    const float* Wv = (const float*)d_in[5];
    const float* Wo = (const float*)d_in[6];
    float* out = (float*)d_out;

    __half *px, *pao, *pwq, *pwk, *pwv, *pwo;
    cudaGetSymbolAddress((void**)&px,  g_px);
    cudaGetSymbolAddress((void**)&pao, g_pao);
    cudaGetSymbolAddress((void**)&pwq, g_pwq);
    cudaGetSymbolAddress((void**)&pwk, g_pwk);
    cudaGetSymbolAddress((void**)&pwv, g_pwv);
    cudaGetSymbolAddress((void**)&pwo, g_pwo);

    __nv_bfloat16 *qh, *ql, *kh, *kl, *vth, *vtl;
    cudaGetSymbolAddress((void**)&qh,  g_qh);
    cudaGetSymbolAddress((void**)&ql,  g_ql);
    cudaGetSymbolAddress((void**)&kh,  g_kh);
    cudaGetSymbolAddress((void**)&kl,  g_kl);
    cudaGetSymbolAddress((void**)&vth, g_vth);
    cudaGetSymbolAddress((void**)&vtl, g_vtl);

    cudaFuncSetAttribute(gemm_bulk,
                         cudaFuncAttributeMaxDynamicSharedMemorySize, GB_SMEM);
    cudaFuncSetAttribute(gemm_qkv_fused,
                         cudaFuncAttributeMaxDynamicSharedMemorySize, GB_SMEM);
    cudaFuncSetAttribute(flash_mma,
                         cudaFuncAttributeMaxDynamicSharedMemorySize, FA_SMEM);

    // repack inputs
    conv_pack<<<S_LEN, 256>>>(x, px, 128);
    conv_pack_w4<<<dim3(EMB, 4), 256>>>(Wq, Wk, Wv, Wo, pwq, pwk, pwv, pwo);

    // fused QKV projection + RoPE/split/transpose epilogue
    dim3 gq(EMB / 256, S_LEN / 128, 3);
    gemm_qkv_fused<<<gq, 256, GB_SMEM>>>(px, pwq, pwk, pwv, rc, rs,
                                         qh, ql, kh, kl, vth, vtl);

    // flash attention -> packed fp16 pao
    flash_mma<<<dim3(S_LEN / 128, NHEAD), 256, FA_SMEM>>>(qh, ql, kh, kl, vth, vtl, pao);

    // output projection
    dim3 gg(EMB / 256, S_LEN / 128);
    gemm_bulk<<<gg, 256, GB_SMEM>>>(pao, pwo, out);
}

// round 10
// speedup vs baseline: 1.2563x; 1.2563x over previous
#include <cuda_runtime.h>
#include <cuda_bf16.h>
#include <cuda_fp16.h>
#include <math.h>
#include <stdint.h>

#define S_LEN 2048
#define EMB   2048
#define NHEAD 16
#define HDIM  128

// ---------------- scratch (no cudaMalloc allowed) ----------------
// packed fp16 GEMM operands (stage-contiguous, swizzled)
__device__ __align__(256) __half g_px [S_LEN * EMB];
__device__ __align__(256) __half g_pao[S_LEN * EMB];
__device__ __align__(256) __half g_pwq[EMB * EMB];
__device__ __align__(256) __half g_pwk[EMB * EMB];
__device__ __align__(256) __half g_pwv[EMB * EMB];
__device__ __align__(256) __half g_pwo[EMB * EMB];

// attention operands (fp16)
__device__ __half g_qh [S_LEN * EMB];   // q hi
__device__ __half g_ql [S_LEN * EMB];   // q lo
__device__ __half g_kh [S_LEN * EMB];   // k (single)
__device__ __half g_vth[NHEAD * HDIM * S_LEN];   // [h][d][s] v hi
__device__ __half g_vtl[NHEAD * HDIM * S_LEN];   // v lo

// ================= helpers (baseline PTX only) ==============
__device__ __forceinline__ uint32_t s2u(const void* p) {
    uint32_t a;
    asm("{ .reg .u64 t; cvta.to.shared.u64 t, %1; cvt.u32.u64 %0, t; }"
        : "=r"(a) : "l"(p));
    return a;
}

__device__ __forceinline__ void cpa16(uint32_t dst, const void* src) {
    asm volatile("cp.async.cg.shared.global [%0], [%1], 16;" :: "r"(dst), "l"(src));
}
#define CPA_COMMIT() asm volatile("cp.async.commit_group;" ::: "memory")
#define CPA_WAIT1()  asm volatile("cp.async.wait_group 1;" ::: "memory")

__device__ __forceinline__ void ldsm4(uint32_t addr, uint32_t& r0, uint32_t& r1,
                                      uint32_t& r2, uint32_t& r3) {
    asm volatile("ldmatrix.sync.aligned.m8n8.x4.shared.b16 {%0,%1,%2,%3}, [%4];"
                 : "=r"(r0), "=r"(r1), "=r"(r2), "=r"(r3) : "r"(addr));
}

__device__ __forceinline__ void mma_f16(float* d, const uint32_t* a,
                                        uint32_t b0, uint32_t b1) {
    asm volatile(
        "mma.sync.aligned.m16n8k16.row.col.f32.f16.f16.f32 "
        "{%0,%1,%2,%3}, {%4,%5,%6,%7}, {%8,%9}, {%0,%1,%2,%3};"
        : "+f"(d[0]), "+f"(d[1]), "+f"(d[2]), "+f"(d[3])
        : "r"(a[0]), "r"(a[1]), "r"(a[2]), "r"(a[3]), "r"(b0), "r"(b1));
}

__device__ __forceinline__ uint32_t h2u(__half2 v) {
    return *reinterpret_cast<uint32_t*>(&v);
}

// ---- mbarrier / bulk-copy (sm_90 baseline PTX) ----
#define MBAR_INIT(mbar, cnt) \
    asm volatile("mbarrier.init.shared.b64 [%0], %1;" \
                 :: "r"((uint32_t)(mbar)), "r"((uint32_t)(cnt)) : "memory")
#define MBAR_EXPECT_TX(mbar, bytes) \
    asm volatile("mbarrier.arrive.expect_tx.shared.b64 _, [%0], %1;" \
                 :: "r"((uint32_t)(mbar)), "r"((uint32_t)(bytes)) : "memory")
#define MBAR_ARRIVE(mbar) \
    asm volatile("mbarrier.arrive.shared.b64 _, [%0];" \
                 :: "r"((uint32_t)(mbar)) : "memory")

__device__ __forceinline__ void mbar_wait(uint32_t mbar, uint32_t phase) {
    asm volatile(
        "{\n\t.reg .pred P1;\n\t"
        "WAIT_LOOP_%=:\n\t"
        "mbarrier.try_wait.parity.acquire.cta.shared::cta.b64 P1, [%0], %1, 0x989680;\n\t"
        "@P1 bra.uni WAIT_DONE_%=;\n\t"
        "bra.uni WAIT_LOOP_%=;\n\t"
        "WAIT_DONE_%=:\n\t}"
        :: "r"(mbar), "r"(phase) : "memory");
}

__device__ __forceinline__ void bulkcp(uint32_t dst, const void* src,
                                       uint32_t bytes, uint32_t mbar) {
    asm volatile(
        "cp.async.bulk.shared::cluster.global.mbarrier::complete_tx::bytes "
        "[%0], [%1], %2, [%3];"
        :: "r"(dst), "l"(src), "r"(bytes), "r"(mbar) : "memory");
}

// ================= repack fp32 -> fp16, stage-contiguous + XOR swizzle ====
__device__ __forceinline__ void pack_row(
    const float* __restrict__ src, __half* __restrict__ dst,
    int r, int t, int blkrows)
{
    const int ks  = t >> 3;
    const int cs  = t & 7;
    const int rin = r & (blkrows - 1);
    const int blk = r / blkrows;
    const int c   = cs ^ (rin & 7);

    const float* s = src + (size_t)r * EMB + ks * 64 + c * 8;
    float4 v0 = *(const float4*)(s);
    float4 v1 = *(const float4*)(s + 4);

    __half2 h0 = __floats2half2_rn(v0.x, v0.y);
    __half2 h1 = __floats2half2_rn(v0.z, v0.w);
    __half2 h2 = __floats2half2_rn(v1.x, v1.y);
    __half2 h3 = __floats2half2_rn(v1.z, v1.w);

    size_t chunk = ((size_t)(blk * 32 + ks) * blkrows + rin) * 8 + cs;
    uint4 out;
    out.x = h2u(h0); out.y = h2u(h1); out.z = h2u(h2); out.w = h2u(h3);
    *(reinterpret_cast<uint4*>(dst) + chunk) = out;
}

__global__ __launch_bounds__(256) void conv_pack(
    const float* __restrict__ src, __half* __restrict__ dst, int blkrows)
{
    pack_row(src, dst, blockIdx.x, threadIdx.x, blkrows);
}

__global__ __launch_bounds__(256) void conv_pack_w4(
    const float* __restrict__ w0, const float* __restrict__ w1,
    const float* __restrict__ w2, const float* __restrict__ w3,
    __half* __restrict__ d0, __half* __restrict__ d1,
    __half* __restrict__ d2, __half* __restrict__ d3)
{
    const float* s;
    __half* d;
    switch (blockIdx.y) {
        case 0: s = w0; d = d0; break;
        case 1: s = w1; d = d1; break;
        case 2: s = w2; d = d2; break;
        default: s = w3; d = d3; break;
    }
    pack_row(s, d, blockIdx.x, threadIdx.x, 256);
}

// ================= TMA-bulk fp16 GEMM mainloop (round-7 proven config) ====
// CTA tile 128x256, 8 warps (2x4), warp tile 64x64. K staged 64; 3-slot ring.
#define GB_A_BYTES 16384
#define GB_B_BYTES 32768
#define GB_STAGE   49152
#define GB_SMEM    (3 * GB_STAGE + 128)

__device__ __forceinline__ void gemm_main(
    const __half* __restrict__ Ap, const __half* __restrict__ Bp,
    int bx, int by, float acc[4][8][4])
{
    extern __shared__ char smraw[];
    const uint32_t sbase = s2u(smraw);
    const uint32_t mb    = sbase + 3 * GB_STAGE;

    const int tid  = threadIdx.x;
    const int lane = tid & 31;
    const int wid  = tid >> 5;
    const int wm   = wid & 1;
    const int wn   = wid >> 1;

    const int l8 = lane & 7;
    const int mt = lane >> 3;

    int rA[4], rB[4];
#pragma unroll
    for (int i = 0; i < 4; i++)
        rA[i] = wm * 64 + i * 16 + (mt & 1) * 8 + l8;
#pragma unroll
    for (int j = 0; j < 4; j++)
        rB[j] = wn * 64 + j * 16 + (mt >> 1) * 8 + l8;
    const int hcA = mt >> 1;
    const int hcB = mt & 1;

#pragma unroll
    for (int i = 0; i < 4; i++)
#pragma unroll
        for (int j = 0; j < 8; j++)
#pragma unroll
            for (int t = 0; t < 4; t++) acc[i][j][t] = 0.f;

    if (tid == 0) {
#pragma unroll
        for (int i = 0; i < 3; i++) {
            MBAR_INIT(mb + i * 16, 1);
            MBAR_INIT(mb + i * 16 + 8, 8);
        }
    }
    __syncthreads();

    const __half* Asrc = Ap + (size_t)by * 32 * 128 * 64;
    const __half* Bsrc = Bp + (size_t)bx * 32 * 256 * 64;

    if (tid == 0) {
#pragma unroll
        for (int i = 0; i < 3; i++) {
            MBAR_EXPECT_TX(mb + i * 16, GB_STAGE);
            bulkcp(sbase + i * GB_STAGE, Asrc + (size_t)i * 128 * 64,
                   GB_A_BYTES, mb + i * 16);
            bulkcp(sbase + i * GB_STAGE + GB_A_BYTES, Bsrc + (size_t)i * 256 * 64,
                   GB_B_BYTES, mb + i * 16);
        }
    }

    const int NST = EMB / 64;
    for (int s = 0; s < NST; s++) {
        const int sl = s - (s / 3) * 3;
        const uint32_t ph = (uint32_t)((s / 3) & 1);
        const uint32_t slot = sbase + sl * GB_STAGE;

        mbar_wait(mb + sl * 16, ph);

#pragma unroll
        for (int ks = 0; ks < 4; ks++) {
            uint32_t a[4][4];
#pragma unroll
            for (int i = 0; i < 4; i++) {
                uint32_t ch = (uint32_t)((2 * ks + hcA) ^ (rA[i] & 7));
                ldsm4(slot + rA[i] * 128 + ch * 16,
                      a[i][0], a[i][1], a[i][2], a[i][3]);
            }
            uint32_t b[4][4];
#pragma unroll
            for (int j = 0; j < 4; j++) {
                uint32_t ch = (uint32_t)((2 * ks + hcB) ^ (rB[j] & 7));
                ldsm4(slot + GB_A_BYTES + rB[j] * 128 + ch * 16,
                      b[j][0], b[j][1], b[j][2], b[j][3]);
            }
#pragma unroll
            for (int i = 0; i < 4; i++)
#pragma unroll
                for (int j = 0; j < 4; j++) {
                    mma_f16(acc[i][j * 2 + 0], a[i], b[j][0], b[j][1]);
                    mma_f16(acc[i][j * 2 + 1], a[i], b[j][2], b[j][3]);
                }
        }

        if (lane == 0) MBAR_ARRIVE(mb + sl * 16 + 8);

        if (tid == 0 && s + 3 < NST) {
            mbar_wait(mb + sl * 16 + 8, ph);
            MBAR_EXPECT_TX(mb + sl * 16, GB_STAGE);
            bulkcp(slot, Asrc + (size_t)(s + 3) * 128 * 64,
                   GB_A_BYTES, mb + sl * 16);
            bulkcp(slot + GB_A_BYTES, Bsrc + (size_t)(s + 3) * 256 * 64,
                   GB_B_BYTES, mb + sl * 16);
        }
    }
}

// ---- Wo GEMM: plain fp32 epilogue ----
__global__ __launch_bounds__(256, 1) void gemm_bulk(
    const __half* __restrict__ Ap, const __half* __restrict__ Bp,
    float* __restrict__ C)
{
    float acc[4][8][4];
    gemm_main(Ap, Bp, blockIdx.x, blockIdx.y, acc);

    const int tid  = threadIdx.x;
    const int lane = tid & 31;
    const int wid  = tid >> 5;
    const int wm   = wid & 1;
    const int wn   = wid >> 1;
    const int bm   = blockIdx.y * 128;
    const int bn   = blockIdx.x * 256;
    const int g = lane >> 2;
    const int q = (lane & 3) * 2;
#pragma unroll
    for (int i = 0; i < 4; i++) {
#pragma unroll
        for (int j = 0; j < 8; j++) {
            int row = bm + wm * 64 + i * 16 + g;
            int col = bn + wn * 64 + j * 8 + q;
            *(float2*)(C + (size_t)row * EMB + col) =
                make_float2(acc[i][j][0], acc[i][j][1]);
            *(float2*)(C + (size_t)(row + 8) * EMB + col) =
                make_float2(acc[i][j][2], acc[i][j][3]);
        }
    }
}

// ---- fused QKV GEMM: epilogue RoPE+split (Q), RoPE (K), transpose+split (V)
#define EP_STRIDE 265   // floats; %32 == 9 -> conflict-free column reads

__global__ __launch_bounds__(256, 1) void gemm_qkv_fused(
    const __half* __restrict__ Ap,
    const __half* __restrict__ Bq, const __half* __restrict__ Bk,
    const __half* __restrict__ Bv,
    const float* __restrict__ cosb, const float* __restrict__ sinb,
    __half* __restrict__ qh, __half* __restrict__ ql,
    __half* __restrict__ kh,
    __half* __restrict__ vth, __half* __restrict__ vtl)
{
    const int z = blockIdx.z;
    const __half* Bp = (z == 0) ? Bq : (z == 1) ? Bk : Bv;

    float acc[4][8][4];
    gemm_main(Ap, Bp, blockIdx.x, blockIdx.y, acc);

    extern __shared__ char smraw[];
    float* smf = reinterpret_cast<float*>(smraw);

    const int tid  = threadIdx.x;
    const int lane = tid & 31;
    const int wid  = tid >> 5;
    const int wm   = wid & 1;
    const int wn   = wid >> 1;
    const int bm   = blockIdx.y * 128;
    const int bn   = blockIdx.x * 256;
    const int g = lane >> 2;
    const int q = (lane & 3) * 2;

    __syncthreads();   // all warps out of mainloop before overwriting smem

#pragma unroll
    for (int i = 0; i < 4; i++) {
#pragma unroll
        for (int j = 0; j < 8; j++) {
            int row = wm * 64 + i * 16 + g;
            int col = wn * 64 + j * 8 + q;
            smf[row * EP_STRIDE + col]           = acc[i][j][0];
            smf[row * EP_STRIDE + col + 1]       = acc[i][j][1];
            smf[(row + 8) * EP_STRIDE + col]     = acc[i][j][2];
            smf[(row + 8) * EP_STRIDE + col + 1] = acc[i][j][3];
        }
    }
    __syncthreads();

    if (z < 2) {
        // RoPE; Q also split fp16 hi/lo, K single fp16
        const float sc = (z == 0) ? 0.088388347648318447f : 1.f;
        const int c  = tid;
        const int hd = c & 127;
        const bool low = hd < 64;
#pragma unroll 4
        for (int s = 0; s < 128; s++) {
            float a = smf[s * EP_STRIDE + c];
            float b = smf[s * EP_STRIDE + (c ^ 64)];
            int srow = bm + s;
            float cv = cosb[srow * HDIM + hd];
            float sv = sinb[srow * HDIM + hd];
            float out = (low ? (a * cv - b * sv) : (a * cv + b * sv)) * sc;
            size_t off = (size_t)srow * EMB + bn + c;
            if (z == 0) {
                __half hi = __float2half_rn(out);
                qh[off] = hi;
                ql[off] = __float2half_rn(out - __half2float(hi));
            } else {
                kh[off] = __float2half_rn(out);
            }
        }
    } else {
        // V: transpose + fp16 hi/lo split
        const int c0 = wid * 32;
#pragma unroll 2
        for (int cc = 0; cc < 32; cc++) {
            int col  = c0 + cc;
            int hloc = col >> 7;
            int d    = col & 127;
            size_t rowbase = ((size_t)((blockIdx.x * 2 + hloc) * HDIM + d)) * S_LEN + bm;
#pragma unroll
            for (int s4 = 0; s4 < 4; s4++) {
                int s = s4 * 32 + lane;
                float val = smf[s * EP_STRIDE + col];
                __half hi = __float2half_rn(val);
                vth[rowbase + s] = hi;
                vtl[rowbase + s] = __float2half_rn(val - __half2float(hi));
            }
        }
    }
}

// ---------------- Flash attention (mma.sync, fp16 2-pass both sides) ------
#define QB_ROW  272
#define KB_ROW  272
#define VB_ROW  144
#define SM_QPL  (128 * QB_ROW)
#define SM_Q    (2 * SM_QPL)            // q hi + lo
#define SM_KPL  (64 * KB_ROW)           // k single plane
#define SM_VPL  (128 * VB_ROW)
#define SM_KV   (SM_KPL + 2 * SM_VPL)   // 54272 per buffer
#define FA_SMEM (SM_Q + 2 * SM_KV)      // 178176

__global__ __launch_bounds__(256, 1) void flash_mma(
    const __half* __restrict__ qh, const __half* __restrict__ ql,
    const __half* __restrict__ kh,
    const __half* __restrict__ vth, const __half* __restrict__ vtl,
    __half* __restrict__ pao)
{
    extern __shared__ char smraw[];
    const uint32_t sQ = s2u(smraw);

    const int tid  = threadIdx.x;
    const int lane = tid & 31;
    const int w    = tid >> 5;
    const int g    = lane >> 2;
    const int qd   = lane & 3;
    const int l8   = lane & 7;
    const int mt   = lane >> 3;
    const int qbi  = gridDim.x - 1 - blockIdx.x;   // heaviest CTAs first
    const int h    = blockIdx.y;

    const uint32_t offAq = (uint32_t)((w * 16 + (mt & 1) * 8 + l8) * QB_ROW + (mt >> 1) * 16);
    uint32_t offBk[4], offBv[8];
#pragma unroll
    for (int j = 0; j < 4; j++)
        offBk[j] = (uint32_t)((j * 16 + (mt >> 1) * 8 + l8) * KB_ROW + (mt & 1) * 16);
#pragma unroll
    for (int j = 0; j < 8; j++)
        offBv[j] = (uint32_t)((j * 16 + (mt >> 1) * 8 + l8) * VB_ROW + (mt & 1) * 16);

    // ---- load Q (hi + lo planes) ----
#pragma unroll
    for (int i = 0; i < 16; i++) {
        int e = tid + i * 256;
        int p = e >> 11;
        int r = (e >> 4) & 127;
        int c = e & 15;
        const __half* s = (p ? ql : qh) + (size_t)(qbi * 128 + r) * EMB + h * HDIM + c * 8;
        cpa16(sQ + p * SM_QPL + r * QB_ROW + c * 16, s);
    }

    auto load_kv = [&](int buf, int kb) {
        uint32_t kvb = sQ + SM_Q + buf * SM_KV;
#pragma unroll
        for (int i = 0; i < 4; i++) {           // K single plane
            int e = tid + i * 256;
            int r = (e >> 4) & 63;
            int c = e & 15;
            const __half* s = kh + (size_t)(kb * 64 + r) * EMB + h * HDIM + c * 8;
            cpa16(kvb + r * KB_ROW + c * 16, s);
        }
#pragma unroll
        for (int i = 0; i < 8; i++) {           // V hi + lo (transposed)
            int e = tid + i * 256;
            int p = e >> 10;
            int r = (e >> 3) & 127;
            int c = e & 7;
            const __half* s = (p ? vtl : vth) + (size_t)(h * HDIM + r) * S_LEN + kb * 64 + c * 8;
            cpa16(kvb + SM_KPL + p * SM_VPL + r * VB_ROW + c * 16, s);
        }
    };

    const int nkb = 2 * qbi + 2;
    load_kv(0, 0);
    CPA_COMMIT();

    float acco[16][4];
#pragma unroll
    for (int j = 0; j < 16; j++)
#pragma unroll
        for (int t = 0; t < 4; t++) acco[j][t] = 0.f;
    float m0 = -1e30f, m8 = -1e30f, l0 = 0.f, lsum8 = 0.f;

    const int row0 = qbi * 128 + w * 16 + g;
    const int row8 = row0 + 8;

    for (int kb = 0; kb < nkb; kb++) {
        if (kb + 1 < nkb) load_kv((kb + 1) & 1, kb + 1);
        CPA_COMMIT();
        CPA_WAIT1();
        __syncthreads();

        const uint32_t kvb = sQ + SM_Q + (kb & 1) * SM_KV;

        // ---- S = Q K^T (2 passes: qh*k, ql*k) ----
        float accs[8][4];
#pragma unroll
        for (int j = 0; j < 8; j++)
#pragma unroll
            for (int t = 0; t < 4; t++) accs[j][t] = 0.f;

#pragma unroll
        for (int p = 0; p < 2; p++) {
#pragma unroll
            for (int ks = 0; ks < 8; ks++) {
                uint32_t a[4];
                ldsm4(sQ + p * SM_QPL + offAq + ks * 32, a[0], a[1], a[2], a[3]);
#pragma unroll
                for (int j = 0; j < 4; j++) {
                    uint32_t b0, b1, b2, b3;
                    ldsm4(kvb + offBk[j] + ks * 32, b0, b1, b2, b3);
                    mma_f16(accs[j * 2 + 0], a, b0, b1);
                    mma_f16(accs[j * 2 + 1], a, b2, b3);
                }
            }
        }

        if (kb >= 2 * qbi) {
#pragma unroll
            for (int jt = 0; jt < 8; jt++) {
                int col = kb * 64 + jt * 8 + 2 * qd;
                if (col     > row0) accs[jt][0] = -1e30f;
                if (col + 1 > row0) accs[jt][1] = -1e30f;
                if (col     > row8) accs[jt][2] = -1e30f;
                if (col + 1 > row8) accs[jt][3] = -1e30f;
            }
        }

        // ---- online softmax ----
        float mx0 = -1e30f, mx8 = -1e30f;
#pragma unroll
        for (int jt = 0; jt < 8; jt++) {
            mx0 = fmaxf(mx0, fmaxf(accs[jt][0], accs[jt][1]));
            mx8 = fmaxf(mx8, fmaxf(accs[jt][2], accs[jt][3]));
        }
        mx0 = fmaxf(mx0, __shfl_xor_sync(0xffffffffu, mx0, 1));
        mx0 = fmaxf(mx0, __shfl_xor_sync(0xffffffffu, mx0, 2));
        mx8 = fmaxf(mx8, __shfl_xor_sync(0xffffffffu, mx8, 1));
        mx8 = fmaxf(mx8, __shfl_xor_sync(0xffffffffu, mx8, 2));

        float nm0 = fmaxf(m0, mx0), nm8 = fmaxf(m8, mx8);
        float al0 = __expf(m0 - nm0), al8 = __expf(m8 - nm8);
        m0 = nm0; m8 = nm8;

        float s0 = 0.f, s8 = 0.f;
#pragma unroll
        for (int jt = 0; jt < 8; jt++) {
            accs[jt][0] = __expf(accs[jt][0] - nm0);
            accs[jt][1] = __expf(accs[jt][1] - nm0);
            accs[jt][2] = __expf(accs[jt][2] - nm8);
            accs[jt][3] = __expf(accs[jt][3] - nm8);
            s0 += accs[jt][0] + accs[jt][1];
            s8 += accs[jt][2] + accs[jt][3];
        }
        s0 += __shfl_xor_sync(0xffffffffu, s0, 1);
        s0 += __shfl_xor_sync(0xffffffffu, s0, 2);
        s8 += __shfl_xor_sync(0xffffffffu, s8, 1);
        s8 += __shfl_xor_sync(0xffffffffu, s8, 2);
        l0 = l0 * al0 + s0;
        lsum8 = lsum8 * al8 + s8;

#pragma unroll
        for (int j = 0; j < 16; j++) {
            acco[j][0] *= al0; acco[j][1] *= al0;
            acco[j][2] *= al8; acco[j][3] *= al8;
        }

        // ---- P -> fp16 fragments (single precision level) ----
        uint32_t pf[8][2];
#pragma unroll
        for (int jt = 0; jt < 8; jt++) {
            pf[jt][0] = h2u(__floats2half2_rn(accs[jt][0], accs[jt][1]));
            pf[jt][1] = h2u(__floats2half2_rn(accs[jt][2], accs[jt][3]));
        }

        // ---- O += P V (2 passes: p*vh, p*vl) ----
        const uint32_t vbase = kvb + SM_KPL;
#pragma unroll
        for (int p = 0; p < 2; p++) {
            const uint32_t voff = p ? (uint32_t)SM_VPL : 0u;
#pragma unroll
            for (int t = 0; t < 4; t++) {
                uint32_t a[4];
                a[0] = pf[2 * t][0]; a[1] = pf[2 * t][1];
                a[2] = pf[2 * t + 1][0]; a[3] = pf[2 * t + 1][1];
#pragma unroll
                for (int jn = 0; jn < 8; jn++) {
                    uint32_t b0, b1, b2, b3;
                    ldsm4(vbase + voff + offBv[jn] + t * 32, b0, b1, b2, b3);
                    mma_f16(acco[jn * 2 + 0], a, b0, b1);
                    mma_f16(acco[jn * 2 + 1], a, b2, b3);
                }
            }
        }
        __syncthreads();
    }

    // ---- epilogue: write packed fp16 directly (layout consumed by Wo GEMM)
    float inv0 = 1.f / l0, inv8 = 1.f / lsum8;
    const int blk  = qbi;
    const int rin0 = w * 16 + g;
    const int rin8 = rin0 + 8;
#pragma unroll
    for (int jt = 0; jt < 16; jt++) {
        int ks = h * 2 + (jt >> 3);
        int c8 = jt & 7;
        size_t chunk0 = ((size_t)(blk * 32 + ks) * 128 + rin0) * 8 + (c8 ^ (rin0 & 7));
        size_t chunk8 = ((size_t)(blk * 32 + ks) * 128 + rin8) * 8 + (c8 ^ (rin8 & 7));
        __half2 v0 = __floats2half2_rn(acco[jt][0] * inv0, acco[jt][1] * inv0);
        __half2 v8 = __floats2half2_rn(acco[jt][2] * inv8, acco[jt][3] * inv8);
        *reinterpret_cast<__half2*>(pao + chunk0 * 8 + qd * 2) = v0;
        *reinterpret_cast<__half2*>(pao + chunk8 * 8 + qd * 2) = v8;
    }
}

// ---------------- launch ----------------
extern "C" void kernel_launch(void* const* d_in, const int* in_sizes, int n_in,
                              void* d_out, int out_size)
{
    const float* x  = (const float*)d_in[0];
    const float* rc = (const float*)d_in[1];
    const float* rs = (const float*)d_in[2];
    const float* Wq = (const float*)d_in[3];
    const float* Wk = (const float*)d_in[4];
    const float* Wv = (const float*)d_in[5];
    const float* Wo = (const float*)d_in[6];
    float* out = (float*)d_out;

    __half *px, *pao, *pwq, *pwk, *pwv, *pwo;
    cudaGetSymbolAddress((void**)&px,  g_px);
    cudaGetSymbolAddress((void**)&pao, g_pao);
    cudaGetSymbolAddress((void**)&pwq, g_pwq);
    cudaGetSymbolAddress((void**)&pwk, g_pwk);
    cudaGetSymbolAddress((void**)&pwv, g_pwv);
    cudaGetSymbolAddress((void**)&pwo, g_pwo);

    __half *qh, *ql, *kh, *vth, *vtl;
    cudaGetSymbolAddress((void**)&qh,  g_qh);
    cudaGetSymbolAddress((void**)&ql,  g_ql);
    cudaGetSymbolAddress((void**)&kh,  g_kh);
    cudaGetSymbolAddress((void**)&vth, g_vth);
    cudaGetSymbolAddress((void**)&vtl, g_vtl);

    cudaFuncSetAttribute(gemm_bulk,
                         cudaFuncAttributeMaxDynamicSharedMemorySize, GB_SMEM);
    cudaFuncSetAttribute(gemm_qkv_fused,
                         cudaFuncAttributeMaxDynamicSharedMemorySize, GB_SMEM);
    cudaFuncSetAttribute(flash_mma,
                         cudaFuncAttributeMaxDynamicSharedMemorySize, FA_SMEM);

    // repack inputs
    conv_pack<<<S_LEN, 256>>>(x, px, 128);
    conv_pack_w4<<<dim3(EMB, 4), 256>>>(Wq, Wk, Wv, Wo, pwq, pwk, pwv, pwo);

    // fused QKV projection + RoPE/split/transpose epilogue
    dim3 gq(EMB / 256, S_LEN / 128, 3);
    gemm_qkv_fused<<<gq, 256, GB_SMEM>>>(px, pwq, pwk, pwv, rc, rs,
                                         qh, ql, kh, vth, vtl);

    // flash attention -> packed fp16 pao
    flash_mma<<<dim3(S_LEN / 128, NHEAD), 256, FA_SMEM>>>(qh, ql, kh, vth, vtl, pao);

    // output projection
    dim3 gg(EMB / 256, S_LEN / 128);
    gemm_bulk<<<gg, 256, GB_SMEM>>>(pao, pwo, out);
}

// round 11
// speedup vs baseline: 1.5303x; 1.2181x over previous
#include <cuda_runtime.h>
#include <cuda_bf16.h>
#include <cuda_fp16.h>
#include <math.h>
#include <stdint.h>

#define S_LEN 2048
#define EMB   2048
#define NHEAD 16
#define HDIM  128

// ---------------- scratch (no cudaMalloc allowed) ----------------
// packed fp16 GEMM operands (stage-contiguous, swizzled)
__device__ __align__(256) __half g_px [S_LEN * EMB];
__device__ __align__(256) __half g_pao[S_LEN * EMB];
__device__ __align__(256) __half g_pwq[EMB * EMB];
__device__ __align__(256) __half g_pwk[EMB * EMB];
__device__ __align__(256) __half g_pwv[EMB * EMB];
__device__ __align__(256) __half g_pwo[EMB * EMB];

// attention operands (fp16, single precision level)
__device__ __half g_qh [S_LEN * EMB];
__device__ __half g_kh [S_LEN * EMB];
__device__ __half g_vth[NHEAD * HDIM * S_LEN];   // [h][d][s]

// ================= helpers (baseline PTX only) ==============
__device__ __forceinline__ uint32_t s2u(const void* p) {
    uint32_t a;
    asm("{ .reg .u64 t; cvta.to.shared.u64 t, %1; cvt.u32.u64 %0, t; }"
        : "=r"(a) : "l"(p));
    return a;
}

__device__ __forceinline__ void cpa16(uint32_t dst, const void* src) {
    asm volatile("cp.async.cg.shared.global [%0], [%1], 16;" :: "r"(dst), "l"(src));
}
#define CPA_COMMIT() asm volatile("cp.async.commit_group;" ::: "memory")
#define CPA_WAIT1()  asm volatile("cp.async.wait_group 1;" ::: "memory")

__device__ __forceinline__ void ldsm4(uint32_t addr, uint32_t& r0, uint32_t& r1,
                                      uint32_t& r2, uint32_t& r3) {
    asm volatile("ldmatrix.sync.aligned.m8n8.x4.shared.b16 {%0,%1,%2,%3}, [%4];"
                 : "=r"(r0), "=r"(r1), "=r"(r2), "=r"(r3) : "r"(addr));
}

__device__ __forceinline__ void mma_f16(float* d, const uint32_t* a,
                                        uint32_t b0, uint32_t b1) {
    asm volatile(
        "mma.sync.aligned.m16n8k16.row.col.f32.f16.f16.f32 "
        "{%0,%1,%2,%3}, {%4,%5,%6,%7}, {%8,%9}, {%0,%1,%2,%3};"
        : "+f"(d[0]), "+f"(d[1]), "+f"(d[2]), "+f"(d[3])
        : "r"(a[0]), "r"(a[1]), "r"(a[2]), "r"(a[3]), "r"(b0), "r"(b1));
}

__device__ __forceinline__ uint32_t h2u(__half2 v) {
    return *reinterpret_cast<uint32_t*>(&v);
}

// ---- mbarrier / bulk-copy (sm_90 baseline PTX) ----
#define MBAR_INIT(mbar, cnt) \
    asm volatile("mbarrier.init.shared.b64 [%0], %1;" \
                 :: "r"((uint32_t)(mbar)), "r"((uint32_t)(cnt)) : "memory")
#define MBAR_EXPECT_TX(mbar, bytes) \
    asm volatile("mbarrier.arrive.expect_tx.shared.b64 _, [%0], %1;" \
                 :: "r"((uint32_t)(mbar)), "r"((uint32_t)(bytes)) : "memory")
#define MBAR_ARRIVE(mbar) \
    asm volatile("mbarrier.arrive.shared.b64 _, [%0];" \
                 :: "r"((uint32_t)(mbar)) : "memory")

__device__ __forceinline__ void mbar_wait(uint32_t mbar, uint32_t phase) {
    asm volatile(
        "{\n\t.reg .pred P1;\n\t"
        "WAIT_LOOP_%=:\n\t"
        "mbarrier.try_wait.parity.acquire.cta.shared::cta.b64 P1, [%0], %1, 0x989680;\n\t"
        "@P1 bra.uni WAIT_DONE_%=;\n\t"
        "bra.uni WAIT_LOOP_%=;\n\t"
        "WAIT_DONE_%=:\n\t}"
        :: "r"(mbar), "r"(phase) : "memory");
}

__device__ __forceinline__ void bulkcp(uint32_t dst, const void* src,
                                       uint32_t bytes, uint32_t mbar) {
    asm volatile(
        "cp.async.bulk.shared::cluster.global.mbarrier::complete_tx::bytes "
        "[%0], [%1], %2, [%3];"
        :: "r"(dst), "l"(src), "r"(bytes), "r"(mbar) : "memory");
}

// ================= repack fp32 -> fp16, stage-contiguous + XOR swizzle ====
__device__ __forceinline__ void pack_row(
    const float* __restrict__ src, __half* __restrict__ dst,
    int r, int t, int blkrows)
{
    const int ks  = t >> 3;
    const int cs  = t & 7;
    const int rin = r & (blkrows - 1);
    const int blk = r / blkrows;
    const int c   = cs ^ (rin & 7);

    const float* s = src + (size_t)r * EMB + ks * 64 + c * 8;
    float4 v0 = *(const float4*)(s);
    float4 v1 = *(const float4*)(s + 4);

    __half2 h0 = __floats2half2_rn(v0.x, v0.y);
    __half2 h1 = __floats2half2_rn(v0.z, v0.w);
    __half2 h2 = __floats2half2_rn(v1.x, v1.y);
    __half2 h3 = __floats2half2_rn(v1.z, v1.w);

    size_t chunk = ((size_t)(blk * 32 + ks) * blkrows + rin) * 8 + cs;
    uint4 out;
    out.x = h2u(h0); out.y = h2u(h1); out.z = h2u(h2); out.w = h2u(h3);
    *(reinterpret_cast<uint4*>(dst) + chunk) = out;
}

__global__ __launch_bounds__(256) void conv_pack(
    const float* __restrict__ src, __half* __restrict__ dst, int blkrows)
{
    pack_row(src, dst, blockIdx.x, threadIdx.x, blkrows);
}

__global__ __launch_bounds__(256) void conv_pack_w4(
    const float* __restrict__ w0, const float* __restrict__ w1,
    const float* __restrict__ w2, const float* __restrict__ w3,
    __half* __restrict__ d0, __half* __restrict__ d1,
    __half* __restrict__ d2, __half* __restrict__ d3)
{
    const float* s;
    __half* d;
    switch (blockIdx.y) {
        case 0: s = w0; d = d0; break;
        case 1: s = w1; d = d1; break;
        case 2: s = w2; d = d2; break;
        default: s = w3; d = d3; break;
    }
    pack_row(s, d, blockIdx.x, threadIdx.x, 256);
}

// ================= TMA-bulk fp16 GEMM mainloop (round-7 proven config) ====
// CTA tile 128x256, 8 warps (2x4), warp tile 64x64. K staged 64; 3-slot ring.
#define GB_A_BYTES 16384
#define GB_B_BYTES 32768
#define GB_STAGE   49152
#define GB_SMEM    (3 * GB_STAGE + 128)

__device__ __forceinline__ void gemm_main(
    const __half* __restrict__ Ap, const __half* __restrict__ Bp,
    int bx, int by, float acc[4][8][4])
{
    extern __shared__ char smraw[];
    const uint32_t sbase = s2u(smraw);
    const uint32_t mb    = sbase + 3 * GB_STAGE;

    const int tid  = threadIdx.x;
    const int lane = tid & 31;
    const int wid  = tid >> 5;
    const int wm   = wid & 1;
    const int wn   = wid >> 1;

    const int l8 = lane & 7;
    const int mt = lane >> 3;

    int rA[4], rB[4];
#pragma unroll
    for (int i = 0; i < 4; i++)
        rA[i] = wm * 64 + i * 16 + (mt & 1) * 8 + l8;
#pragma unroll
    for (int j = 0; j < 4; j++)
        rB[j] = wn * 64 + j * 16 + (mt >> 1) * 8 + l8;
    const int hcA = mt >> 1;
    const int hcB = mt & 1;

#pragma unroll
    for (int i = 0; i < 4; i++)
#pragma unroll
        for (int j = 0; j < 8; j++)
#pragma unroll
            for (int t = 0; t < 4; t++) acc[i][j][t] = 0.f;

    if (tid == 0) {
#pragma unroll
        for (int i = 0; i < 3; i++) {
            MBAR_INIT(mb + i * 16, 1);
            MBAR_INIT(mb + i * 16 + 8, 8);
        }
    }
    __syncthreads();

    const __half* Asrc = Ap + (size_t)by * 32 * 128 * 64;
    const __half* Bsrc = Bp + (size_t)bx * 32 * 256 * 64;

    if (tid == 0) {
#pragma unroll
        for (int i = 0; i < 3; i++) {
            MBAR_EXPECT_TX(mb + i * 16, GB_STAGE);
            bulkcp(sbase + i * GB_STAGE, Asrc + (size_t)i * 128 * 64,
                   GB_A_BYTES, mb + i * 16);
            bulkcp(sbase + i * GB_STAGE + GB_A_BYTES, Bsrc + (size_t)i * 256 * 64,
                   GB_B_BYTES, mb + i * 16);
        }
    }

    const int NST = EMB / 64;
    for (int s = 0; s < NST; s++) {
        const int sl = s - (s / 3) * 3;
        const uint32_t ph = (uint32_t)((s / 3) & 1);
        const uint32_t slot = sbase + sl * GB_STAGE;

        mbar_wait(mb + sl * 16, ph);

#pragma unroll
        for (int ks = 0; ks < 4; ks++) {
            uint32_t a[4][4];
#pragma unroll
            for (int i = 0; i < 4; i++) {
                uint32_t ch = (uint32_t)((2 * ks + hcA) ^ (rA[i] & 7));
                ldsm4(slot + rA[i] * 128 + ch * 16,
                      a[i][0], a[i][1], a[i][2], a[i][3]);
            }
            uint32_t b[4][4];
#pragma unroll
            for (int j = 0; j < 4; j++) {
                uint32_t ch = (uint32_t)((2 * ks + hcB) ^ (rB[j] & 7));
                ldsm4(slot + GB_A_BYTES + rB[j] * 128 + ch * 16,
                      b[j][0], b[j][1], b[j][2], b[j][3]);
            }
#pragma unroll
            for (int i = 0; i < 4; i++)
#pragma unroll
                for (int j = 0; j < 4; j++) {
                    mma_f16(acc[i][j * 2 + 0], a[i], b[j][0], b[j][1]);
                    mma_f16(acc[i][j * 2 + 1], a[i], b[j][2], b[j][3]);
                }
        }

        if (lane == 0) MBAR_ARRIVE(mb + sl * 16 + 8);

        if (tid == 0 && s + 3 < NST) {
            mbar_wait(mb + sl * 16 + 8, ph);
            MBAR_EXPECT_TX(mb + sl * 16, GB_STAGE);
            bulkcp(slot, Asrc + (size_t)(s + 3) * 128 * 64,
                   GB_A_BYTES, mb + sl * 16);
            bulkcp(slot + GB_A_BYTES, Bsrc + (size_t)(s + 3) * 256 * 64,
                   GB_B_BYTES, mb + sl * 16);
        }
    }
}

// ---- Wo GEMM: plain fp32 epilogue ----
__global__ __launch_bounds__(256, 1) void gemm_bulk(
    const __half* __restrict__ Ap, const __half* __restrict__ Bp,
    float* __restrict__ C)
{
    float acc[4][8][4];
    gemm_main(Ap, Bp, blockIdx.x, blockIdx.y, acc);

    const int tid  = threadIdx.x;
    const int lane = tid & 31;
    const int wid  = tid >> 5;
    const int wm   = wid & 1;
    const int wn   = wid >> 1;
    const int bm   = blockIdx.y * 128;
    const int bn   = blockIdx.x * 256;
    const int g = lane >> 2;
    const int q = (lane & 3) * 2;
#pragma unroll
    for (int i = 0; i < 4; i++) {
#pragma unroll
        for (int j = 0; j < 8; j++) {
            int row = bm + wm * 64 + i * 16 + g;
            int col = bn + wn * 64 + j * 8 + q;
            *(float2*)(C + (size_t)row * EMB + col) =
                make_float2(acc[i][j][0], acc[i][j][1]);
            *(float2*)(C + (size_t)(row + 8) * EMB + col) =
                make_float2(acc[i][j][2], acc[i][j][3]);
        }
    }
}

// ---- fused QKV GEMM: epilogue RoPE (Q scaled, K), transpose (V) ----
#define EP_STRIDE 265   // floats; %32 == 9 -> conflict-free column reads

__global__ __launch_bounds__(256, 1) void gemm_qkv_fused(
    const __half* __restrict__ Ap,
    const __half* __restrict__ Bq, const __half* __restrict__ Bk,
    const __half* __restrict__ Bv,
    const float* __restrict__ cosb, const float* __restrict__ sinb,
    __half* __restrict__ qh, __half* __restrict__ kh,
    __half* __restrict__ vth)
{
    const int z = blockIdx.z;
    const __half* Bp = (z == 0) ? Bq : (z == 1) ? Bk : Bv;

    float acc[4][8][4];
    gemm_main(Ap, Bp, blockIdx.x, blockIdx.y, acc);

    extern __shared__ char smraw[];
    float* smf = reinterpret_cast<float*>(smraw);

    const int tid  = threadIdx.x;
    const int lane = tid & 31;
    const int wid  = tid >> 5;
    const int wm   = wid & 1;
    const int wn   = wid >> 1;
    const int bm   = blockIdx.y * 128;
    const int bn   = blockIdx.x * 256;
    const int g = lane >> 2;
    const int q = (lane & 3) * 2;

    __syncthreads();   // all warps out of mainloop before overwriting smem

#pragma unroll
    for (int i = 0; i < 4; i++) {
#pragma unroll
        for (int j = 0; j < 8; j++) {
            int row = wm * 64 + i * 16 + g;
            int col = wn * 64 + j * 8 + q;
            smf[row * EP_STRIDE + col]           = acc[i][j][0];
            smf[row * EP_STRIDE + col + 1]       = acc[i][j][1];
            smf[(row + 8) * EP_STRIDE + col]     = acc[i][j][2];
            smf[(row + 8) * EP_STRIDE + col + 1] = acc[i][j][3];
        }
    }
    __syncthreads();

    if (z < 2) {
        // RoPE -> single fp16
        __half* dst = (z == 0) ? qh : kh;
        const float sc = (z == 0) ? 0.088388347648318447f : 1.f;
        const int c  = tid;
        const int hd = c & 127;
        const bool low = hd < 64;
#pragma unroll 4
        for (int s = 0; s < 128; s++) {
            float a = smf[s * EP_STRIDE + c];
            float b = smf[s * EP_STRIDE + (c ^ 64)];
            int srow = bm + s;
            float cv = cosb[srow * HDIM + hd];
            float sv = sinb[srow * HDIM + hd];
            float out = (low ? (a * cv - b * sv) : (a * cv + b * sv)) * sc;
            dst[(size_t)srow * EMB + bn + c] = __float2half_rn(out);
        }
    } else {
        // V: transpose -> single fp16
        const int c0 = wid * 32;
#pragma unroll 2
        for (int cc = 0; cc < 32; cc++) {
            int col  = c0 + cc;
            int hloc = col >> 7;
            int d    = col & 127;
            size_t rowbase = ((size_t)((blockIdx.x * 2 + hloc) * HDIM + d)) * S_LEN + bm;
#pragma unroll
            for (int s4 = 0; s4 < 4; s4++) {
                int s = s4 * 32 + lane;
                vth[rowbase + s] = __float2half_rn(smf[s * EP_STRIDE + col]);
            }
        }
    }
}

// ---------------- Flash attention (mma.sync, fp16 single-pass) ------------
#define QB_ROW  272
#define KB_ROW  272
#define VB_ROW  144
#define SM_Q    (128 * QB_ROW)          // 34816, single plane
#define SM_KPL  (64 * KB_ROW)           // 17408
#define SM_VPL  (128 * VB_ROW)          // 18432
#define SM_KV   (SM_KPL + SM_VPL)       // 35840 per buffer
#define FA_SMEM (SM_Q + 2 * SM_KV)      // 106496

__global__ __launch_bounds__(256, 1) void flash_mma(
    const __half* __restrict__ qh, const __half* __restrict__ kh,
    const __half* __restrict__ vth,
    __half* __restrict__ pao)
{
    extern __shared__ char smraw[];
    const uint32_t sQ = s2u(smraw);

    const int tid  = threadIdx.x;
    const int lane = tid & 31;
    const int w    = tid >> 5;
    const int g    = lane >> 2;
    const int qd   = lane & 3;
    const int l8   = lane & 7;
    const int mt   = lane >> 3;
    const int qbi  = gridDim.x - 1 - blockIdx.x;   // heaviest CTAs first
    const int h    = blockIdx.y;

    const uint32_t offAq = (uint32_t)((w * 16 + (mt & 1) * 8 + l8) * QB_ROW + (mt >> 1) * 16);
    uint32_t offBk[4], offBv[8];
#pragma unroll
    for (int j = 0; j < 4; j++)
        offBk[j] = (uint32_t)((j * 16 + (mt >> 1) * 8 + l8) * KB_ROW + (mt & 1) * 16);
#pragma unroll
    for (int j = 0; j < 8; j++)
        offBv[j] = (uint32_t)((j * 16 + (mt >> 1) * 8 + l8) * VB_ROW + (mt & 1) * 16);

    // ---- load Q (single plane) ----
#pragma unroll
    for (int i = 0; i < 8; i++) {
        int e = tid + i * 256;
        int r = (e >> 4) & 127;
        int c = e & 15;
        const __half* s = qh + (size_t)(qbi * 128 + r) * EMB + h * HDIM + c * 8;
        cpa16(sQ + r * QB_ROW + c * 16, s);
    }

    auto load_kv = [&](int buf, int kb) {
        uint32_t kvb = sQ + SM_Q + buf * SM_KV;
#pragma unroll
        for (int i = 0; i < 4; i++) {           // K
            int e = tid + i * 256;
            int r = (e >> 4) & 63;
            int c = e & 15;
            const __half* s = kh + (size_t)(kb * 64 + r) * EMB + h * HDIM + c * 8;
            cpa16(kvb + r * KB_ROW + c * 16, s);
        }
#pragma unroll
        for (int i = 0; i < 4; i++) {           // V (transposed)
            int e = tid + i * 256;
            int r = (e >> 3) & 127;
            int c = e & 7;
            const __half* s = vth + (size_t)(h * HDIM + r) * S_LEN + kb * 64 + c * 8;
            cpa16(kvb + SM_KPL + r * VB_ROW + c * 16, s);
        }
    };

    const int nkb = 2 * qbi + 2;
    load_kv(0, 0);
    CPA_COMMIT();

    float acco[16][4];
#pragma unroll
    for (int j = 0; j < 16; j++)
#pragma unroll
        for (int t = 0; t < 4; t++) acco[j][t] = 0.f;
    float m0 = -1e30f, m8 = -1e30f, l0 = 0.f, lsum8 = 0.f;

    const int row0 = qbi * 128 + w * 16 + g;
    const int row8 = row0 + 8;

    for (int kb = 0; kb < nkb; kb++) {
        if (kb + 1 < nkb) load_kv((kb + 1) & 1, kb + 1);
        CPA_COMMIT();
        CPA_WAIT1();
        __syncthreads();

        const uint32_t kvb = sQ + SM_Q + (kb & 1) * SM_KV;

        // ---- S = Q K^T (single pass) ----
        float accs[8][4];
#pragma unroll
        for (int j = 0; j < 8; j++)
#pragma unroll
            for (int t = 0; t < 4; t++) accs[j][t] = 0.f;

#pragma unroll
        for (int ks = 0; ks < 8; ks++) {
            uint32_t a[4];
            ldsm4(sQ + offAq + ks * 32, a[0], a[1], a[2], a[3]);
#pragma unroll
            for (int j = 0; j < 4; j++) {
                uint32_t b0, b1, b2, b3;
                ldsm4(kvb + offBk[j] + ks * 32, b0, b1, b2, b3);
                mma_f16(accs[j * 2 + 0], a, b0, b1);
                mma_f16(accs[j * 2 + 1], a, b2, b3);
            }
        }

        if (kb >= 2 * qbi) {
#pragma unroll
            for (int jt = 0; jt < 8; jt++) {
                int col = kb * 64 + jt * 8 + 2 * qd;
                if (col     > row0) accs[jt][0] = -1e30f;
                if (col + 1 > row0) accs[jt][1] = -1e30f;
                if (col     > row8) accs[jt][2] = -1e30f;
                if (col + 1 > row8) accs[jt][3] = -1e30f;
            }
        }

        // ---- online softmax ----
        float mx0 = -1e30f, mx8 = -1e30f;
#pragma unroll
        for (int jt = 0; jt < 8; jt++) {
            mx0 = fmaxf(mx0, fmaxf(accs[jt][0], accs[jt][1]));
            mx8 = fmaxf(mx8, fmaxf(accs[jt][2], accs[jt][3]));
        }
        mx0 = fmaxf(mx0, __shfl_xor_sync(0xffffffffu, mx0, 1));
        mx0 = fmaxf(mx0, __shfl_xor_sync(0xffffffffu, mx0, 2));
        mx8 = fmaxf(mx8, __shfl_xor_sync(0xffffffffu, mx8, 1));
        mx8 = fmaxf(mx8, __shfl_xor_sync(0xffffffffu, mx8, 2));

        float nm0 = fmaxf(m0, mx0), nm8 = fmaxf(m8, mx8);
        float al0 = __expf(m0 - nm0), al8 = __expf(m8 - nm8);
        m0 = nm0; m8 = nm8;

        float s0 = 0.f, s8 = 0.f;
#pragma unroll
        for (int jt = 0; jt < 8; jt++) {
            accs[jt][0] = __expf(accs[jt][0] - nm0);
            accs[jt][1] = __expf(accs[jt][1] - nm0);
            accs[jt][2] = __expf(accs[jt][2] - nm8);
            accs[jt][3] = __expf(accs[jt][3] - nm8);
            s0 += accs[jt][0] + accs[jt][1];
            s8 += accs[jt][2] + accs[jt][3];
        }
        s0 += __shfl_xor_sync(0xffffffffu, s0, 1);
        s0 += __shfl_xor_sync(0xffffffffu, s0, 2);
        s8 += __shfl_xor_sync(0xffffffffu, s8, 1);
        s8 += __shfl_xor_sync(0xffffffffu, s8, 2);
        l0 = l0 * al0 + s0;
        lsum8 = lsum8 * al8 + s8;

#pragma unroll
        for (int j = 0; j < 16; j++) {
            acco[j][0] *= al0; acco[j][1] *= al0;
            acco[j][2] *= al8; acco[j][3] *= al8;
        }

        // ---- P -> fp16 fragments ----
        uint32_t pf[8][2];
#pragma unroll
        for (int jt = 0; jt < 8; jt++) {
            pf[jt][0] = h2u(__floats2half2_rn(accs[jt][0], accs[jt][1]));
            pf[jt][1] = h2u(__floats2half2_rn(accs[jt][2], accs[jt][3]));
        }

        // ---- O += P V (single pass) ----
        const uint32_t vbase = kvb + SM_KPL;
#pragma unroll
        for (int t = 0; t < 4; t++) {
            uint32_t a[4];
            a[0] = pf[2 * t][0]; a[1] = pf[2 * t][1];
            a[2] = pf[2 * t + 1][0]; a[3] = pf[2 * t + 1][1];
#pragma unroll
            for (int jn = 0; jn < 8; jn++) {
                uint32_t b0, b1, b2, b3;
                ldsm4(vbase + offBv[jn] + t * 32, b0, b1, b2, b3);
                mma_f16(acco[jn * 2 + 0], a, b0, b1);
                mma_f16(acco[jn * 2 + 1], a, b2, b3);
            }
        }
        __syncthreads();
    }

    // ---- epilogue: write packed fp16 directly (layout consumed by Wo GEMM)
    float inv0 = 1.f / l0, inv8 = 1.f / lsum8;
    const int blk  = qbi;
    const int rin0 = w * 16 + g;
    const int rin8 = rin0 + 8;
#pragma unroll
    for (int jt = 0; jt < 16; jt++) {
        int ks = h * 2 + (jt >> 3);
        int c8 = jt & 7;
        size_t chunk0 = ((size_t)(blk * 32 + ks) * 128 + rin0) * 8 + (c8 ^ (rin0 & 7));
        size_t chunk8 = ((size_t)(blk * 32 + ks) * 128 + rin8) * 8 + (c8 ^ (rin8 & 7));
        __half2 v0 = __floats2half2_rn(acco[jt][0] * inv0, acco[jt][1] * inv0);
        __half2 v8 = __floats2half2_rn(acco[jt][2] * inv8, acco[jt][3] * inv8);
        *reinterpret_cast<__half2*>(pao + chunk0 * 8 + qd * 2) = v0;
        *reinterpret_cast<__half2*>(pao + chunk8 * 8 + qd * 2) = v8;
    }
}

// ---------------- launch ----------------
extern "C" void kernel_launch(void* const* d_in, const int* in_sizes, int n_in,
                              void* d_out, int out_size)
{
    const float* x  = (const float*)d_in[0];
    const float* rc = (const float*)d_in[1];
    const float* rs = (const float*)d_in[2];
    const float* Wq = (const float*)d_in[3];
    const float* Wk = (const float*)d_in[4];
    const float* Wv = (const float*)d_in[5];
    const float* Wo = (const float*)d_in[6];
    float* out = (float*)d_out;

    __half *px, *pao, *pwq, *pwk, *pwv, *pwo;
    cudaGetSymbolAddress((void**)&px,  g_px);
    cudaGetSymbolAddress((void**)&pao, g_pao);
    cudaGetSymbolAddress((void**)&pwq, g_pwq);
    cudaGetSymbolAddress((void**)&pwk, g_pwk);
    cudaGetSymbolAddress((void**)&pwv, g_pwv);
    cudaGetSymbolAddress((void**)&pwo, g_pwo);

    __half *qh, *kh, *vth;
    cudaGetSymbolAddress((void**)&qh,  g_qh);
    cudaGetSymbolAddress((void**)&kh,  g_kh);
    cudaGetSymbolAddress((void**)&vth, g_vth);

    cudaFuncSetAttribute(gemm_bulk,
                         cudaFuncAttributeMaxDynamicSharedMemorySize, GB_SMEM);
    cudaFuncSetAttribute(gemm_qkv_fused,
                         cudaFuncAttributeMaxDynamicSharedMemorySize, GB_SMEM);
    cudaFuncSetAttribute(flash_mma,
                         cudaFuncAttributeMaxDynamicSharedMemorySize, FA_SMEM);

    // repack inputs
    conv_pack<<<S_LEN, 256>>>(x, px, 128);
    conv_pack_w4<<<dim3(EMB, 4), 256>>>(Wq, Wk, Wv, Wo, pwq, pwk, pwv, pwo);

    // fused QKV projection + RoPE/transpose epilogue
    dim3 gq(EMB / 256, S_LEN / 128, 3);
    gemm_qkv_fused<<<gq, 256, GB_SMEM>>>(px, pwq, pwk, pwv, rc, rs,
                                         qh, kh, vth);

    // flash attention -> packed fp16 pao
    flash_mma<<<dim3(S_LEN / 128, NHEAD), 256, FA_SMEM>>>(qh, kh, vth, pao);

    // output projection
    dim3 gg(EMB / 256, S_LEN / 128);
    gemm_bulk<<<gg, 256, GB_SMEM>>>(pao, pwo, out);
}

// round 12
// speedup vs baseline: 1.5716x; 1.0270x over previous
#include <cuda_runtime.h>
#include <cuda_bf16.h>
#include <cuda_fp16.h>
#include <math.h>
#include <stdint.h>

#define S_LEN 2048
#define EMB   2048
#define NHEAD 16
#define HDIM  128

// ---------------- scratch (no cudaMalloc allowed) ----------------
// packed fp16 GEMM operands (stage-contiguous, swizzled)
__device__ __align__(256) __half g_px [S_LEN * EMB];
__device__ __align__(256) __half g_pao[S_LEN * EMB];
__device__ __align__(256) __half g_pwq[EMB * EMB];
__device__ __align__(256) __half g_pwk[EMB * EMB];
__device__ __align__(256) __half g_pwv[EMB * EMB];
__device__ __align__(256) __half g_pwo[EMB * EMB];

// attention operands (fp16, single precision level)
__device__ __half g_qh [S_LEN * EMB];
__device__ __half g_kh [S_LEN * EMB];
__device__ __half g_vth[NHEAD * HDIM * S_LEN];   // [h][d][s]

// ================= helpers (baseline PTX only) ==============
__device__ __forceinline__ uint32_t s2u(const void* p) {
    uint32_t a;
    asm("{ .reg .u64 t; cvta.to.shared.u64 t, %1; cvt.u32.u64 %0, t; }"
        : "=r"(a) : "l"(p));
    return a;
}

__device__ __forceinline__ void cpa16(uint32_t dst, const void* src) {
    asm volatile("cp.async.cg.shared.global [%0], [%1], 16;" :: "r"(dst), "l"(src));
}
#define CPA_COMMIT() asm volatile("cp.async.commit_group;" ::: "memory")
#define CPA_WAIT1()  asm volatile("cp.async.wait_group 1;" ::: "memory")

__device__ __forceinline__ void ldsm4(uint32_t addr, uint32_t& r0, uint32_t& r1,
                                      uint32_t& r2, uint32_t& r3) {
    asm volatile("ldmatrix.sync.aligned.m8n8.x4.shared.b16 {%0,%1,%2,%3}, [%4];"
                 : "=r"(r0), "=r"(r1), "=r"(r2), "=r"(r3) : "r"(addr));
}

__device__ __forceinline__ void mma_f16(float* d, const uint32_t* a,
                                        uint32_t b0, uint32_t b1) {
    asm volatile(
        "mma.sync.aligned.m16n8k16.row.col.f32.f16.f16.f32 "
        "{%0,%1,%2,%3}, {%4,%5,%6,%7}, {%8,%9}, {%0,%1,%2,%3};"
        : "+f"(d[0]), "+f"(d[1]), "+f"(d[2]), "+f"(d[3])
        : "r"(a[0]), "r"(a[1]), "r"(a[2]), "r"(a[3]), "r"(b0), "r"(b1));
}

__device__ __forceinline__ uint32_t h2u(__half2 v) {
    return *reinterpret_cast<uint32_t*>(&v);
}

// ---- mbarrier / bulk-copy (sm_90 baseline PTX) ----
#define MBAR_INIT(mbar, cnt) \
    asm volatile("mbarrier.init.shared.b64 [%0], %1;" \
                 :: "r"((uint32_t)(mbar)), "r"((uint32_t)(cnt)) : "memory")
#define MBAR_EXPECT_TX(mbar, bytes) \
    asm volatile("mbarrier.arrive.expect_tx.shared.b64 _, [%0], %1;" \
                 :: "r"((uint32_t)(mbar)), "r"((uint32_t)(bytes)) : "memory")
#define MBAR_ARRIVE(mbar) \
    asm volatile("mbarrier.arrive.shared.b64 _, [%0];" \
                 :: "r"((uint32_t)(mbar)) : "memory")

__device__ __forceinline__ void mbar_wait(uint32_t mbar, uint32_t phase) {
    asm volatile(
        "{\n\t.reg .pred P1;\n\t"
        "WAIT_LOOP_%=:\n\t"
        "mbarrier.try_wait.parity.acquire.cta.shared::cta.b64 P1, [%0], %1, 0x989680;\n\t"
        "@P1 bra.uni WAIT_DONE_%=;\n\t"
        "bra.uni WAIT_LOOP_%=;\n\t"
        "WAIT_DONE_%=:\n\t}"
        :: "r"(mbar), "r"(phase) : "memory");
}

__device__ __forceinline__ void bulkcp(uint32_t dst, const void* src,
                                       uint32_t bytes, uint32_t mbar) {
    asm volatile(
        "cp.async.bulk.shared::cluster.global.mbarrier::complete_tx::bytes "
        "[%0], [%1], %2, [%3];"
        :: "r"(dst), "l"(src), "r"(bytes), "r"(mbar) : "memory");
}

// ================= repack fp32 -> fp16, stage-contiguous + XOR swizzle ====
__device__ __forceinline__ void pack_row(
    const float* __restrict__ src, __half* __restrict__ dst,
    int r, int t, int blkrows)
{
    const int ks  = t >> 3;
    const int cs  = t & 7;
    const int rin = r & (blkrows - 1);
    const int blk = r / blkrows;
    const int c   = cs ^ (rin & 7);

    const float* s = src + (size_t)r * EMB + ks * 64 + c * 8;
    float4 v0 = *(const float4*)(s);
    float4 v1 = *(const float4*)(s + 4);

    __half2 h0 = __floats2half2_rn(v0.x, v0.y);
    __half2 h1 = __floats2half2_rn(v0.z, v0.w);
    __half2 h2 = __floats2half2_rn(v1.x, v1.y);
    __half2 h3 = __floats2half2_rn(v1.z, v1.w);

    size_t chunk = ((size_t)(blk * 32 + ks) * blkrows + rin) * 8 + cs;
    uint4 out;
    out.x = h2u(h0); out.y = h2u(h1); out.z = h2u(h2); out.w = h2u(h3);
    *(reinterpret_cast<uint4*>(dst) + chunk) = out;
}

__global__ __launch_bounds__(256) void conv_pack(
    const float* __restrict__ src, __half* __restrict__ dst, int blkrows)
{
    pack_row(src, dst, blockIdx.x, threadIdx.x, blkrows);
}

__global__ __launch_bounds__(256) void conv_pack_w4(
    const float* __restrict__ w0, const float* __restrict__ w1,
    const float* __restrict__ w2, const float* __restrict__ w3,
    __half* __restrict__ d0, __half* __restrict__ d1,
    __half* __restrict__ d2, __half* __restrict__ d3)
{
    const float* s;
    __half* d;
    switch (blockIdx.y) {
        case 0: s = w0; d = d0; break;
        case 1: s = w1; d = d1; break;
        case 2: s = w2; d = d2; break;
        default: s = w3; d = d3; break;
    }
    pack_row(s, d, blockIdx.x, threadIdx.x, 256);
}

// ================= TMA-bulk fp16 GEMM mainloop (round-7 proven config) ====
// CTA tile 128x256, 8 warps (2x4), warp tile 64x64. K staged 64; 3-slot ring.
#define GB_A_BYTES 16384
#define GB_B_BYTES 32768
#define GB_STAGE   49152
#define GB_SMEM    (3 * GB_STAGE + 128)

__device__ __forceinline__ void gemm_main(
    const __half* __restrict__ Ap, const __half* __restrict__ Bp,
    int bx, int by, float acc[4][8][4])
{
    extern __shared__ char smraw[];
    const uint32_t sbase = s2u(smraw);
    const uint32_t mb    = sbase + 3 * GB_STAGE;

    const int tid  = threadIdx.x;
    const int lane = tid & 31;
    const int wid  = tid >> 5;
    const int wm   = wid & 1;
    const int wn   = wid >> 1;

    const int l8 = lane & 7;
    const int mt = lane >> 3;

    int rA[4], rB[4];
#pragma unroll
    for (int i = 0; i < 4; i++)
        rA[i] = wm * 64 + i * 16 + (mt & 1) * 8 + l8;
#pragma unroll
    for (int j = 0; j < 4; j++)
        rB[j] = wn * 64 + j * 16 + (mt >> 1) * 8 + l8;
    const int hcA = mt >> 1;
    const int hcB = mt & 1;

#pragma unroll
    for (int i = 0; i < 4; i++)
#pragma unroll
        for (int j = 0; j < 8; j++)
#pragma unroll
            for (int t = 0; t < 4; t++) acc[i][j][t] = 0.f;

    if (tid == 0) {
#pragma unroll
        for (int i = 0; i < 3; i++) {
            MBAR_INIT(mb + i * 16, 1);
            MBAR_INIT(mb + i * 16 + 8, 8);
        }
    }
    __syncthreads();

    const __half* Asrc = Ap + (size_t)by * 32 * 128 * 64;
    const __half* Bsrc = Bp + (size_t)bx * 32 * 256 * 64;

    if (tid == 0) {
#pragma unroll
        for (int i = 0; i < 3; i++) {
            MBAR_EXPECT_TX(mb + i * 16, GB_STAGE);
            bulkcp(sbase + i * GB_STAGE, Asrc + (size_t)i * 128 * 64,
                   GB_A_BYTES, mb + i * 16);
            bulkcp(sbase + i * GB_STAGE + GB_A_BYTES, Bsrc + (size_t)i * 256 * 64,
                   GB_B_BYTES, mb + i * 16);
        }
    }

    const int NST = EMB / 64;
    for (int s = 0; s < NST; s++) {
        const int sl = s - (s / 3) * 3;
        const uint32_t ph = (uint32_t)((s / 3) & 1);
        const uint32_t slot = sbase + sl * GB_STAGE;

        mbar_wait(mb + sl * 16, ph);

#pragma unroll
        for (int ks = 0; ks < 4; ks++) {
            uint32_t a[4][4];
#pragma unroll
            for (int i = 0; i < 4; i++) {
                uint32_t ch = (uint32_t)((2 * ks + hcA) ^ (rA[i] & 7));
                ldsm4(slot + rA[i] * 128 + ch * 16,
                      a[i][0], a[i][1], a[i][2], a[i][3]);
            }
            uint32_t b[4][4];
#pragma unroll
            for (int j = 0; j < 4; j++) {
                uint32_t ch = (uint32_t)((2 * ks + hcB) ^ (rB[j] & 7));
                ldsm4(slot + GB_A_BYTES + rB[j] * 128 + ch * 16,
                      b[j][0], b[j][1], b[j][2], b[j][3]);
            }
#pragma unroll
            for (int i = 0; i < 4; i++)
#pragma unroll
                for (int j = 0; j < 4; j++) {
                    mma_f16(acc[i][j * 2 + 0], a[i], b[j][0], b[j][1]);
                    mma_f16(acc[i][j * 2 + 1], a[i], b[j][2], b[j][3]);
                }
        }

        if (lane == 0) MBAR_ARRIVE(mb + sl * 16 + 8);

        if (tid == 0 && s + 3 < NST) {
            mbar_wait(mb + sl * 16 + 8, ph);
            MBAR_EXPECT_TX(mb + sl * 16, GB_STAGE);
            bulkcp(slot, Asrc + (size_t)(s + 3) * 128 * 64,
                   GB_A_BYTES, mb + sl * 16);
            bulkcp(slot + GB_A_BYTES, Bsrc + (size_t)(s + 3) * 256 * 64,
                   GB_B_BYTES, mb + sl * 16);
        }
    }
}

// ---- Wo GEMM: plain fp32 epilogue ----
__global__ __launch_bounds__(256, 1) void gemm_bulk(
    const __half* __restrict__ Ap, const __half* __restrict__ Bp,
    float* __restrict__ C)
{
    float acc[4][8][4];
    gemm_main(Ap, Bp, blockIdx.x, blockIdx.y, acc);

    const int tid  = threadIdx.x;
    const int lane = tid & 31;
    const int wid  = tid >> 5;
    const int wm   = wid & 1;
    const int wn   = wid >> 1;
    const int bm   = blockIdx.y * 128;
    const int bn   = blockIdx.x * 256;
    const int g = lane >> 2;
    const int q = (lane & 3) * 2;
#pragma unroll
    for (int i = 0; i < 4; i++) {
#pragma unroll
        for (int j = 0; j < 8; j++) {
            int row = bm + wm * 64 + i * 16 + g;
            int col = bn + wn * 64 + j * 8 + q;
            *(float2*)(C + (size_t)row * EMB + col) =
                make_float2(acc[i][j][0], acc[i][j][1]);
            *(float2*)(C + (size_t)(row + 8) * EMB + col) =
                make_float2(acc[i][j][2], acc[i][j][3]);
        }
    }
}

// ---- fused QKV GEMM: epilogue RoPE (Q scaled, K), transpose (V) ----
#define EP_STRIDE 265   // floats; %32 == 9 -> conflict-free column reads

__global__ __launch_bounds__(256, 1) void gemm_qkv_fused(
    const __half* __restrict__ Ap,
    const __half* __restrict__ Bq, const __half* __restrict__ Bk,
    const __half* __restrict__ Bv,
    const float* __restrict__ cosb, const float* __restrict__ sinb,
    __half* __restrict__ qh, __half* __restrict__ kh,
    __half* __restrict__ vth)
{
    const int z = blockIdx.z;
    const __half* Bp = (z == 0) ? Bq : (z == 1) ? Bk : Bv;

    float acc[4][8][4];
    gemm_main(Ap, Bp, blockIdx.x, blockIdx.y, acc);

    extern __shared__ char smraw[];
    float* smf = reinterpret_cast<float*>(smraw);

    const int tid  = threadIdx.x;
    const int lane = tid & 31;
    const int wid  = tid >> 5;
    const int wm   = wid & 1;
    const int wn   = wid >> 1;
    const int bm   = blockIdx.y * 128;
    const int bn   = blockIdx.x * 256;
    const int g = lane >> 2;
    const int q = (lane & 3) * 2;

    __syncthreads();   // all warps out of mainloop before overwriting smem

#pragma unroll
    for (int i = 0; i < 4; i++) {
#pragma unroll
        for (int j = 0; j < 8; j++) {
            int row = wm * 64 + i * 16 + g;
            int col = wn * 64 + j * 8 + q;
            smf[row * EP_STRIDE + col]           = acc[i][j][0];
            smf[row * EP_STRIDE + col + 1]       = acc[i][j][1];
            smf[(row + 8) * EP_STRIDE + col]     = acc[i][j][2];
            smf[(row + 8) * EP_STRIDE + col + 1] = acc[i][j][3];
        }
    }
    __syncthreads();

    if (z < 2) {
        // RoPE -> single fp16
        __half* dst = (z == 0) ? qh : kh;
        const float sc = (z == 0) ? 0.088388347648318447f : 1.f;
        const int c  = tid;
        const int hd = c & 127;
        const bool low = hd < 64;
#pragma unroll 4
        for (int s = 0; s < 128; s++) {
            float a = smf[s * EP_STRIDE + c];
            float b = smf[s * EP_STRIDE + (c ^ 64)];
            int srow = bm + s;
            float cv = cosb[srow * HDIM + hd];
            float sv = sinb[srow * HDIM + hd];
            float out = (low ? (a * cv - b * sv) : (a * cv + b * sv)) * sc;
            dst[(size_t)srow * EMB + bn + c] = __float2half_rn(out);
        }
    } else {
        // V: transpose -> single fp16
        const int c0 = wid * 32;
#pragma unroll 2
        for (int cc = 0; cc < 32; cc++) {
            int col  = c0 + cc;
            int hloc = col >> 7;
            int d    = col & 127;
            size_t rowbase = ((size_t)((blockIdx.x * 2 + hloc) * HDIM + d)) * S_LEN + bm;
#pragma unroll
            for (int s4 = 0; s4 < 4; s4++) {
                int s = s4 * 32 + lane;
                vth[rowbase + s] = __float2half_rn(smf[s * EP_STRIDE + col]);
            }
        }
    }
}

// ---------------- Flash attention (mma.sync, fp16, K-block = 128) ---------
#define QB_ROW  272
#define KB_ROW  272
#define VB_ROW  272
#define SM_Q    (128 * QB_ROW)          // 34816
#define SM_KPL  (128 * KB_ROW)          // 34816 (128 k-rows)
#define SM_VPL  (128 * VB_ROW)          // 34816 (128 d-rows x 128 s-cols)
#define SM_KV   (SM_KPL + SM_VPL)       // 69632 per buffer
#define FA_SMEM (SM_Q + 2 * SM_KV)      // 174080

__global__ __launch_bounds__(256, 1) void flash_mma(
    const __half* __restrict__ qh, const __half* __restrict__ kh,
    const __half* __restrict__ vth,
    __half* __restrict__ pao)
{
    extern __shared__ char smraw[];
    const uint32_t sQ = s2u(smraw);

    const int tid  = threadIdx.x;
    const int lane = tid & 31;
    const int w    = tid >> 5;
    const int g    = lane >> 2;
    const int qd   = lane & 3;
    const int l8   = lane & 7;
    const int mt   = lane >> 3;
    const int qbi  = gridDim.x - 1 - blockIdx.x;   // heaviest CTAs first
    const int h    = blockIdx.y;

    const uint32_t offAq = (uint32_t)((w * 16 + (mt & 1) * 8 + l8) * QB_ROW + (mt >> 1) * 16);
    uint32_t offBk[8], offBv[8];
#pragma unroll
    for (int j = 0; j < 8; j++)
        offBk[j] = (uint32_t)((j * 16 + (mt >> 1) * 8 + l8) * KB_ROW + (mt & 1) * 16);
#pragma unroll
    for (int j = 0; j < 8; j++)
        offBv[j] = (uint32_t)((j * 16 + (mt >> 1) * 8 + l8) * VB_ROW + (mt & 1) * 16);

    // ---- load Q (single plane, 128 rows x 128 halves) ----
#pragma unroll
    for (int i = 0; i < 8; i++) {
        int e = tid + i * 256;
        int r = (e >> 4) & 127;
        int c = e & 15;
        const __half* s = qh + (size_t)(qbi * 128 + r) * EMB + h * HDIM + c * 8;
        cpa16(sQ + r * QB_ROW + c * 16, s);
    }

    auto load_kv = [&](int buf, int kb) {
        uint32_t kvb = sQ + SM_Q + buf * SM_KV;
#pragma unroll
        for (int i = 0; i < 8; i++) {           // K: 128 rows x 128 halves
            int e = tid + i * 256;
            int r = (e >> 4) & 127;
            int c = e & 15;
            const __half* s = kh + (size_t)(kb * 128 + r) * EMB + h * HDIM + c * 8;
            cpa16(kvb + r * KB_ROW + c * 16, s);
        }
#pragma unroll
        for (int i = 0; i < 8; i++) {           // V (transposed): 128 d-rows x 128 s
            int e = tid + i * 256;
            int r = (e >> 4) & 127;
            int c = e & 15;
            const __half* s = vth + (size_t)(h * HDIM + r) * S_LEN + kb * 128 + c * 8;
            cpa16(kvb + SM_KPL + r * VB_ROW + c * 16, s);
        }
    };

    const int nkb = qbi + 1;
    load_kv(0, 0);
    CPA_COMMIT();

    float acco[16][4];
#pragma unroll
    for (int j = 0; j < 16; j++)
#pragma unroll
        for (int t = 0; t < 4; t++) acco[j][t] = 0.f;
    float m0 = -1e30f, m8 = -1e30f, l0 = 0.f, lsum8 = 0.f;

    const int row0 = qbi * 128 + w * 16 + g;
    const int row8 = row0 + 8;

    for (int kb = 0; kb < nkb; kb++) {
        if (kb + 1 < nkb) load_kv((kb + 1) & 1, kb + 1);
        CPA_COMMIT();
        CPA_WAIT1();
        __syncthreads();

        const uint32_t kvb = sQ + SM_Q + (kb & 1) * SM_KV;

        // ---- S = Q K^T : 16 x 128 tile ----
        float accs[16][4];
#pragma unroll
        for (int j = 0; j < 16; j++)
#pragma unroll
            for (int t = 0; t < 4; t++) accs[j][t] = 0.f;

#pragma unroll
        for (int ks = 0; ks < 8; ks++) {
            uint32_t a[4];
            ldsm4(sQ + offAq + ks * 32, a[0], a[1], a[2], a[3]);
#pragma unroll
            for (int j = 0; j < 8; j++) {
                uint32_t b0, b1, b2, b3;
                ldsm4(kvb + offBk[j] + ks * 32, b0, b1, b2, b3);
                mma_f16(accs[j * 2 + 0], a, b0, b1);
                mma_f16(accs[j * 2 + 1], a, b2, b3);
            }
        }

        // causal mask: only the diagonal k-block needs it (block width == q tile)
        if (kb == qbi) {
#pragma unroll
            for (int jt = 0; jt < 16; jt++) {
                int col = kb * 128 + jt * 8 + 2 * qd;
                if (col     > row0) accs[jt][0] = -1e30f;
                if (col + 1 > row0) accs[jt][1] = -1e30f;
                if (col     > row8) accs[jt][2] = -1e30f;
                if (col + 1 > row8) accs[jt][3] = -1e30f;
            }
        }

        // ---- online softmax ----
        float mx0 = -1e30f, mx8 = -1e30f;
#pragma unroll
        for (int jt = 0; jt < 16; jt++) {
            mx0 = fmaxf(mx0, fmaxf(accs[jt][0], accs[jt][1]));
            mx8 = fmaxf(mx8, fmaxf(accs[jt][2], accs[jt][3]));
        }
        mx0 = fmaxf(mx0, __shfl_xor_sync(0xffffffffu, mx0, 1));
        mx0 = fmaxf(mx0, __shfl_xor_sync(0xffffffffu, mx0, 2));
        mx8 = fmaxf(mx8, __shfl_xor_sync(0xffffffffu, mx8, 1));
        mx8 = fmaxf(mx8, __shfl_xor_sync(0xffffffffu, mx8, 2));

        float nm0 = fmaxf(m0, mx0), nm8 = fmaxf(m8, mx8);
        float al0 = __expf(m0 - nm0), al8 = __expf(m8 - nm8);
        m0 = nm0; m8 = nm8;

        float s0 = 0.f, s8 = 0.f;
#pragma unroll
        for (int jt = 0; jt < 16; jt++) {
            accs[jt][0] = __expf(accs[jt][0] - nm0);
            accs[jt][1] = __expf(accs[jt][1] - nm0);
            accs[jt][2] = __expf(accs[jt][2] - nm8);
            accs[jt][3] = __expf(accs[jt][3] - nm8);
            s0 += accs[jt][0] + accs[jt][1];
            s8 += accs[jt][2] + accs[jt][3];
        }
        s0 += __shfl_xor_sync(0xffffffffu, s0, 1);
        s0 += __shfl_xor_sync(0xffffffffu, s0, 2);
        s8 += __shfl_xor_sync(0xffffffffu, s8, 1);
        s8 += __shfl_xor_sync(0xffffffffu, s8, 2);
        l0 = l0 * al0 + s0;
        lsum8 = lsum8 * al8 + s8;

#pragma unroll
        for (int j = 0; j < 16; j++) {
            acco[j][0] *= al0; acco[j][1] *= al0;
            acco[j][2] *= al8; acco[j][3] *= al8;
        }

        // ---- P -> fp16 fragments (16 k-steps of 16) ----
        uint32_t pf[16][2];
#pragma unroll
        for (int jt = 0; jt < 16; jt++) {
            pf[jt][0] = h2u(__floats2half2_rn(accs[jt][0], accs[jt][1]));
            pf[jt][1] = h2u(__floats2half2_rn(accs[jt][2], accs[jt][3]));
        }

        // ---- O += P V : K = 128 (8 k-steps) ----
        const uint32_t vbase = kvb + SM_KPL;
#pragma unroll
        for (int t = 0; t < 8; t++) {
            uint32_t a[4];
            a[0] = pf[2 * t][0]; a[1] = pf[2 * t][1];
            a[2] = pf[2 * t + 1][0]; a[3] = pf[2 * t + 1][1];
#pragma unroll
            for (int jn = 0; jn < 8; jn++) {
                uint32_t b0, b1, b2, b3;
                ldsm4(vbase + offBv[jn] + t * 32, b0, b1, b2, b3);
                mma_f16(acco[jn * 2 + 0], a, b0, b1);
                mma_f16(acco[jn * 2 + 1], a, b2, b3);
            }
        }
        __syncthreads();
    }

    // ---- epilogue: write packed fp16 directly (layout consumed by Wo GEMM)
    float inv0 = 1.f / l0, inv8 = 1.f / lsum8;
    const int blk  = qbi;
    const int rin0 = w * 16 + g;
    const int rin8 = rin0 + 8;
#pragma unroll
    for (int jt = 0; jt < 16; jt++) {
        int ks = h * 2 + (jt >> 3);
        int c8 = jt & 7;
        size_t chunk0 = ((size_t)(blk * 32 + ks) * 128 + rin0) * 8 + (c8 ^ (rin0 & 7));
        size_t chunk8 = ((size_t)(blk * 32 + ks) * 128 + rin8) * 8 + (c8 ^ (rin8 & 7));
        __half2 v0 = __floats2half2_rn(acco[jt][0] * inv0, acco[jt][1] * inv0);
        __half2 v8 = __floats2half2_rn(acco[jt][2] * inv8, acco[jt][3] * inv8);
        *reinterpret_cast<__half2*>(pao + chunk0 * 8 + qd * 2) = v0;
        *reinterpret_cast<__half2*>(pao + chunk8 * 8 + qd * 2) = v8;
    }
}

// ---------------- launch ----------------
extern "C" void kernel_launch(void* const* d_in, const int* in_sizes, int n_in,
                              void* d_out, int out_size)
{
    const float* x  = (const float*)d_in[0];
    const float* rc = (const float*)d_in[1];
    const float* rs = (const float*)d_in[2];
    const float* Wq = (const float*)d_in[3];
    const float* Wk = (const float*)d_in[4];
    const float* Wv = (const float*)d_in[5];
    const float* Wo = (const float*)d_in[6];
    float* out = (float*)d_out;

    __half *px, *pao, *pwq, *pwk, *pwv, *pwo;
    cudaGetSymbolAddress((void**)&px,  g_px);
    cudaGetSymbolAddress((void**)&pao, g_pao);
    cudaGetSymbolAddress((void**)&pwq, g_pwq);
    cudaGetSymbolAddress((void**)&pwk, g_pwk);
    cudaGetSymbolAddress((void**)&pwv, g_pwv);
    cudaGetSymbolAddress((void**)&pwo, g_pwo);

    __half *qh, *kh, *vth;
    cudaGetSymbolAddress((void**)&qh,  g_qh);
    cudaGetSymbolAddress((void**)&kh,  g_kh);
    cudaGetSymbolAddress((void**)&vth, g_vth);

    cudaFuncSetAttribute(gemm_bulk,
                         cudaFuncAttributeMaxDynamicSharedMemorySize, GB_SMEM);
    cudaFuncSetAttribute(gemm_qkv_fused,
                         cudaFuncAttributeMaxDynamicSharedMemorySize, GB_SMEM);
    cudaFuncSetAttribute(flash_mma,
                         cudaFuncAttributeMaxDynamicSharedMemorySize, FA_SMEM);

    // repack inputs
    conv_pack<<<S_LEN, 256>>>(x, px, 128);
    conv_pack_w4<<<dim3(EMB, 4), 256>>>(Wq, Wk, Wv, Wo, pwq, pwk, pwv, pwo);

    // fused QKV projection + RoPE/transpose epilogue
    dim3 gq(EMB / 256, S_LEN / 128, 3);
    gemm_qkv_fused<<<gq, 256, GB_SMEM>>>(px, pwq, pwk, pwv, rc, rs,
                                         qh, kh, vth);

    // flash attention -> packed fp16 pao
    flash_mma<<<dim3(S_LEN / 128, NHEAD), 256, FA_SMEM>>>(qh, kh, vth, pao);

    // output projection
    dim3 gg(EMB / 256, S_LEN / 128);
    gemm_bulk<<<gg, 256, GB_SMEM>>>(pao, pwo, out);
}

// round 13
// speedup vs baseline: 1.5846x; 1.0083x over previous
#include <cuda_runtime.h>
#include <cuda_bf16.h>
#include <cuda_fp16.h>
#include <math.h>
#include <stdint.h>

#define S_LEN 2048
#define EMB   2048
#define NHEAD 16
#define HDIM  128

// ---------------- scratch (no cudaMalloc allowed) ----------------
// packed fp16 GEMM operands (stage-contiguous, swizzled)
__device__ __align__(256) __half g_px [S_LEN * EMB];
__device__ __align__(256) __half g_pao[S_LEN * EMB];
__device__ __align__(256) __half g_pwq[EMB * EMB];
__device__ __align__(256) __half g_pwk[EMB * EMB];
__device__ __align__(256) __half g_pwv[EMB * EMB];
__device__ __align__(256) __half g_pwo[EMB * EMB];

// attention operands (fp16, single precision level)
__device__ __half g_qh [S_LEN * EMB];   // q (scaled by log2e/sqrt(d))
__device__ __half g_kh [S_LEN * EMB];
__device__ __half g_vth[NHEAD * HDIM * S_LEN];   // [h][d][s]

// ================= helpers (baseline PTX only) ==============
__device__ __forceinline__ uint32_t s2u(const void* p) {
    uint32_t a;
    asm("{ .reg .u64 t; cvta.to.shared.u64 t, %1; cvt.u32.u64 %0, t; }"
        : "=r"(a) : "l"(p));
    return a;
}

__device__ __forceinline__ void cpa16(uint32_t dst, const void* src) {
    asm volatile("cp.async.cg.shared.global [%0], [%1], 16;" :: "r"(dst), "l"(src));
}
#define CPA_COMMIT() asm volatile("cp.async.commit_group;" ::: "memory")
#define CPA_WAIT1()  asm volatile("cp.async.wait_group 1;" ::: "memory")

__device__ __forceinline__ void ldsm4(uint32_t addr, uint32_t& r0, uint32_t& r1,
                                      uint32_t& r2, uint32_t& r3) {
    asm volatile("ldmatrix.sync.aligned.m8n8.x4.shared.b16 {%0,%1,%2,%3}, [%4];"
                 : "=r"(r0), "=r"(r1), "=r"(r2), "=r"(r3) : "r"(addr));
}

__device__ __forceinline__ void mma_f16(float* d, const uint32_t* a,
                                        uint32_t b0, uint32_t b1) {
    asm volatile(
        "mma.sync.aligned.m16n8k16.row.col.f32.f16.f16.f32 "
        "{%0,%1,%2,%3}, {%4,%5,%6,%7}, {%8,%9}, {%0,%1,%2,%3};"
        : "+f"(d[0]), "+f"(d[1]), "+f"(d[2]), "+f"(d[3])
        : "r"(a[0]), "r"(a[1]), "r"(a[2]), "r"(a[3]), "r"(b0), "r"(b1));
}

__device__ __forceinline__ uint32_t h2u(__half2 v) {
    return *reinterpret_cast<uint32_t*>(&v);
}

// ---- mbarrier / bulk-copy (sm_90 baseline PTX) ----
#define MBAR_INIT(mbar, cnt) \
    asm volatile("mbarrier.init.shared.b64 [%0], %1;" \
                 :: "r"((uint32_t)(mbar)), "r"((uint32_t)(cnt)) : "memory")
#define MBAR_EXPECT_TX(mbar, bytes) \
    asm volatile("mbarrier.arrive.expect_tx.shared.b64 _, [%0], %1;" \
                 :: "r"((uint32_t)(mbar)), "r"((uint32_t)(bytes)) : "memory")
#define MBAR_ARRIVE(mbar) \
    asm volatile("mbarrier.arrive.shared.b64 _, [%0];" \
                 :: "r"((uint32_t)(mbar)) : "memory")

__device__ __forceinline__ void mbar_wait(uint32_t mbar, uint32_t phase) {
    asm volatile(
        "{\n\t.reg .pred P1;\n\t"
        "WAIT_LOOP_%=:\n\t"
        "mbarrier.try_wait.parity.acquire.cta.shared::cta.b64 P1, [%0], %1, 0x989680;\n\t"
        "@P1 bra.uni WAIT_DONE_%=;\n\t"
        "bra.uni WAIT_LOOP_%=;\n\t"
        "WAIT_DONE_%=:\n\t}"
        :: "r"(mbar), "r"(phase) : "memory");
}

__device__ __forceinline__ void bulkcp(uint32_t dst, const void* src,
                                       uint32_t bytes, uint32_t mbar) {
    asm volatile(
        "cp.async.bulk.shared::cluster.global.mbarrier::complete_tx::bytes "
        "[%0], [%1], %2, [%3];"
        :: "r"(dst), "l"(src), "r"(bytes), "r"(mbar) : "memory");
}

// ================= repack fp32 -> fp16, stage-contiguous + XOR swizzle ====
__device__ __forceinline__ void pack_row(
    const float* __restrict__ src, __half* __restrict__ dst,
    int r, int t, int blkrows)
{
    const int ks  = t >> 3;
    const int cs  = t & 7;
    const int rin = r & (blkrows - 1);
    const int blk = r / blkrows;
    const int c   = cs ^ (rin & 7);

    const float* s = src + (size_t)r * EMB + ks * 64 + c * 8;
    float4 v0 = *(const float4*)(s);
    float4 v1 = *(const float4*)(s + 4);

    __half2 h0 = __floats2half2_rn(v0.x, v0.y);
    __half2 h1 = __floats2half2_rn(v0.z, v0.w);
    __half2 h2 = __floats2half2_rn(v1.x, v1.y);
    __half2 h3 = __floats2half2_rn(v1.z, v1.w);

    size_t chunk = ((size_t)(blk * 32 + ks) * blkrows + rin) * 8 + cs;
    uint4 out;
    out.x = h2u(h0); out.y = h2u(h1); out.z = h2u(h2); out.w = h2u(h3);
    *(reinterpret_cast<uint4*>(dst) + chunk) = out;
}

__global__ __launch_bounds__(256) void conv_pack(
    const float* __restrict__ src, __half* __restrict__ dst, int blkrows)
{
    pack_row(src, dst, blockIdx.x, threadIdx.x, blkrows);
}

__global__ __launch_bounds__(256) void conv_pack_w4(
    const float* __restrict__ w0, const float* __restrict__ w1,
    const float* __restrict__ w2, const float* __restrict__ w3,
    __half* __restrict__ d0, __half* __restrict__ d1,
    __half* __restrict__ d2, __half* __restrict__ d3)
{
    const float* s;
    __half* d;
    switch (blockIdx.y) {
        case 0: s = w0; d = d0; break;
        case 1: s = w1; d = d1; break;
        case 2: s = w2; d = d2; break;
        default: s = w3; d = d3; break;
    }
    pack_row(s, d, blockIdx.x, threadIdx.x, 256);
}

// ================= TMA-bulk fp16 GEMM mainloop (round-7 proven config) ====
// CTA tile 128x256, 8 warps (2x4), warp tile 64x64. K staged 64; 3-slot ring.
#define GB_A_BYTES 16384
#define GB_B_BYTES 32768
#define GB_STAGE   49152
#define GB_SMEM    (3 * GB_STAGE + 128)

__device__ __forceinline__ void gemm_main(
    const __half* __restrict__ Ap, const __half* __restrict__ Bp,
    int bx, int by, float acc[4][8][4])
{
    extern __shared__ char smraw[];
    const uint32_t sbase = s2u(smraw);
    const uint32_t mb    = sbase + 3 * GB_STAGE;

    const int tid  = threadIdx.x;
    const int lane = tid & 31;
    const int wid  = tid >> 5;
    const int wm   = wid & 1;
    const int wn   = wid >> 1;

    const int l8 = lane & 7;
    const int mt = lane >> 3;

    int rA[4], rB[4];
#pragma unroll
    for (int i = 0; i < 4; i++)
        rA[i] = wm * 64 + i * 16 + (mt & 1) * 8 + l8;
#pragma unroll
    for (int j = 0; j < 4; j++)
        rB[j] = wn * 64 + j * 16 + (mt >> 1) * 8 + l8;
    const int hcA = mt >> 1;
    const int hcB = mt & 1;

#pragma unroll
    for (int i = 0; i < 4; i++)
#pragma unroll
        for (int j = 0; j < 8; j++)
#pragma unroll
            for (int t = 0; t < 4; t++) acc[i][j][t] = 0.f;

    if (tid == 0) {
#pragma unroll
        for (int i = 0; i < 3; i++) {
            MBAR_INIT(mb + i * 16, 1);
            MBAR_INIT(mb + i * 16 + 8, 8);
        }
    }
    __syncthreads();

    const __half* Asrc = Ap + (size_t)by * 32 * 128 * 64;
    const __half* Bsrc = Bp + (size_t)bx * 32 * 256 * 64;

    if (tid == 0) {
#pragma unroll
        for (int i = 0; i < 3; i++) {
            MBAR_EXPECT_TX(mb + i * 16, GB_STAGE);
            bulkcp(sbase + i * GB_STAGE, Asrc + (size_t)i * 128 * 64,
                   GB_A_BYTES, mb + i * 16);
            bulkcp(sbase + i * GB_STAGE + GB_A_BYTES, Bsrc + (size_t)i * 256 * 64,
                   GB_B_BYTES, mb + i * 16);
        }
    }

    const int NST = EMB / 64;
    for (int s = 0; s < NST; s++) {
        const int sl = s - (s / 3) * 3;
        const uint32_t ph = (uint32_t)((s / 3) & 1);
        const uint32_t slot = sbase + sl * GB_STAGE;

        mbar_wait(mb + sl * 16, ph);

#pragma unroll
        for (int ks = 0; ks < 4; ks++) {
            uint32_t a[4][4];
#pragma unroll
            for (int i = 0; i < 4; i++) {
                uint32_t ch = (uint32_t)((2 * ks + hcA) ^ (rA[i] & 7));
                ldsm4(slot + rA[i] * 128 + ch * 16,
                      a[i][0], a[i][1], a[i][2], a[i][3]);
            }
            uint32_t b[4][4];
#pragma unroll
            for (int j = 0; j < 4; j++) {
                uint32_t ch = (uint32_t)((2 * ks + hcB) ^ (rB[j] & 7));
                ldsm4(slot + GB_A_BYTES + rB[j] * 128 + ch * 16,
                      b[j][0], b[j][1], b[j][2], b[j][3]);
            }
#pragma unroll
            for (int i = 0; i < 4; i++)
#pragma unroll
                for (int j = 0; j < 4; j++) {
                    mma_f16(acc[i][j * 2 + 0], a[i], b[j][0], b[j][1]);
                    mma_f16(acc[i][j * 2 + 1], a[i], b[j][2], b[j][3]);
                }
        }

        if (lane == 0) MBAR_ARRIVE(mb + sl * 16 + 8);

        if (tid == 0 && s + 3 < NST) {
            mbar_wait(mb + sl * 16 + 8, ph);
            MBAR_EXPECT_TX(mb + sl * 16, GB_STAGE);
            bulkcp(slot, Asrc + (size_t)(s + 3) * 128 * 64,
                   GB_A_BYTES, mb + sl * 16);
            bulkcp(slot + GB_A_BYTES, Bsrc + (size_t)(s + 3) * 256 * 64,
                   GB_B_BYTES, mb + sl * 16);
        }
    }
}

// ---- Wo GEMM: plain fp32 epilogue ----
__global__ __launch_bounds__(256, 1) void gemm_bulk(
    const __half* __restrict__ Ap, const __half* __restrict__ Bp,
    float* __restrict__ C)
{
    float acc[4][8][4];
    gemm_main(Ap, Bp, blockIdx.x, blockIdx.y, acc);

    const int tid  = threadIdx.x;
    const int lane = tid & 31;
    const int wid  = tid >> 5;
    const int wm   = wid & 1;
    const int wn   = wid >> 1;
    const int bm   = blockIdx.y * 128;
    const int bn   = blockIdx.x * 256;
    const int g = lane >> 2;
    const int q = (lane & 3) * 2;
#pragma unroll
    for (int i = 0; i < 4; i++) {
#pragma unroll
        for (int j = 0; j < 8; j++) {
            int row = bm + wm * 64 + i * 16 + g;
            int col = bn + wn * 64 + j * 8 + q;
            *(float2*)(C + (size_t)row * EMB + col) =
                make_float2(acc[i][j][0], acc[i][j][1]);
            *(float2*)(C + (size_t)(row + 8) * EMB + col) =
                make_float2(acc[i][j][2], acc[i][j][3]);
        }
    }
}

// ---- fused QKV GEMM: epilogue RoPE (Q scaled incl. log2e, K), transpose (V)
#define EP_STRIDE 265   // floats; %32 == 9 -> conflict-free column reads

__global__ __launch_bounds__(256, 1) void gemm_qkv_fused(
    const __half* __restrict__ Ap,
    const __half* __restrict__ Bq, const __half* __restrict__ Bk,
    const __half* __restrict__ Bv,
    const float* __restrict__ cosb, const float* __restrict__ sinb,
    __half* __restrict__ qh, __half* __restrict__ kh,
    __half* __restrict__ vth)
{
    const int z = blockIdx.z;
    const __half* Bp = (z == 0) ? Bq : (z == 1) ? Bk : Bv;

    float acc[4][8][4];
    gemm_main(Ap, Bp, blockIdx.x, blockIdx.y, acc);

    extern __shared__ char smraw[];
    float* smf = reinterpret_cast<float*>(smraw);

    const int tid  = threadIdx.x;
    const int lane = tid & 31;
    const int wid  = tid >> 5;
    const int wm   = wid & 1;
    const int wn   = wid >> 1;
    const int bm   = blockIdx.y * 128;
    const int bn   = blockIdx.x * 256;
    const int g = lane >> 2;
    const int q = (lane & 3) * 2;

    __syncthreads();   // all warps out of mainloop before overwriting smem

#pragma unroll
    for (int i = 0; i < 4; i++) {
#pragma unroll
        for (int j = 0; j < 8; j++) {
            int row = wm * 64 + i * 16 + g;
            int col = wn * 64 + j * 8 + q;
            smf[row * EP_STRIDE + col]           = acc[i][j][0];
            smf[row * EP_STRIDE + col + 1]       = acc[i][j][1];
            smf[(row + 8) * EP_STRIDE + col]     = acc[i][j][2];
            smf[(row + 8) * EP_STRIDE + col + 1] = acc[i][j][3];
        }
    }
    __syncthreads();

    if (z < 2) {
        // RoPE -> single fp16. Q scale absorbs 1/sqrt(d) * log2(e).
        __half* dst = (z == 0) ? qh : kh;
        const float sc = (z == 0) ? 0.12751744f : 1.f;   // 0.08838835 * 1.4426950
        const int c  = tid;
        const int hd = c & 127;
        const bool low = hd < 64;
#pragma unroll 4
        for (int s = 0; s < 128; s++) {
            float a = smf[s * EP_STRIDE + c];
            float b = smf[s * EP_STRIDE + (c ^ 64)];
            int srow = bm + s;
            float cv = cosb[srow * HDIM + hd];
            float sv = sinb[srow * HDIM + hd];
            float out = (low ? (a * cv - b * sv) : (a * cv + b * sv)) * sc;
            dst[(size_t)srow * EMB + bn + c] = __float2half_rn(out);
        }
    } else {
        // V: transpose -> single fp16
        const int c0 = wid * 32;
#pragma unroll 2
        for (int cc = 0; cc < 32; cc++) {
            int col  = c0 + cc;
            int hloc = col >> 7;
            int d    = col & 127;
            size_t rowbase = ((size_t)((blockIdx.x * 2 + hloc) * HDIM + d)) * S_LEN + bm;
#pragma unroll
            for (int s4 = 0; s4 < 4; s4++) {
                int s = s4 * 32 + lane;
                vth[rowbase + s] = __float2half_rn(smf[s * EP_STRIDE + col]);
            }
        }
    }
}

// ---------------- Flash attention (mma.sync, fp16, K-block = 128) ---------
// Scores arrive pre-scaled by log2(e); softmax uses exp2 throughout.
#define QB_ROW  272
#define KB_ROW  272
#define VB_ROW  272
#define SM_Q    (128 * QB_ROW)          // 34816
#define SM_KPL  (128 * KB_ROW)          // 34816 (128 k-rows)
#define SM_VPL  (128 * VB_ROW)          // 34816 (128 d-rows x 128 s-cols)
#define SM_KV   (SM_KPL + SM_VPL)       // 69632 per buffer
#define FA_SMEM (SM_Q + 2 * SM_KV)      // 174080

__global__ __launch_bounds__(256, 1) void flash_mma(
    const __half* __restrict__ qh, const __half* __restrict__ kh,
    const __half* __restrict__ vth,
    __half* __restrict__ pao)
{
    extern __shared__ char smraw[];
    const uint32_t sQ = s2u(smraw);

    const int tid  = threadIdx.x;
    const int lane = tid & 31;
    const int w    = tid >> 5;
    const int g    = lane >> 2;
    const int qd   = lane & 3;
    const int l8   = lane & 7;
    const int mt   = lane >> 3;
    const int qbi  = gridDim.x - 1 - blockIdx.x;   // heaviest CTAs first
    const int h    = blockIdx.y;

    const uint32_t offAq = (uint32_t)((w * 16 + (mt & 1) * 8 + l8) * QB_ROW + (mt >> 1) * 16);
    uint32_t offBk[8], offBv[8];
#pragma unroll
    for (int j = 0; j < 8; j++)
        offBk[j] = (uint32_t)((j * 16 + (mt >> 1) * 8 + l8) * KB_ROW + (mt & 1) * 16);
#pragma unroll
    for (int j = 0; j < 8; j++)
        offBv[j] = (uint32_t)((j * 16 + (mt >> 1) * 8 + l8) * VB_ROW + (mt & 1) * 16);

    // ---- load Q (single plane, 128 rows x 128 halves) ----
#pragma unroll
    for (int i = 0; i < 8; i++) {
        int e = tid + i * 256;
        int r = (e >> 4) & 127;
        int c = e & 15;
        const __half* s = qh + (size_t)(qbi * 128 + r) * EMB + h * HDIM + c * 8;
        cpa16(sQ + r * QB_ROW + c * 16, s);
    }

    auto load_kv = [&](int buf, int kb) {
        uint32_t kvb = sQ + SM_Q + buf * SM_KV;
#pragma unroll
        for (int i = 0; i < 8; i++) {           // K: 128 rows x 128 halves
            int e = tid + i * 256;
            int r = (e >> 4) & 127;
            int c = e & 15;
            const __half* s = kh + (size_t)(kb * 128 + r) * EMB + h * HDIM + c * 8;
            cpa16(kvb + r * KB_ROW + c * 16, s);
        }
#pragma unroll
        for (int i = 0; i < 8; i++) {           // V (transposed): 128 d-rows x 128 s
            int e = tid + i * 256;
            int r = (e >> 4) & 127;
            int c = e & 15;
            const __half* s = vth + (size_t)(h * HDIM + r) * S_LEN + kb * 128 + c * 8;
            cpa16(kvb + SM_KPL + r * VB_ROW + c * 16, s);
        }
    };

    const int nkb = qbi + 1;
    load_kv(0, 0);
    CPA_COMMIT();

    float acco[16][4];
#pragma unroll
    for (int j = 0; j < 16; j++)
#pragma unroll
        for (int t = 0; t < 4; t++) acco[j][t] = 0.f;
    float m0 = -1e30f, m8 = -1e30f, l0 = 0.f, lsum8 = 0.f;

    const int row0 = qbi * 128 + w * 16 + g;
    const int row8 = row0 + 8;

    for (int kb = 0; kb < nkb; kb++) {
        if (kb + 1 < nkb) load_kv((kb + 1) & 1, kb + 1);
        CPA_COMMIT();
        CPA_WAIT1();
        __syncthreads();

        const uint32_t kvb = sQ + SM_Q + (kb & 1) * SM_KV;

        // ---- S = Q K^T : 16 x 128 tile (scores already in log2 domain) ----
        float accs[16][4];
#pragma unroll
        for (int j = 0; j < 16; j++)
#pragma unroll
            for (int t = 0; t < 4; t++) accs[j][t] = 0.f;

#pragma unroll
        for (int ks = 0; ks < 8; ks++) {
            uint32_t a[4];
            ldsm4(sQ + offAq + ks * 32, a[0], a[1], a[2], a[3]);
#pragma unroll
            for (int j = 0; j < 8; j++) {
                uint32_t b0, b1, b2, b3;
                ldsm4(kvb + offBk[j] + ks * 32, b0, b1, b2, b3);
                mma_f16(accs[j * 2 + 0], a, b0, b1);
                mma_f16(accs[j * 2 + 1], a, b2, b3);
            }
        }

        // causal mask: only the diagonal k-block needs it
        if (kb == qbi) {
#pragma unroll
            for (int jt = 0; jt < 16; jt++) {
                int col = kb * 128 + jt * 8 + 2 * qd;
                if (col     > row0) accs[jt][0] = -1e30f;
                if (col + 1 > row0) accs[jt][1] = -1e30f;
                if (col     > row8) accs[jt][2] = -1e30f;
                if (col + 1 > row8) accs[jt][3] = -1e30f;
            }
        }

        // ---- online softmax (base-2) ----
        float mx0 = -1e30f, mx8 = -1e30f;
#pragma unroll
        for (int jt = 0; jt < 16; jt++) {
            mx0 = fmaxf(mx0, fmaxf(accs[jt][0], accs[jt][1]));
            mx8 = fmaxf(mx8, fmaxf(accs[jt][2], accs[jt][3]));
        }
        mx0 = fmaxf(mx0, __shfl_xor_sync(0xffffffffu, mx0, 1));
        mx0 = fmaxf(mx0, __shfl_xor_sync(0xffffffffu, mx0, 2));
        mx8 = fmaxf(mx8, __shfl_xor_sync(0xffffffffu, mx8, 1));
        mx8 = fmaxf(mx8, __shfl_xor_sync(0xffffffffu, mx8, 2));

        float nm0 = fmaxf(m0, mx0), nm8 = fmaxf(m8, mx8);
        bool nochg = (nm0 == m0) && (nm8 == m8);
        bool allno = __all_sync(0xffffffffu, nochg);
        float al0 = 1.f, al8 = 1.f;
        if (!allno) {
            al0 = exp2f(m0 - nm0);
            al8 = exp2f(m8 - nm8);
#pragma unroll
            for (int j = 0; j < 16; j++) {
                acco[j][0] *= al0; acco[j][1] *= al0;
                acco[j][2] *= al8; acco[j][3] *= al8;
            }
        }
        m0 = nm0; m8 = nm8;

        float s0 = 0.f, s8 = 0.f;
#pragma unroll
        for (int jt = 0; jt < 16; jt++) {
            accs[jt][0] = exp2f(accs[jt][0] - nm0);
            accs[jt][1] = exp2f(accs[jt][1] - nm0);
            accs[jt][2] = exp2f(accs[jt][2] - nm8);
            accs[jt][3] = exp2f(accs[jt][3] - nm8);
            s0 += accs[jt][0] + accs[jt][1];
            s8 += accs[jt][2] + accs[jt][3];
        }
        s0 += __shfl_xor_sync(0xffffffffu, s0, 1);
        s0 += __shfl_xor_sync(0xffffffffu, s0, 2);
        s8 += __shfl_xor_sync(0xffffffffu, s8, 1);
        s8 += __shfl_xor_sync(0xffffffffu, s8, 2);
        l0 = l0 * al0 + s0;
        lsum8 = lsum8 * al8 + s8;

        // ---- P -> fp16 fragments (16 k-steps of 16) ----
        uint32_t pf[16][2];
#pragma unroll
        for (int jt = 0; jt < 16; jt++) {
            pf[jt][0] = h2u(__floats2half2_rn(accs[jt][0], accs[jt][1]));
            pf[jt][1] = h2u(__floats2half2_rn(accs[jt][2], accs[jt][3]));
        }

        // ---- O += P V : K = 128 (8 k-steps) ----
        const uint32_t vbase = kvb + SM_KPL;
#pragma unroll
        for (int t = 0; t < 8; t++) {
            uint32_t a[4];
            a[0] = pf[2 * t][0]; a[1] = pf[2 * t][1];
            a[2] = pf[2 * t + 1][0]; a[3] = pf[2 * t + 1][1];
#pragma unroll
            for (int jn = 0; jn < 8; jn++) {
                uint32_t b0, b1, b2, b3;
                ldsm4(vbase + offBv[jn] + t * 32, b0, b1, b2, b3);
                mma_f16(acco[jn * 2 + 0], a, b0, b1);
                mma_f16(acco[jn * 2 + 1], a, b2, b3);
            }
        }
        __syncthreads();
    }

    // ---- epilogue: write packed fp16 directly (layout consumed by Wo GEMM)
    float inv0 = 1.f / l0, inv8 = 1.f / lsum8;
    const int blk  = qbi;
    const int rin0 = w * 16 + g;
    const int rin8 = rin0 + 8;
#pragma unroll
    for (int jt = 0; jt < 16; jt++) {
        int ks = h * 2 + (jt >> 3);
        int c8 = jt & 7;
        size_t chunk0 = ((size_t)(blk * 32 + ks) * 128 + rin0) * 8 + (c8 ^ (rin0 & 7));
        size_t chunk8 = ((size_t)(blk * 32 + ks) * 128 + rin8) * 8 + (c8 ^ (rin8 & 7));
        __half2 v0 = __floats2half2_rn(acco[jt][0] * inv0, acco[jt][1] * inv0);
        __half2 v8 = __floats2half2_rn(acco[jt][2] * inv8, acco[jt][3] * inv8);
        *reinterpret_cast<__half2*>(pao + chunk0 * 8 + qd * 2) = v0;
        *reinterpret_cast<__half2*>(pao + chunk8 * 8 + qd * 2) = v8;
    }
}

// ---------------- launch ----------------
extern "C" void kernel_launch(void* const* d_in, const int* in_sizes, int n_in,
                              void* d_out, int out_size)
{
    const float* x  = (const float*)d_in[0];
    const float* rc = (const float*)d_in[1];
    const float* rs = (const float*)d_in[2];
    const float* Wq = (const float*)d_in[3];
    const float* Wk = (const float*)d_in[4];
    const float* Wv = (const float*)d_in[5];
    const float* Wo = (const float*)d_in[6];
    float* out = (float*)d_out;

    __half *px, *pao, *pwq, *pwk, *pwv, *pwo;
    cudaGetSymbolAddress((void**)&px,  g_px);
    cudaGetSymbolAddress((void**)&pao, g_pao);
    cudaGetSymbolAddress((void**)&pwq, g_pwq);
    cudaGetSymbolAddress((void**)&pwk, g_pwk);
    cudaGetSymbolAddress((void**)&pwv, g_pwv);
    cudaGetSymbolAddress((void**)&pwo, g_pwo);

    __half *qh, *kh, *vth;
    cudaGetSymbolAddress((void**)&qh,  g_qh);
    cudaGetSymbolAddress((void**)&kh,  g_kh);
    cudaGetSymbolAddress((void**)&vth, g_vth);

    cudaFuncSetAttribute(gemm_bulk,
                         cudaFuncAttributeMaxDynamicSharedMemorySize, GB_SMEM);
    cudaFuncSetAttribute(gemm_qkv_fused,
                         cudaFuncAttributeMaxDynamicSharedMemorySize, GB_SMEM);
    cudaFuncSetAttribute(flash_mma,
                         cudaFuncAttributeMaxDynamicSharedMemorySize, FA_SMEM);

    // repack inputs
    conv_pack<<<S_LEN, 256>>>(x, px, 128);
    conv_pack_w4<<<dim3(EMB, 4), 256>>>(Wq, Wk, Wv, Wo, pwq, pwk, pwv, pwo);

    // fused QKV projection + RoPE/transpose epilogue
    dim3 gq(EMB / 256, S_LEN / 128, 3);
    gemm_qkv_fused<<<gq, 256, GB_SMEM>>>(px, pwq, pwk, pwv, rc, rs,
                                         qh, kh, vth);

    // flash attention -> packed fp16 pao
    flash_mma<<<dim3(S_LEN / 128, NHEAD), 256, FA_SMEM>>>(qh, kh, vth, pao);

    // output projection
    dim3 gg(EMB / 256, S_LEN / 128);
    gemm_bulk<<<gg, 256, GB_SMEM>>>(pao, pwo, out);
}

// round 14
// speedup vs baseline: 1.6717x; 1.0550x over previous
#include <cuda_runtime.h>
#include <cuda_bf16.h>
#include <cuda_fp16.h>
#include <math.h>
#include <stdint.h>

#define S_LEN 2048
#define EMB   2048
#define NHEAD 16
#define HDIM  128

// ---------------- scratch (no cudaMalloc allowed) ----------------
// packed fp16 GEMM operands (stage-contiguous, swizzled, blkrows=128)
__device__ __align__(256) __half g_px [S_LEN * EMB];
__device__ __align__(256) __half g_pao[S_LEN * EMB];
__device__ __align__(256) __half g_pwq[EMB * EMB];
__device__ __align__(256) __half g_pwk[EMB * EMB];
__device__ __align__(256) __half g_pwv[EMB * EMB];
__device__ __align__(256) __half g_pwo[EMB * EMB];

// attention operands (fp16, single precision level)
__device__ __half g_qh [S_LEN * EMB];   // q (scaled by log2e/sqrt(d))
__device__ __half g_kh [S_LEN * EMB];
__device__ __half g_vth[NHEAD * HDIM * S_LEN];   // [h][d][s]

// ================= helpers (baseline PTX only) ==============
__device__ __forceinline__ uint32_t s2u(const void* p) {
    uint32_t a;
    asm("{ .reg .u64 t; cvta.to.shared.u64 t, %1; cvt.u32.u64 %0, t; }"
        : "=r"(a) : "l"(p));
    return a;
}

__device__ __forceinline__ void cpa16(uint32_t dst, const void* src) {
    asm volatile("cp.async.cg.shared.global [%0], [%1], 16;" :: "r"(dst), "l"(src));
}
#define CPA_COMMIT() asm volatile("cp.async.commit_group;" ::: "memory")
#define CPA_WAIT1()  asm volatile("cp.async.wait_group 1;" ::: "memory")

__device__ __forceinline__ void ldsm4(uint32_t addr, uint32_t& r0, uint32_t& r1,
                                      uint32_t& r2, uint32_t& r3) {
    asm volatile("ldmatrix.sync.aligned.m8n8.x4.shared.b16 {%0,%1,%2,%3}, [%4];"
                 : "=r"(r0), "=r"(r1), "=r"(r2), "=r"(r3) : "r"(addr));
}

__device__ __forceinline__ void mma_f16(float* d, const uint32_t* a,
                                        uint32_t b0, uint32_t b1) {
    asm volatile(
        "mma.sync.aligned.m16n8k16.row.col.f32.f16.f16.f32 "
        "{%0,%1,%2,%3}, {%4,%5,%6,%7}, {%8,%9}, {%0,%1,%2,%3};"
        : "+f"(d[0]), "+f"(d[1]), "+f"(d[2]), "+f"(d[3])
        : "r"(a[0]), "r"(a[1]), "r"(a[2]), "r"(a[3]), "r"(b0), "r"(b1));
}

__device__ __forceinline__ uint32_t h2u(__half2 v) {
    return *reinterpret_cast<uint32_t*>(&v);
}

// ---- mbarrier / bulk-copy (sm_90 baseline PTX) ----
#define MBAR_INIT(mbar, cnt) \
    asm volatile("mbarrier.init.shared.b64 [%0], %1;" \
                 :: "r"((uint32_t)(mbar)), "r"((uint32_t)(cnt)) : "memory")
#define MBAR_EXPECT_TX(mbar, bytes) \
    asm volatile("mbarrier.arrive.expect_tx.shared.b64 _, [%0], %1;" \
                 :: "r"((uint32_t)(mbar)), "r"((uint32_t)(bytes)) : "memory")
#define MBAR_ARRIVE(mbar) \
    asm volatile("mbarrier.arrive.shared.b64 _, [%0];" \
                 :: "r"((uint32_t)(mbar)) : "memory")

__device__ __forceinline__ void mbar_wait(uint32_t mbar, uint32_t phase) {
    asm volatile(
        "{\n\t.reg .pred P1;\n\t"
        "WAIT_LOOP_%=:\n\t"
        "mbarrier.try_wait.parity.acquire.cta.shared::cta.b64 P1, [%0], %1, 0x989680;\n\t"
        "@P1 bra.uni WAIT_DONE_%=;\n\t"
        "bra.uni WAIT_LOOP_%=;\n\t"
        "WAIT_DONE_%=:\n\t}"
        :: "r"(mbar), "r"(phase) : "memory");
}

__device__ __forceinline__ void bulkcp(uint32_t dst, const void* src,
                                       uint32_t bytes, uint32_t mbar) {
    asm volatile(
        "cp.async.bulk.shared::cluster.global.mbarrier::complete_tx::bytes "
        "[%0], [%1], %2, [%3];"
        :: "r"(dst), "l"(src), "r"(bytes), "r"(mbar) : "memory");
}

// ================= repack fp32 -> fp16, stage-contiguous + XOR swizzle ====
// blkrows = 128 for ALL operands now (A row-blocks and B col-blocks).
__device__ __forceinline__ void pack_row(
    const float* __restrict__ src, __half* __restrict__ dst, int r, int t)
{
    const int ks  = t >> 3;
    const int cs  = t & 7;
    const int rin = r & 127;
    const int blk = r >> 7;
    const int c   = cs ^ (rin & 7);

    const float* s = src + (size_t)r * EMB + ks * 64 + c * 8;
    float4 v0 = *(const float4*)(s);
    float4 v1 = *(const float4*)(s + 4);

    __half2 h0 = __floats2half2_rn(v0.x, v0.y);
    __half2 h1 = __floats2half2_rn(v0.z, v0.w);
    __half2 h2 = __floats2half2_rn(v1.x, v1.y);
    __half2 h3 = __floats2half2_rn(v1.z, v1.w);

    size_t chunk = ((size_t)(blk * 32 + ks) * 128 + rin) * 8 + cs;
    uint4 out;
    out.x = h2u(h0); out.y = h2u(h1); out.z = h2u(h2); out.w = h2u(h3);
    *(reinterpret_cast<uint4*>(dst) + chunk) = out;
}

__global__ __launch_bounds__(256) void conv_pack(
    const float* __restrict__ src, __half* __restrict__ dst)
{
    pack_row(src, dst, blockIdx.x, threadIdx.x);
}

__global__ __launch_bounds__(256) void conv_pack_w4(
    const float* __restrict__ w0, const float* __restrict__ w1,
    const float* __restrict__ w2, const float* __restrict__ w3,
    __half* __restrict__ d0, __half* __restrict__ d1,
    __half* __restrict__ d2, __half* __restrict__ d3)
{
    const float* s;
    __half* d;
    switch (blockIdx.y) {
        case 0: s = w0; d = d0; break;
        case 1: s = w1; d = d1; break;
        case 2: s = w2; d = d2; break;
        default: s = w3; d = d3; break;
    }
    pack_row(s, d, blockIdx.x, threadIdx.x);
}

// ================= TMA-bulk fp16 GEMM: CTA 128x128, 2 CTAs/SM ============
// 8 warps (2x4), warp tile 64x32. K staged 64; 3-slot ring. smem 96KB.
#define GB_AB_BYTES 16384
#define GB_STAGE    32768
#define GB_SMEM     (3 * GB_STAGE + 128)

__device__ __forceinline__ void gemm_main(
    const __half* __restrict__ Ap, const __half* __restrict__ Bp,
    int bx, int by, float acc[4][4][4])
{
    extern __shared__ char smraw[];
    const uint32_t sbase = s2u(smraw);
    const uint32_t mb    = sbase + 3 * GB_STAGE;

    const int tid  = threadIdx.x;
    const int lane = tid & 31;
    const int wid  = tid >> 5;
    const int wm   = wid & 1;        // 64-row group
    const int wn   = wid >> 1;       // 0..3, 32-col group

    const int l8 = lane & 7;
    const int mt = lane >> 3;

    int rA[4], rB[2];
#pragma unroll
    for (int i = 0; i < 4; i++)
        rA[i] = wm * 64 + i * 16 + (mt & 1) * 8 + l8;
#pragma unroll
    for (int j = 0; j < 2; j++)
        rB[j] = wn * 32 + j * 16 + (mt >> 1) * 8 + l8;
    const int hcA = mt >> 1;
    const int hcB = mt & 1;

#pragma unroll
    for (int i = 0; i < 4; i++)
#pragma unroll
        for (int j = 0; j < 4; j++)
#pragma unroll
            for (int t = 0; t < 4; t++) acc[i][j][t] = 0.f;

    if (tid == 0) {
#pragma unroll
        for (int i = 0; i < 3; i++) {
            MBAR_INIT(mb + i * 16, 1);
            MBAR_INIT(mb + i * 16 + 8, 8);
        }
    }
    __syncthreads();

    const __half* Asrc = Ap + (size_t)by * 32 * 128 * 64;
    const __half* Bsrc = Bp + (size_t)bx * 32 * 128 * 64;

    if (tid == 0) {
#pragma unroll
        for (int i = 0; i < 3; i++) {
            MBAR_EXPECT_TX(mb + i * 16, GB_STAGE);
            bulkcp(sbase + i * GB_STAGE, Asrc + (size_t)i * 128 * 64,
                   GB_AB_BYTES, mb + i * 16);
            bulkcp(sbase + i * GB_STAGE + GB_AB_BYTES, Bsrc + (size_t)i * 128 * 64,
                   GB_AB_BYTES, mb + i * 16);
        }
    }

    const int NST = EMB / 64;
    for (int s = 0; s < NST; s++) {
        const int sl = s - (s / 3) * 3;
        const uint32_t ph = (uint32_t)((s / 3) & 1);
        const uint32_t slot = sbase + sl * GB_STAGE;

        mbar_wait(mb + sl * 16, ph);

#pragma unroll
        for (int ks = 0; ks < 4; ks++) {
            uint32_t a[4][4];
#pragma unroll
            for (int i = 0; i < 4; i++) {
                uint32_t ch = (uint32_t)((2 * ks + hcA) ^ (rA[i] & 7));
                ldsm4(slot + rA[i] * 128 + ch * 16,
                      a[i][0], a[i][1], a[i][2], a[i][3]);
            }
            uint32_t b[2][4];
#pragma unroll
            for (int j = 0; j < 2; j++) {
                uint32_t ch = (uint32_t)((2 * ks + hcB) ^ (rB[j] & 7));
                ldsm4(slot + GB_AB_BYTES + rB[j] * 128 + ch * 16,
                      b[j][0], b[j][1], b[j][2], b[j][3]);
            }
#pragma unroll
            for (int i = 0; i < 4; i++)
#pragma unroll
                for (int j = 0; j < 2; j++) {
                    mma_f16(acc[i][j * 2 + 0], a[i], b[j][0], b[j][1]);
                    mma_f16(acc[i][j * 2 + 1], a[i], b[j][2], b[j][3]);
                }
        }

        if (lane == 0) MBAR_ARRIVE(mb + sl * 16 + 8);

        if (tid == 0 && s + 3 < NST) {
            mbar_wait(mb + sl * 16 + 8, ph);
            MBAR_EXPECT_TX(mb + sl * 16, GB_STAGE);
            bulkcp(slot, Asrc + (size_t)(s + 3) * 128 * 64,
                   GB_AB_BYTES, mb + sl * 16);
            bulkcp(slot + GB_AB_BYTES, Bsrc + (size_t)(s + 3) * 128 * 64,
                   GB_AB_BYTES, mb + sl * 16);
        }
    }
}

// ---- Wo GEMM: plain fp32 epilogue ----
__global__ __launch_bounds__(256, 2) void gemm_bulk(
    const __half* __restrict__ Ap, const __half* __restrict__ Bp,
    float* __restrict__ C)
{
    float acc[4][4][4];
    gemm_main(Ap, Bp, blockIdx.x, blockIdx.y, acc);

    const int tid  = threadIdx.x;
    const int lane = tid & 31;
    const int wid  = tid >> 5;
    const int wm   = wid & 1;
    const int wn   = wid >> 1;
    const int bm   = blockIdx.y * 128;
    const int bn   = blockIdx.x * 128;
    const int g = lane >> 2;
    const int q = (lane & 3) * 2;
#pragma unroll
    for (int i = 0; i < 4; i++) {
#pragma unroll
        for (int j = 0; j < 4; j++) {
            int row = bm + wm * 64 + i * 16 + g;
            int col = bn + wn * 32 + j * 8 + q;
            *(float2*)(C + (size_t)row * EMB + col) =
                make_float2(acc[i][j][0], acc[i][j][1]);
            *(float2*)(C + (size_t)(row + 8) * EMB + col) =
                make_float2(acc[i][j][2], acc[i][j][3]);
        }
    }
}

// ---- fused QKV GEMM: 128x128 tile = one head. RoPE (Q,K) / transpose (V) -
#define EP_STRIDE 129   // odd -> conflict-free column reads; scalar writes

__global__ __launch_bounds__(256, 2) void gemm_qkv_fused(
    const __half* __restrict__ Ap,
    const __half* __restrict__ Bq, const __half* __restrict__ Bk,
    const __half* __restrict__ Bv,
    const float* __restrict__ cosb, const float* __restrict__ sinb,
    __half* __restrict__ qh, __half* __restrict__ kh,
    __half* __restrict__ vth)
{
    const int z = blockIdx.z;
    const __half* Bp = (z == 0) ? Bq : (z == 1) ? Bk : Bv;

    float acc[4][4][4];
    gemm_main(Ap, Bp, blockIdx.x, blockIdx.y, acc);

    extern __shared__ char smraw[];
    float* smf = reinterpret_cast<float*>(smraw);

    const int tid  = threadIdx.x;
    const int lane = tid & 31;
    const int wid  = tid >> 5;
    const int wm   = wid & 1;
    const int wn   = wid >> 1;
    const int bm   = blockIdx.y * 128;
    const int h    = blockIdx.x;      // one head per CTA column block
    const int g = lane >> 2;
    const int q = (lane & 3) * 2;

    __syncthreads();   // all warps out of mainloop before overwriting smem

    // stage acc in smem [128 rows][EP_STRIDE]
#pragma unroll
    for (int i = 0; i < 4; i++) {
#pragma unroll
        for (int j = 0; j < 4; j++) {
            int row = wm * 64 + i * 16 + g;
            int col = wn * 32 + j * 8 + q;
            smf[row * EP_STRIDE + col]           = acc[i][j][0];
            smf[row * EP_STRIDE + col + 1]       = acc[i][j][1];
            smf[(row + 8) * EP_STRIDE + col]     = acc[i][j][2];
            smf[(row + 8) * EP_STRIDE + col + 1] = acc[i][j][3];
        }
    }
    __syncthreads();

    if (z < 2) {
        // RoPE -> single fp16. Q scale absorbs 1/sqrt(d) * log2(e).
        __half* dst = (z == 0) ? qh : kh;
        const float sc = (z == 0) ? 0.12751744f : 1.f;
        const int c    = tid & 127;          // head-dim index
        const int shal = tid >> 7;           // row half (0/1)
        const bool low = c < 64;
#pragma unroll 4
        for (int si = 0; si < 64; si++) {
            int s = shal * 64 + si;
            float a = smf[s * EP_STRIDE + c];
            float b = smf[s * EP_STRIDE + (c ^ 64)];
            int srow = bm + s;
            float cv = cosb[srow * HDIM + c];
            float sv = sinb[srow * HDIM + c];
            float out = (low ? (a * cv - b * sv) : (a * cv + b * sv)) * sc;
            dst[(size_t)srow * EMB + h * HDIM + c] = __float2half_rn(out);
        }
    } else {
        // V: transpose -> single fp16. warp owns 16 cols; lanes iterate s.
        const int c0 = wid * 16;
#pragma unroll 4
        for (int cc = 0; cc < 16; cc++) {
            int d = c0 + cc;
            size_t rowbase = ((size_t)(h * HDIM + d)) * S_LEN + bm;
#pragma unroll
            for (int s4 = 0; s4 < 4; s4++) {
                int s = s4 * 32 + lane;
                vth[rowbase + s] = __float2half_rn(smf[s * EP_STRIDE + d]);
            }
        }
    }
}

// ---------------- Flash attention (mma.sync, fp16, K-block = 128) ---------
#define QB_ROW  272
#define KB_ROW  272
#define VB_ROW  272
#define SM_Q    (128 * QB_ROW)
#define SM_KPL  (128 * KB_ROW)
#define SM_VPL  (128 * VB_ROW)
#define SM_KV   (SM_KPL + SM_VPL)
#define FA_SMEM (SM_Q + 2 * SM_KV)      // 174080

__global__ __launch_bounds__(256, 1) void flash_mma(
    const __half* __restrict__ qh, const __half* __restrict__ kh,
    const __half* __restrict__ vth,
    __half* __restrict__ pao)
{
    extern __shared__ char smraw[];
    const uint32_t sQ = s2u(smraw);

    const int tid  = threadIdx.x;
    const int lane = tid & 31;
    const int w    = tid >> 5;
    const int g    = lane >> 2;
    const int qd   = lane & 3;
    const int l8   = lane & 7;
    const int mt   = lane >> 3;
    const int qbi  = gridDim.x - 1 - blockIdx.x;
    const int h    = blockIdx.y;

    const uint32_t offAq = (uint32_t)((w * 16 + (mt & 1) * 8 + l8) * QB_ROW + (mt >> 1) * 16);
    uint32_t offBk[8], offBv[8];
#pragma unroll
    for (int j = 0; j < 8; j++)
        offBk[j] = (uint32_t)((j * 16 + (mt >> 1) * 8 + l8) * KB_ROW + (mt & 1) * 16);
#pragma unroll
    for (int j = 0; j < 8; j++)
        offBv[j] = (uint32_t)((j * 16 + (mt >> 1) * 8 + l8) * VB_ROW + (mt & 1) * 16);

#pragma unroll
    for (int i = 0; i < 8; i++) {
        int e = tid + i * 256;
        int r = (e >> 4) & 127;
        int c = e & 15;
        const __half* s = qh + (size_t)(qbi * 128 + r) * EMB + h * HDIM + c * 8;
        cpa16(sQ + r * QB_ROW + c * 16, s);
    }

    auto load_kv = [&](int buf, int kb) {
        uint32_t kvb = sQ + SM_Q + buf * SM_KV;
#pragma unroll
        for (int i = 0; i < 8; i++) {
            int e = tid + i * 256;
            int r = (e >> 4) & 127;
            int c = e & 15;
            const __half* s = kh + (size_t)(kb * 128 + r) * EMB + h * HDIM + c * 8;
            cpa16(kvb + r * KB_ROW + c * 16, s);
        }
#pragma unroll
        for (int i = 0; i < 8; i++) {
            int e = tid + i * 256;
            int r = (e >> 4) & 127;
            int c = e & 15;
            const __half* s = vth + (size_t)(h * HDIM + r) * S_LEN + kb * 128 + c * 8;
            cpa16(kvb + SM_KPL + r * VB_ROW + c * 16, s);
        }
    };

    const int nkb = qbi + 1;
    load_kv(0, 0);
    CPA_COMMIT();

    float acco[16][4];
#pragma unroll
    for (int j = 0; j < 16; j++)
#pragma unroll
        for (int t = 0; t < 4; t++) acco[j][t] = 0.f;
    float m0 = -1e30f, m8 = -1e30f, l0 = 0.f, lsum8 = 0.f;

    const int row0 = qbi * 128 + w * 16 + g;
    const int row8 = row0 + 8;

    for (int kb = 0; kb < nkb; kb++) {
        if (kb + 1 < nkb) load_kv((kb + 1) & 1, kb + 1);
        CPA_COMMIT();
        CPA_WAIT1();
        __syncthreads();

        const uint32_t kvb = sQ + SM_Q + (kb & 1) * SM_KV;

        float accs[16][4];
#pragma unroll
        for (int j = 0; j < 16; j++)
#pragma unroll
            for (int t = 0; t < 4; t++) accs[j][t] = 0.f;

#pragma unroll
        for (int ks = 0; ks < 8; ks++) {
            uint32_t a[4];
            ldsm4(sQ + offAq + ks * 32, a[0], a[1], a[2], a[3]);
#pragma unroll
            for (int j = 0; j < 8; j++) {
                uint32_t b0, b1, b2, b3;
                ldsm4(kvb + offBk[j] + ks * 32, b0, b1, b2, b3);
                mma_f16(accs[j * 2 + 0], a, b0, b1);
                mma_f16(accs[j * 2 + 1], a, b2, b3);
            }
        }

        if (kb == qbi) {
#pragma unroll
            for (int jt = 0; jt < 16; jt++) {
                int col = kb * 128 + jt * 8 + 2 * qd;
                if (col     > row0) accs[jt][0] = -1e30f;
                if (col + 1 > row0) accs[jt][1] = -1e30f;
                if (col     > row8) accs[jt][2] = -1e30f;
                if (col + 1 > row8) accs[jt][3] = -1e30f;
            }
        }

        float mx0 = -1e30f, mx8 = -1e30f;
#pragma unroll
        for (int jt = 0; jt < 16; jt++) {
            mx0 = fmaxf(mx0, fmaxf(accs[jt][0], accs[jt][1]));
            mx8 = fmaxf(mx8, fmaxf(accs[jt][2], accs[jt][3]));
        }
        mx0 = fmaxf(mx0, __shfl_xor_sync(0xffffffffu, mx0, 1));
        mx0 = fmaxf(mx0, __shfl_xor_sync(0xffffffffu, mx0, 2));
        mx8 = fmaxf(mx8, __shfl_xor_sync(0xffffffffu, mx8, 1));
        mx8 = fmaxf(mx8, __shfl_xor_sync(0xffffffffu, mx8, 2));

        float nm0 = fmaxf(m0, mx0), nm8 = fmaxf(m8, mx8);
        bool nochg = (nm0 == m0) && (nm8 == m8);
        bool allno = __all_sync(0xffffffffu, nochg);
        float al0 = 1.f, al8 = 1.f;
        if (!allno) {
            al0 = exp2f(m0 - nm0);
            al8 = exp2f(m8 - nm8);
#pragma unroll
            for (int j = 0; j < 16; j++) {
                acco[j][0] *= al0; acco[j][1] *= al0;
                acco[j][2] *= al8; acco[j][3] *= al8;
            }
        }
        m0 = nm0; m8 = nm8;

        float s0 = 0.f, s8 = 0.f;
#pragma unroll
        for (int jt = 0; jt < 16; jt++) {
            accs[jt][0] = exp2f(accs[jt][0] - nm0);
            accs[jt][1] = exp2f(accs[jt][1] - nm0);
            accs[jt][2] = exp2f(accs[jt][2] - nm8);
            accs[jt][3] = exp2f(accs[jt][3] - nm8);
            s0 += accs[jt][0] + accs[jt][1];
            s8 += accs[jt][2] + accs[jt][3];
        }
        s0 += __shfl_xor_sync(0xffffffffu, s0, 1);
        s0 += __shfl_xor_sync(0xffffffffu, s0, 2);
        s8 += __shfl_xor_sync(0xffffffffu, s8, 1);
        s8 += __shfl_xor_sync(0xffffffffu, s8, 2);
        l0 = l0 * al0 + s0;
        lsum8 = lsum8 * al8 + s8;

        uint32_t pf[16][2];
#pragma unroll
        for (int jt = 0; jt < 16; jt++) {
            pf[jt][0] = h2u(__floats2half2_rn(accs[jt][0], accs[jt][1]));
            pf[jt][1] = h2u(__floats2half2_rn(accs[jt][2], accs[jt][3]));
        }

        const uint32_t vbase = kvb + SM_KPL;
#pragma unroll
        for (int t = 0; t < 8; t++) {
            uint32_t a[4];
            a[0] = pf[2 * t][0]; a[1] = pf[2 * t][1];
            a[2] = pf[2 * t + 1][0]; a[3] = pf[2 * t + 1][1];
#pragma unroll
            for (int jn = 0; jn < 8; jn++) {
                uint32_t b0, b1, b2, b3;
                ldsm4(vbase + offBv[jn] + t * 32, b0, b1, b2, b3);
                mma_f16(acco[jn * 2 + 0], a, b0, b1);
                mma_f16(acco[jn * 2 + 1], a, b2, b3);
            }
        }
        __syncthreads();
    }

    float inv0 = 1.f / l0, inv8 = 1.f / lsum8;
    const int blk  = qbi;
    const int rin0 = w * 16 + g;
    const int rin8 = rin0 + 8;
#pragma unroll
    for (int jt = 0; jt < 16; jt++) {
        int ks = h * 2 + (jt >> 3);
        int c8 = jt & 7;
        size_t chunk0 = ((size_t)(blk * 32 + ks) * 128 + rin0) * 8 + (c8 ^ (rin0 & 7));
        size_t chunk8 = ((size_t)(blk * 32 + ks) * 128 + rin8) * 8 + (c8 ^ (rin8 & 7));
        __half2 v0 = __floats2half2_rn(acco[jt][0] * inv0, acco[jt][1] * inv0);
        __half2 v8 = __floats2half2_rn(acco[jt][2] * inv8, acco[jt][3] * inv8);
        *reinterpret_cast<__half2*>(pao + chunk0 * 8 + qd * 2) = v0;
        *reinterpret_cast<__half2*>(pao + chunk8 * 8 + qd * 2) = v8;
    }
}

// ---------------- launch ----------------
extern "C" void kernel_launch(void* const* d_in, const int* in_sizes, int n_in,
                              void* d_out, int out_size)
{
    const float* x  = (const float*)d_in[0];
    const float* rc = (const float*)d_in[1];
    const float* rs = (const float*)d_in[2];
    const float* Wq = (const float*)d_in[3];
    const float* Wk = (const float*)d_in[4];
    const float* Wv = (const float*)d_in[5];
    const float* Wo = (const float*)d_in[6];
    float* out = (float*)d_out;

    __half *px, *pao, *pwq, *pwk, *pwv, *pwo;
    cudaGetSymbolAddress((void**)&px,  g_px);
    cudaGetSymbolAddress((void**)&pao, g_pao);
    cudaGetSymbolAddress((void**)&pwq, g_pwq);
    cudaGetSymbolAddress((void**)&pwk, g_pwk);
    cudaGetSymbolAddress((void**)&pwv, g_pwv);
    cudaGetSymbolAddress((void**)&pwo, g_pwo);

    __half *qh, *kh, *vth;
    cudaGetSymbolAddress((void**)&qh,  g_qh);
    cudaGetSymbolAddress((void**)&kh,  g_kh);
    cudaGetSymbolAddress((void**)&vth, g_vth);

    cudaFuncSetAttribute(gemm_bulk,
                         cudaFuncAttributeMaxDynamicSharedMemorySize, GB_SMEM);
    cudaFuncSetAttribute(gemm_qkv_fused,
                         cudaFuncAttributeMaxDynamicSharedMemorySize, GB_SMEM);
    cudaFuncSetAttribute(flash_mma,
                         cudaFuncAttributeMaxDynamicSharedMemorySize, FA_SMEM);

    // repack inputs (all blkrows = 128)
    conv_pack<<<S_LEN, 256>>>(x, px);
    conv_pack_w4<<<dim3(EMB, 4), 256>>>(Wq, Wk, Wv, Wo, pwq, pwk, pwv, pwo);

    // fused QKV projection + RoPE/transpose epilogue (768 CTAs, 2/SM)
    dim3 gq(EMB / 128, S_LEN / 128, 3);
    gemm_qkv_fused<<<gq, 256, GB_SMEM>>>(px, pwq, pwk, pwv, rc, rs,
                                         qh, kh, vth);

    // flash attention -> packed fp16 pao
    flash_mma<<<dim3(S_LEN / 128, NHEAD), 256, FA_SMEM>>>(qh, kh, vth, pao);

    // output projection
    dim3 gg(EMB / 128, S_LEN / 128);
    gemm_bulk<<<gg, 256, GB_SMEM>>>(pao, pwo, out);
}

// round 15
// speedup vs baseline: 1.7114x; 1.0237x over previous
#include <cuda_runtime.h>
#include <cuda_bf16.h>
#include <cuda_fp16.h>
#include <math.h>
#include <stdint.h>

#define S_LEN 2048
#define EMB   2048
#define NHEAD 16
#define HDIM  128

// ---------------- scratch (no cudaMalloc allowed) ----------------
// packed fp16 GEMM operands (stage-contiguous, swizzled, blkrows=128)
__device__ __align__(256) __half g_px [S_LEN * EMB];
__device__ __align__(256) __half g_pao[S_LEN * EMB];
__device__ __align__(256) __half g_pwq[EMB * EMB];
__device__ __align__(256) __half g_pwk[EMB * EMB];
__device__ __align__(256) __half g_pwv[EMB * EMB];
__device__ __align__(256) __half g_pwo[EMB * EMB];

// attention operands (fp16, single precision level)
__device__ __half g_qh [S_LEN * EMB];   // q (scaled by log2e/sqrt(d))
__device__ __half g_kh [S_LEN * EMB];
__device__ __half g_vth[NHEAD * HDIM * S_LEN];   // [h][d][s]

// ================= helpers (baseline PTX only) ==============
__device__ __forceinline__ uint32_t s2u(const void* p) {
    uint32_t a;
    asm("{ .reg .u64 t; cvta.to.shared.u64 t, %1; cvt.u32.u64 %0, t; }"
        : "=r"(a) : "l"(p));
    return a;
}

__device__ __forceinline__ void cpa16(uint32_t dst, const void* src) {
    asm volatile("cp.async.cg.shared.global [%0], [%1], 16;" :: "r"(dst), "l"(src));
}
#define CPA_COMMIT() asm volatile("cp.async.commit_group;" ::: "memory")
#define CPA_WAIT1()  asm volatile("cp.async.wait_group 1;" ::: "memory")

__device__ __forceinline__ void ldsm4(uint32_t addr, uint32_t& r0, uint32_t& r1,
                                      uint32_t& r2, uint32_t& r3) {
    asm volatile("ldmatrix.sync.aligned.m8n8.x4.shared.b16 {%0,%1,%2,%3}, [%4];"
                 : "=r"(r0), "=r"(r1), "=r"(r2), "=r"(r3) : "r"(addr));
}

__device__ __forceinline__ void mma_f16(float* d, const uint32_t* a,
                                        uint32_t b0, uint32_t b1) {
    asm volatile(
        "mma.sync.aligned.m16n8k16.row.col.f32.f16.f16.f32 "
        "{%0,%1,%2,%3}, {%4,%5,%6,%7}, {%8,%9}, {%0,%1,%2,%3};"
        : "+f"(d[0]), "+f"(d[1]), "+f"(d[2]), "+f"(d[3])
        : "r"(a[0]), "r"(a[1]), "r"(a[2]), "r"(a[3]), "r"(b0), "r"(b1));
}

__device__ __forceinline__ uint32_t h2u(__half2 v) {
    return *reinterpret_cast<uint32_t*>(&v);
}

// pack two fp32 -> half2 then ex2.approx.f16x2 (P fragment directly)
__device__ __forceinline__ uint32_t exp2_f16x2(float a, float b) {
    uint32_t packed, r;
    asm("cvt.rn.f16x2.f32 %0, %1, %2;" : "=r"(packed) : "f"(b), "f"(a));
    asm("ex2.approx.f16x2 %0, %1;" : "=r"(r) : "r"(packed));
    return r;
}

// ---- mbarrier / bulk-copy (sm_90 baseline PTX) ----
#define MBAR_INIT(mbar, cnt) \
    asm volatile("mbarrier.init.shared.b64 [%0], %1;" \
                 :: "r"((uint32_t)(mbar)), "r"((uint32_t)(cnt)) : "memory")
#define MBAR_EXPECT_TX(mbar, bytes) \
    asm volatile("mbarrier.arrive.expect_tx.shared.b64 _, [%0], %1;" \
                 :: "r"((uint32_t)(mbar)), "r"((uint32_t)(bytes)) : "memory")
#define MBAR_ARRIVE(mbar) \
    asm volatile("mbarrier.arrive.shared.b64 _, [%0];" \
                 :: "r"((uint32_t)(mbar)) : "memory")

__device__ __forceinline__ void mbar_wait(uint32_t mbar, uint32_t phase) {
    asm volatile(
        "{\n\t.reg .pred P1;\n\t"
        "WAIT_LOOP_%=:\n\t"
        "mbarrier.try_wait.parity.acquire.cta.shared::cta.b64 P1, [%0], %1, 0x989680;\n\t"
        "@P1 bra.uni WAIT_DONE_%=;\n\t"
        "bra.uni WAIT_LOOP_%=;\n\t"
        "WAIT_DONE_%=:\n\t}"
        :: "r"(mbar), "r"(phase) : "memory");
}

__device__ __forceinline__ void bulkcp(uint32_t dst, const void* src,
                                       uint32_t bytes, uint32_t mbar) {
    asm volatile(
        "cp.async.bulk.shared::cluster.global.mbarrier::complete_tx::bytes "
        "[%0], [%1], %2, [%3];"
        :: "r"(dst), "l"(src), "r"(bytes), "r"(mbar) : "memory");
}

// ================= repack fp32 -> fp16, stage-contiguous + XOR swizzle ====
__device__ __forceinline__ void pack_row(
    const float* __restrict__ src, __half* __restrict__ dst, int r, int t)
{
    const int ks  = t >> 3;
    const int cs  = t & 7;
    const int rin = r & 127;
    const int blk = r >> 7;
    const int c   = cs ^ (rin & 7);

    const float* s = src + (size_t)r * EMB + ks * 64 + c * 8;
    float4 v0 = *(const float4*)(s);
    float4 v1 = *(const float4*)(s + 4);

    __half2 h0 = __floats2half2_rn(v0.x, v0.y);
    __half2 h1 = __floats2half2_rn(v0.z, v0.w);
    __half2 h2 = __floats2half2_rn(v1.x, v1.y);
    __half2 h3 = __floats2half2_rn(v1.z, v1.w);

    size_t chunk = ((size_t)(blk * 32 + ks) * 128 + rin) * 8 + cs;
    uint4 out;
    out.x = h2u(h0); out.y = h2u(h1); out.z = h2u(h2); out.w = h2u(h3);
    *(reinterpret_cast<uint4*>(dst) + chunk) = out;
}

// pack x + 4 weights in ONE launch (blockIdx.y selects source)
__global__ __launch_bounds__(256) void conv_pack_all(
    const float* __restrict__ x,
    const float* __restrict__ w0, const float* __restrict__ w1,
    const float* __restrict__ w2, const float* __restrict__ w3,
    __half* __restrict__ dx,
    __half* __restrict__ d0, __half* __restrict__ d1,
    __half* __restrict__ d2, __half* __restrict__ d3)
{
    const float* s;
    __half* d;
    switch (blockIdx.y) {
        case 0: s = x;  d = dx; break;
        case 1: s = w0; d = d0; break;
        case 2: s = w1; d = d1; break;
        case 3: s = w2; d = d2; break;
        default: s = w3; d = d3; break;
    }
    pack_row(s, d, blockIdx.x, threadIdx.x);
}

// ================= TMA-bulk fp16 GEMM: CTA 128x128, 2 CTAs/SM ============
#define GB_AB_BYTES 16384
#define GB_STAGE    32768
#define GB_SMEM     (3 * GB_STAGE + 128)

__device__ __forceinline__ void gemm_main(
    const __half* __restrict__ Ap, const __half* __restrict__ Bp,
    int bx, int by, float acc[4][4][4])
{
    extern __shared__ char smraw[];
    const uint32_t sbase = s2u(smraw);
    const uint32_t mb    = sbase + 3 * GB_STAGE;

    const int tid  = threadIdx.x;
    const int lane = tid & 31;
    const int wid  = tid >> 5;
    const int wm   = wid & 1;
    const int wn   = wid >> 1;

    const int l8 = lane & 7;
    const int mt = lane >> 3;

    int rA[4], rB[2];
#pragma unroll
    for (int i = 0; i < 4; i++)
        rA[i] = wm * 64 + i * 16 + (mt & 1) * 8 + l8;
#pragma unroll
    for (int j = 0; j < 2; j++)
        rB[j] = wn * 32 + j * 16 + (mt >> 1) * 8 + l8;
    const int hcA = mt >> 1;
    const int hcB = mt & 1;

#pragma unroll
    for (int i = 0; i < 4; i++)
#pragma unroll
        for (int j = 0; j < 4; j++)
#pragma unroll
            for (int t = 0; t < 4; t++) acc[i][j][t] = 0.f;

    if (tid == 0) {
#pragma unroll
        for (int i = 0; i < 3; i++) {
            MBAR_INIT(mb + i * 16, 1);
            MBAR_INIT(mb + i * 16 + 8, 8);
        }
    }
    __syncthreads();

    const __half* Asrc = Ap + (size_t)by * 32 * 128 * 64;
    const __half* Bsrc = Bp + (size_t)bx * 32 * 128 * 64;

    if (tid == 0) {
#pragma unroll
        for (int i = 0; i < 3; i++) {
            MBAR_EXPECT_TX(mb + i * 16, GB_STAGE);
            bulkcp(sbase + i * GB_STAGE, Asrc + (size_t)i * 128 * 64,
                   GB_AB_BYTES, mb + i * 16);
            bulkcp(sbase + i * GB_STAGE + GB_AB_BYTES, Bsrc + (size_t)i * 128 * 64,
                   GB_AB_BYTES, mb + i * 16);
        }
    }

    const int NST = EMB / 64;
    for (int s = 0; s < NST; s++) {
        const int sl = s - (s / 3) * 3;
        const uint32_t ph = (uint32_t)((s / 3) & 1);
        const uint32_t slot = sbase + sl * GB_STAGE;

        mbar_wait(mb + sl * 16, ph);

#pragma unroll
        for (int ks = 0; ks < 4; ks++) {
            uint32_t a[4][4];
#pragma unroll
            for (int i = 0; i < 4; i++) {
                uint32_t ch = (uint32_t)((2 * ks + hcA) ^ (rA[i] & 7));
                ldsm4(slot + rA[i] * 128 + ch * 16,
                      a[i][0], a[i][1], a[i][2], a[i][3]);
            }
            uint32_t b[2][4];
#pragma unroll
            for (int j = 0; j < 2; j++) {
                uint32_t ch = (uint32_t)((2 * ks + hcB) ^ (rB[j] & 7));
                ldsm4(slot + GB_AB_BYTES + rB[j] * 128 + ch * 16,
                      b[j][0], b[j][1], b[j][2], b[j][3]);
            }
#pragma unroll
            for (int i = 0; i < 4; i++)
#pragma unroll
                for (int j = 0; j < 2; j++) {
                    mma_f16(acc[i][j * 2 + 0], a[i], b[j][0], b[j][1]);
                    mma_f16(acc[i][j * 2 + 1], a[i], b[j][2], b[j][3]);
                }
        }

        if (lane == 0) MBAR_ARRIVE(mb + sl * 16 + 8);

        if (tid == 0 && s + 3 < NST) {
            mbar_wait(mb + sl * 16 + 8, ph);
            MBAR_EXPECT_TX(mb + sl * 16, GB_STAGE);
            bulkcp(slot, Asrc + (size_t)(s + 3) * 128 * 64,
                   GB_AB_BYTES, mb + sl * 16);
            bulkcp(slot + GB_AB_BYTES, Bsrc + (size_t)(s + 3) * 128 * 64,
                   GB_AB_BYTES, mb + sl * 16);
        }
    }
}

// ---- Wo GEMM: plain fp32 epilogue ----
__global__ __launch_bounds__(256, 2) void gemm_bulk(
    const __half* __restrict__ Ap, const __half* __restrict__ Bp,
    float* __restrict__ C)
{
    float acc[4][4][4];
    gemm_main(Ap, Bp, blockIdx.x, blockIdx.y, acc);

    const int tid  = threadIdx.x;
    const int lane = tid & 31;
    const int wid  = tid >> 5;
    const int wm   = wid & 1;
    const int wn   = wid >> 1;
    const int bm   = blockIdx.y * 128;
    const int bn   = blockIdx.x * 128;
    const int g = lane >> 2;
    const int q = (lane & 3) * 2;
#pragma unroll
    for (int i = 0; i < 4; i++) {
#pragma unroll
        for (int j = 0; j < 4; j++) {
            int row = bm + wm * 64 + i * 16 + g;
            int col = bn + wn * 32 + j * 8 + q;
            *(float2*)(C + (size_t)row * EMB + col) =
                make_float2(acc[i][j][0], acc[i][j][1]);
            *(float2*)(C + (size_t)(row + 8) * EMB + col) =
                make_float2(acc[i][j][2], acc[i][j][3]);
        }
    }
}

// ---- fused QKV GEMM: 128x128 tile = one head. RoPE (Q,K) / transpose (V) -
#define EP_STRIDE 129

__global__ __launch_bounds__(256, 2) void gemm_qkv_fused(
    const __half* __restrict__ Ap,
    const __half* __restrict__ Bq, const __half* __restrict__ Bk,
    const __half* __restrict__ Bv,
    const float* __restrict__ cosb, const float* __restrict__ sinb,
    __half* __restrict__ qh, __half* __restrict__ kh,
    __half* __restrict__ vth)
{
    const int z = blockIdx.z;
    const __half* Bp = (z == 0) ? Bq : (z == 1) ? Bk : Bv;

    float acc[4][4][4];
    gemm_main(Ap, Bp, blockIdx.x, blockIdx.y, acc);

    extern __shared__ char smraw[];
    float* smf = reinterpret_cast<float*>(smraw);

    const int tid  = threadIdx.x;
    const int lane = tid & 31;
    const int wid  = tid >> 5;
    const int wm   = wid & 1;
    const int wn   = wid >> 1;
    const int bm   = blockIdx.y * 128;
    const int h    = blockIdx.x;
    const int g = lane >> 2;
    const int q = (lane & 3) * 2;

    __syncthreads();

#pragma unroll
    for (int i = 0; i < 4; i++) {
#pragma unroll
        for (int j = 0; j < 4; j++) {
            int row = wm * 64 + i * 16 + g;
            int col = wn * 32 + j * 8 + q;
            smf[row * EP_STRIDE + col]           = acc[i][j][0];
            smf[row * EP_STRIDE + col + 1]       = acc[i][j][1];
            smf[(row + 8) * EP_STRIDE + col]     = acc[i][j][2];
            smf[(row + 8) * EP_STRIDE + col + 1] = acc[i][j][3];
        }
    }
    __syncthreads();

    if (z < 2) {
        __half* dst = (z == 0) ? qh : kh;
        const float sc = (z == 0) ? 0.12751744f : 1.f;   // 1/sqrt(d)*log2(e)
        const int c    = tid & 127;
        const int shal = tid >> 7;
        const bool low = c < 64;
#pragma unroll 4
        for (int si = 0; si < 64; si++) {
            int s = shal * 64 + si;
            float a = smf[s * EP_STRIDE + c];
            float b = smf[s * EP_STRIDE + (c ^ 64)];
            int srow = bm + s;
            float cv = cosb[srow * HDIM + c];
            float sv = sinb[srow * HDIM + c];
            float out = (low ? (a * cv - b * sv) : (a * cv + b * sv)) * sc;
            dst[(size_t)srow * EMB + h * HDIM + c] = __float2half_rn(out);
        }
    } else {
        const int c0 = wid * 16;
#pragma unroll 4
        for (int cc = 0; cc < 16; cc++) {
            int d = c0 + cc;
            size_t rowbase = ((size_t)(h * HDIM + d)) * S_LEN + bm;
#pragma unroll
            for (int s4 = 0; s4 < 4; s4++) {
                int s = s4 * 32 + lane;
                vth[rowbase + s] = __float2half_rn(smf[s * EP_STRIDE + d]);
            }
        }
    }
}

// ---------------- Flash attention (mma.sync, fp16, K-block = 128) ---------
// Scores pre-scaled by log2(e); exp via ex2.approx.f16x2 directly into P
// fragments; row-sum l computed by an extra mma against a ones-fragment.
#define QB_ROW  272
#define KB_ROW  272
#define VB_ROW  272
#define SM_Q    (128 * QB_ROW)
#define SM_KPL  (128 * KB_ROW)
#define SM_VPL  (128 * VB_ROW)
#define SM_KV   (SM_KPL + SM_VPL)
#define FA_SMEM (SM_Q + 2 * SM_KV)      // 174080

__global__ __launch_bounds__(256, 1) void flash_mma(
    const __half* __restrict__ qh, const __half* __restrict__ kh,
    const __half* __restrict__ vth,
    __half* __restrict__ pao)
{
    extern __shared__ char smraw[];
    const uint32_t sQ = s2u(smraw);

    const int tid  = threadIdx.x;
    const int lane = tid & 31;
    const int w    = tid >> 5;
    const int g    = lane >> 2;
    const int qd   = lane & 3;
    const int l8   = lane & 7;
    const int mt   = lane >> 3;
    const int qbi  = gridDim.x - 1 - blockIdx.x;
    const int h    = blockIdx.y;

    const uint32_t ONES = 0x3C003C00u;   // half2(1.0, 1.0)

    const uint32_t offAq = (uint32_t)((w * 16 + (mt & 1) * 8 + l8) * QB_ROW + (mt >> 1) * 16);
    uint32_t offBk[8], offBv[8];
#pragma unroll
    for (int j = 0; j < 8; j++)
        offBk[j] = (uint32_t)((j * 16 + (mt >> 1) * 8 + l8) * KB_ROW + (mt & 1) * 16);
#pragma unroll
    for (int j = 0; j < 8; j++)
        offBv[j] = (uint32_t)((j * 16 + (mt >> 1) * 8 + l8) * VB_ROW + (mt & 1) * 16);

#pragma unroll
    for (int i = 0; i < 8; i++) {
        int e = tid + i * 256;
        int r = (e >> 4) & 127;
        int c = e & 15;
        const __half* s = qh + (size_t)(qbi * 128 + r) * EMB + h * HDIM + c * 8;
        cpa16(sQ + r * QB_ROW + c * 16, s);
    }

    auto load_kv = [&](int buf, int kb) {
        uint32_t kvb = sQ + SM_Q + buf * SM_KV;
#pragma unroll
        for (int i = 0; i < 8; i++) {
            int e = tid + i * 256;
            int r = (e >> 4) & 127;
            int c = e & 15;
            const __half* s = kh + (size_t)(kb * 128 + r) * EMB + h * HDIM + c * 8;
            cpa16(kvb + r * KB_ROW + c * 16, s);
        }
#pragma unroll
        for (int i = 0; i < 8; i++) {
            int e = tid + i * 256;
            int r = (e >> 4) & 127;
            int c = e & 15;
            const __half* s = vth + (size_t)(h * HDIM + r) * S_LEN + kb * 128 + c * 8;
            cpa16(kvb + SM_KPL + r * VB_ROW + c * 16, s);
        }
    };

    const int nkb = qbi + 1;
    load_kv(0, 0);
    CPA_COMMIT();

    float acco[16][4];
#pragma unroll
    for (int j = 0; j < 16; j++)
#pragma unroll
        for (int t = 0; t < 4; t++) acco[j][t] = 0.f;
    float lacc[4] = {0.f, 0.f, 0.f, 0.f};   // row-sum accumulator (ones-mma)
    float m0 = -1e30f, m8 = -1e30f;

    const int row0 = qbi * 128 + w * 16 + g;
    const int row8 = row0 + 8;

    for (int kb = 0; kb < nkb; kb++) {
        if (kb + 1 < nkb) load_kv((kb + 1) & 1, kb + 1);
        CPA_COMMIT();
        CPA_WAIT1();
        __syncthreads();

        const uint32_t kvb = sQ + SM_Q + (kb & 1) * SM_KV;

        // ---- S = Q K^T : 16 x 128 tile (log2 domain) ----
        float accs[16][4];
#pragma unroll
        for (int j = 0; j < 16; j++)
#pragma unroll
            for (int t = 0; t < 4; t++) accs[j][t] = 0.f;

#pragma unroll
        for (int ks = 0; ks < 8; ks++) {
            uint32_t a[4];
            ldsm4(sQ + offAq + ks * 32, a[0], a[1], a[2], a[3]);
#pragma unroll
            for (int j = 0; j < 8; j++) {
                uint32_t b0, b1, b2, b3;
                ldsm4(kvb + offBk[j] + ks * 32, b0, b1, b2, b3);
                mma_f16(accs[j * 2 + 0], a, b0, b1);
                mma_f16(accs[j * 2 + 1], a, b2, b3);
            }
        }

        if (kb == qbi) {
#pragma unroll
            for (int jt = 0; jt < 16; jt++) {
                int col = kb * 128 + jt * 8 + 2 * qd;
                if (col     > row0) accs[jt][0] = -1e30f;
                if (col + 1 > row0) accs[jt][1] = -1e30f;
                if (col     > row8) accs[jt][2] = -1e30f;
                if (col + 1 > row8) accs[jt][3] = -1e30f;
            }
        }

        // ---- online max (base-2 domain) ----
        float mx0 = -1e30f, mx8 = -1e30f;
#pragma unroll
        for (int jt = 0; jt < 16; jt++) {
            mx0 = fmaxf(mx0, fmaxf(accs[jt][0], accs[jt][1]));
            mx8 = fmaxf(mx8, fmaxf(accs[jt][2], accs[jt][3]));
        }
        mx0 = fmaxf(mx0, __shfl_xor_sync(0xffffffffu, mx0, 1));
        mx0 = fmaxf(mx0, __shfl_xor_sync(0xffffffffu, mx0, 2));
        mx8 = fmaxf(mx8, __shfl_xor_sync(0xffffffffu, mx8, 1));
        mx8 = fmaxf(mx8, __shfl_xor_sync(0xffffffffu, mx8, 2));

        float nm0 = fmaxf(m0, mx0), nm8 = fmaxf(m8, mx8);
        bool nochg = (nm0 == m0) && (nm8 == m8);
        bool allno = __all_sync(0xffffffffu, nochg);
        if (!allno) {
            float al0 = exp2f(m0 - nm0);
            float al8 = exp2f(m8 - nm8);
#pragma unroll
            for (int j = 0; j < 16; j++) {
                acco[j][0] *= al0; acco[j][1] *= al0;
                acco[j][2] *= al8; acco[j][3] *= al8;
            }
            lacc[0] *= al0; lacc[1] *= al0;
            lacc[2] *= al8; lacc[3] *= al8;
        }
        m0 = nm0; m8 = nm8;

        // ---- P = exp2(S - m) directly into fp16 fragments ----
        uint32_t pf[16][2];
#pragma unroll
        for (int jt = 0; jt < 16; jt++) {
            pf[jt][0] = exp2_f16x2(accs[jt][0] - nm0, accs[jt][1] - nm0);
            pf[jt][1] = exp2_f16x2(accs[jt][2] - nm8, accs[jt][3] - nm8);
        }

        // ---- O += P V ; l += P * 1 (ones-fragment mma, no ldsm) ----
        const uint32_t vbase = kvb + SM_KPL;
#pragma unroll
        for (int t = 0; t < 8; t++) {
            uint32_t a[4];
            a[0] = pf[2 * t][0]; a[1] = pf[2 * t][1];
            a[2] = pf[2 * t + 1][0]; a[3] = pf[2 * t + 1][1];
            mma_f16(lacc, a, ONES, ONES);
#pragma unroll
            for (int jn = 0; jn < 8; jn++) {
                uint32_t b0, b1, b2, b3;
                ldsm4(vbase + offBv[jn] + t * 32, b0, b1, b2, b3);
                mma_f16(acco[jn * 2 + 0], a, b0, b1);
                mma_f16(acco[jn * 2 + 1], a, b2, b3);
            }
        }
        __syncthreads();
    }

    // ---- epilogue: write packed fp16 (layout consumed by Wo GEMM) ----
    float inv0 = 1.f / lacc[0], inv8 = 1.f / lacc[2];
    const int blk  = qbi;
    const int rin0 = w * 16 + g;
    const int rin8 = rin0 + 8;
#pragma unroll
    for (int jt = 0; jt < 16; jt++) {
        int ks = h * 2 + (jt >> 3);
        int c8 = jt & 7;
        size_t chunk0 = ((size_t)(blk * 32 + ks) * 128 + rin0) * 8 + (c8 ^ (rin0 & 7));
        size_t chunk8 = ((size_t)(blk * 32 + ks) * 128 + rin8) * 8 + (c8 ^ (rin8 & 7));
        __half2 v0 = __floats2half2_rn(acco[jt][0] * inv0, acco[jt][1] * inv0);
        __half2 v8 = __floats2half2_rn(acco[jt][2] * inv8, acco[jt][3] * inv8);
        *reinterpret_cast<__half2*>(pao + chunk0 * 8 + qd * 2) = v0;
        *reinterpret_cast<__half2*>(pao + chunk8 * 8 + qd * 2) = v8;
    }
}

// ---------------- launch ----------------
extern "C" void kernel_launch(void* const* d_in, const int* in_sizes, int n_in,
                              void* d_out, int out_size)
{
    const float* x  = (const float*)d_in[0];
    const float* rc = (const float*)d_in[1];
    const float* rs = (const float*)d_in[2];
    const float* Wq = (const float*)d_in[3];
    const float* Wk = (const float*)d_in[4];
    const float* Wv = (const float*)d_in[5];
    const float* Wo = (const float*)d_in[6];
    float* out = (float*)d_out;

    __half *px, *pao, *pwq, *pwk, *pwv, *pwo;
    cudaGetSymbolAddress((void**)&px,  g_px);
    cudaGetSymbolAddress((void**)&pao, g_pao);
    cudaGetSymbolAddress((void**)&pwq, g_pwq);
    cudaGetSymbolAddress((void**)&pwk, g_pwk);
    cudaGetSymbolAddress((void**)&pwv, g_pwv);
    cudaGetSymbolAddress((void**)&pwo, g_pwo);

    __half *qh, *kh, *vth;
    cudaGetSymbolAddress((void**)&qh,  g_qh);
    cudaGetSymbolAddress((void**)&kh,  g_kh);
    cudaGetSymbolAddress((void**)&vth, g_vth);

    cudaFuncSetAttribute(gemm_bulk,
                         cudaFuncAttributeMaxDynamicSharedMemorySize, GB_SMEM);
    cudaFuncSetAttribute(gemm_qkv_fused,
                         cudaFuncAttributeMaxDynamicSharedMemorySize, GB_SMEM);
    cudaFuncSetAttribute(flash_mma,
                         cudaFuncAttributeMaxDynamicSharedMemorySize, FA_SMEM);

    // repack inputs (x + 4 weights in one launch)
    conv_pack_all<<<dim3(EMB, 5), 256>>>(x, Wq, Wk, Wv, Wo,
                                         px, pwq, pwk, pwv, pwo);

    // fused QKV projection + RoPE/transpose epilogue (768 CTAs, 2/SM)
    dim3 gq(EMB / 128, S_LEN / 128, 3);
    gemm_qkv_fused<<<gq, 256, GB_SMEM>>>(px, pwq, pwk, pwv, rc, rs,
                                         qh, kh, vth);

    // flash attention -> packed fp16 pao
    flash_mma<<<dim3(S_LEN / 128, NHEAD), 256, FA_SMEM>>>(qh, kh, vth, pao);

    // output projection
    dim3 gg(EMB / 128, S_LEN / 128);
    gemm_bulk<<<gg, 256, GB_SMEM>>>(pao, pwo, out);
}

// round 16
// speedup vs baseline: 1.7819x; 1.0412x over previous
#include <cuda_runtime.h>
#include <cuda_bf16.h>
#include <cuda_fp16.h>
#include <math.h>
#include <stdint.h>

#define S_LEN 2048
#define EMB   2048
#define NHEAD 16
#define HDIM  128

// ---------------- scratch (no cudaMalloc allowed) ----------------
__device__ __align__(256) __half g_px [S_LEN * EMB];
__device__ __align__(256) __half g_pao[S_LEN * EMB];
__device__ __align__(256) __half g_pwq[EMB * EMB];
__device__ __align__(256) __half g_pwk[EMB * EMB];
__device__ __align__(256) __half g_pwv[EMB * EMB];
__device__ __align__(256) __half g_pwo[EMB * EMB];

__device__ __half g_qh [S_LEN * EMB];   // q (scaled by log2e/sqrt(d))
__device__ __half g_kh [S_LEN * EMB];
__device__ __half g_vth[NHEAD * HDIM * S_LEN];   // [h][d][s]

// ================= helpers (baseline PTX only) ==============
__device__ __forceinline__ uint32_t s2u(const void* p) {
    uint32_t a;
    asm("{ .reg .u64 t; cvta.to.shared.u64 t, %1; cvt.u32.u64 %0, t; }"
        : "=r"(a) : "l"(p));
    return a;
}

__device__ __forceinline__ void cpa16(uint32_t dst, const void* src) {
    asm volatile("cp.async.cg.shared.global [%0], [%1], 16;" :: "r"(dst), "l"(src));
}
#define CPA_COMMIT() asm volatile("cp.async.commit_group;" ::: "memory")
#define CPA_WAIT1()  asm volatile("cp.async.wait_group 1;" ::: "memory")

__device__ __forceinline__ void ldsm4(uint32_t addr, uint32_t& r0, uint32_t& r1,
                                      uint32_t& r2, uint32_t& r3) {
    asm volatile("ldmatrix.sync.aligned.m8n8.x4.shared.b16 {%0,%1,%2,%3}, [%4];"
                 : "=r"(r0), "=r"(r1), "=r"(r2), "=r"(r3) : "r"(addr));
}

__device__ __forceinline__ void mma_f16(float* d, const uint32_t* a,
                                        uint32_t b0, uint32_t b1) {
    asm volatile(
        "mma.sync.aligned.m16n8k16.row.col.f32.f16.f16.f32 "
        "{%0,%1,%2,%3}, {%4,%5,%6,%7}, {%8,%9}, {%0,%1,%2,%3};"
        : "+f"(d[0]), "+f"(d[1]), "+f"(d[2]), "+f"(d[3])
        : "r"(a[0]), "r"(a[1]), "r"(a[2]), "r"(a[3]), "r"(b0), "r"(b1));
}

__device__ __forceinline__ uint32_t h2u(__half2 v) {
    return *reinterpret_cast<uint32_t*>(&v);
}

__device__ __forceinline__ uint32_t exp2_f16x2(float a, float b) {
    uint32_t packed, r;
    asm("cvt.rn.f16x2.f32 %0, %1, %2;" : "=r"(packed) : "f"(b), "f"(a));
    asm("ex2.approx.f16x2 %0, %1;" : "=r"(r) : "r"(packed));
    return r;
}

// ---- mbarrier / bulk-copy (sm_90 baseline PTX) ----
#define MBAR_INIT(mbar, cnt) \
    asm volatile("mbarrier.init.shared.b64 [%0], %1;" \
                 :: "r"((uint32_t)(mbar)), "r"((uint32_t)(cnt)) : "memory")
#define MBAR_EXPECT_TX(mbar, bytes) \
    asm volatile("mbarrier.arrive.expect_tx.shared.b64 _, [%0], %1;" \
                 :: "r"((uint32_t)(mbar)), "r"((uint32_t)(bytes)) : "memory")
#define MBAR_ARRIVE(mbar) \
    asm volatile("mbarrier.arrive.shared.b64 _, [%0];" \
                 :: "r"((uint32_t)(mbar)) : "memory")

__device__ __forceinline__ void mbar_wait(uint32_t mbar, uint32_t phase) {
    asm volatile(
        "{\n\t.reg .pred P1;\n\t"
        "WAIT_LOOP_%=:\n\t"
        "mbarrier.try_wait.parity.acquire.cta.shared::cta.b64 P1, [%0], %1, 0x989680;\n\t"
        "@P1 bra.uni WAIT_DONE_%=;\n\t"
        "bra.uni WAIT_LOOP_%=;\n\t"
        "WAIT_DONE_%=:\n\t}"
        :: "r"(mbar), "r"(phase) : "memory");
}

__device__ __forceinline__ void bulkcp(uint32_t dst, const void* src,
                                       uint32_t bytes, uint32_t mbar) {
    asm volatile(
        "cp.async.bulk.shared::cluster.global.mbarrier::complete_tx::bytes "
        "[%0], [%1], %2, [%3];"
        :: "r"(dst), "l"(src), "r"(bytes), "r"(mbar) : "memory");
}

// ================= repack fp32 -> fp16, stage-contiguous + XOR swizzle ====
__device__ __forceinline__ void pack_row(
    const float* __restrict__ src, __half* __restrict__ dst, int r, int t)
{
    const int ks  = t >> 3;
    const int cs  = t & 7;
    const int rin = r & 127;
    const int blk = r >> 7;
    const int c   = cs ^ (rin & 7);

    const float* s = src + (size_t)r * EMB + ks * 64 + c * 8;
    float4 v0 = *(const float4*)(s);
    float4 v1 = *(const float4*)(s + 4);

    __half2 h0 = __floats2half2_rn(v0.x, v0.y);
    __half2 h1 = __floats2half2_rn(v0.z, v0.w);
    __half2 h2 = __floats2half2_rn(v1.x, v1.y);
    __half2 h3 = __floats2half2_rn(v1.z, v1.w);

    size_t chunk = ((size_t)(blk * 32 + ks) * 128 + rin) * 8 + cs;
    uint4 out;
    out.x = h2u(h0); out.y = h2u(h1); out.z = h2u(h2); out.w = h2u(h3);
    *(reinterpret_cast<uint4*>(dst) + chunk) = out;
}

__global__ __launch_bounds__(256) void conv_pack_all(
    const float* __restrict__ x,
    const float* __restrict__ w0, const float* __restrict__ w1,
    const float* __restrict__ w2, const float* __restrict__ w3,
    __half* __restrict__ dx,
    __half* __restrict__ d0, __half* __restrict__ d1,
    __half* __restrict__ d2, __half* __restrict__ d3)
{
    const float* s;
    __half* d;
    switch (blockIdx.y) {
        case 0: s = x;  d = dx; break;
        case 1: s = w0; d = d0; break;
        case 2: s = w1; d = d1; break;
        case 3: s = w2; d = d2; break;
        default: s = w3; d = d3; break;
    }
    pack_row(s, d, blockIdx.x, threadIdx.x);
}

// ================= TMA-bulk fp16 GEMM: CTA 128x128, 2 CTAs/SM ============
#define GB_AB_BYTES 16384
#define GB_STAGE    32768
#define GB_SMEM     (3 * GB_STAGE + 128)

__device__ __forceinline__ void gemm_main(
    const __half* __restrict__ Ap, const __half* __restrict__ Bp,
    int bx, int by, float acc[4][4][4])
{
    extern __shared__ char smraw[];
    const uint32_t sbase = s2u(smraw);
    const uint32_t mb    = sbase + 3 * GB_STAGE;

    const int tid  = threadIdx.x;
    const int lane = tid & 31;
    const int wid  = tid >> 5;
    const int wm   = wid & 1;
    const int wn   = wid >> 1;

    const int l8 = lane & 7;
    const int mt = lane >> 3;

    int rA[4], rB[2];
#pragma unroll
    for (int i = 0; i < 4; i++)
        rA[i] = wm * 64 + i * 16 + (mt & 1) * 8 + l8;
#pragma unroll
    for (int j = 0; j < 2; j++)
        rB[j] = wn * 32 + j * 16 + (mt >> 1) * 8 + l8;
    const int hcA = mt >> 1;
    const int hcB = mt & 1;

#pragma unroll
    for (int i = 0; i < 4; i++)
#pragma unroll
        for (int j = 0; j < 4; j++)
#pragma unroll
            for (int t = 0; t < 4; t++) acc[i][j][t] = 0.f;

    if (tid == 0) {
#pragma unroll
        for (int i = 0; i < 3; i++) {
            MBAR_INIT(mb + i * 16, 1);
            MBAR_INIT(mb + i * 16 + 8, 8);
        }
    }
    __syncthreads();

    const __half* Asrc = Ap + (size_t)by * 32 * 128 * 64;
    const __half* Bsrc = Bp + (size_t)bx * 32 * 128 * 64;

    if (tid == 0) {
#pragma unroll
        for (int i = 0; i < 3; i++) {
            MBAR_EXPECT_TX(mb + i * 16, GB_STAGE);
            bulkcp(sbase + i * GB_STAGE, Asrc + (size_t)i * 128 * 64,
                   GB_AB_BYTES, mb + i * 16);
            bulkcp(sbase + i * GB_STAGE + GB_AB_BYTES, Bsrc + (size_t)i * 128 * 64,
                   GB_AB_BYTES, mb + i * 16);
        }
    }

    const int NST = EMB / 64;
    for (int s = 0; s < NST; s++) {
        const int sl = s - (s / 3) * 3;
        const uint32_t ph = (uint32_t)((s / 3) & 1);
        const uint32_t slot = sbase + sl * GB_STAGE;

        mbar_wait(mb + sl * 16, ph);

#pragma unroll
        for (int ks = 0; ks < 4; ks++) {
            uint32_t a[4][4];
#pragma unroll
            for (int i = 0; i < 4; i++) {
                uint32_t ch = (uint32_t)((2 * ks + hcA) ^ (rA[i] & 7));
                ldsm4(slot + rA[i] * 128 + ch * 16,
                      a[i][0], a[i][1], a[i][2], a[i][3]);
            }
            uint32_t b[2][4];
#pragma unroll
            for (int j = 0; j < 2; j++) {
                uint32_t ch = (uint32_t)((2 * ks + hcB) ^ (rB[j] & 7));
                ldsm4(slot + GB_AB_BYTES + rB[j] * 128 + ch * 16,
                      b[j][0], b[j][1], b[j][2], b[j][3]);
            }
#pragma unroll
            for (int i = 0; i < 4; i++)
#pragma unroll
                for (int j = 0; j < 2; j++) {
                    mma_f16(acc[i][j * 2 + 0], a[i], b[j][0], b[j][1]);
                    mma_f16(acc[i][j * 2 + 1], a[i], b[j][2], b[j][3]);
                }
        }

        if (lane == 0) MBAR_ARRIVE(mb + sl * 16 + 8);

        if (tid == 0 && s + 3 < NST) {
            mbar_wait(mb + sl * 16 + 8, ph);
            MBAR_EXPECT_TX(mb + sl * 16, GB_STAGE);
            bulkcp(slot, Asrc + (size_t)(s + 3) * 128 * 64,
                   GB_AB_BYTES, mb + sl * 16);
            bulkcp(slot + GB_AB_BYTES, Bsrc + (size_t)(s + 3) * 128 * 64,
                   GB_AB_BYTES, mb + sl * 16);
        }
    }
}

// ---- Wo GEMM: plain fp32 epilogue ----
__global__ __launch_bounds__(256, 2) void gemm_bulk(
    const __half* __restrict__ Ap, const __half* __restrict__ Bp,
    float* __restrict__ C)
{
    float acc[4][4][4];
    gemm_main(Ap, Bp, blockIdx.x, blockIdx.y, acc);

    const int tid  = threadIdx.x;
    const int lane = tid & 31;
    const int wid  = tid >> 5;
    const int wm   = wid & 1;
    const int wn   = wid >> 1;
    const int bm   = blockIdx.y * 128;
    const int bn   = blockIdx.x * 128;
    const int g = lane >> 2;
    const int q = (lane & 3) * 2;
#pragma unroll
    for (int i = 0; i < 4; i++) {
#pragma unroll
        for (int j = 0; j < 4; j++) {
            int row = bm + wm * 64 + i * 16 + g;
            int col = bn + wn * 32 + j * 8 + q;
            *(float2*)(C + (size_t)row * EMB + col) =
                make_float2(acc[i][j][0], acc[i][j][1]);
            *(float2*)(C + (size_t)(row + 8) * EMB + col) =
                make_float2(acc[i][j][2], acc[i][j][3]);
        }
    }
}

// ---- fused QKV GEMM: 128x128 tile = one head. RoPE (Q,K) / transpose (V) -
#define EP_STRIDE 129

__global__ __launch_bounds__(256, 2) void gemm_qkv_fused(
    const __half* __restrict__ Ap,
    const __half* __restrict__ Bq, const __half* __restrict__ Bk,
    const __half* __restrict__ Bv,
    const float* __restrict__ cosb, const float* __restrict__ sinb,
    __half* __restrict__ qh, __half* __restrict__ kh,
    __half* __restrict__ vth)
{
    const int z = blockIdx.z;
    const __half* Bp = (z == 0) ? Bq : (z == 1) ? Bk : Bv;

    float acc[4][4][4];
    gemm_main(Ap, Bp, blockIdx.x, blockIdx.y, acc);

    extern __shared__ char smraw[];
    float* smf = reinterpret_cast<float*>(smraw);

    const int tid  = threadIdx.x;
    const int lane = tid & 31;
    const int wid  = tid >> 5;
    const int wm   = wid & 1;
    const int wn   = wid >> 1;
    const int bm   = blockIdx.y * 128;
    const int h    = blockIdx.x;
    const int g = lane >> 2;
    const int q = (lane & 3) * 2;

    __syncthreads();

#pragma unroll
    for (int i = 0; i < 4; i++) {
#pragma unroll
        for (int j = 0; j < 4; j++) {
            int row = wm * 64 + i * 16 + g;
            int col = wn * 32 + j * 8 + q;
            smf[row * EP_STRIDE + col]           = acc[i][j][0];
            smf[row * EP_STRIDE + col + 1]       = acc[i][j][1];
            smf[(row + 8) * EP_STRIDE + col]     = acc[i][j][2];
            smf[(row + 8) * EP_STRIDE + col + 1] = acc[i][j][3];
        }
    }
    __syncthreads();

    if (z < 2) {
        __half* dst = (z == 0) ? qh : kh;
        const float sc = (z == 0) ? 0.12751744f : 1.f;
        const int c    = tid & 127;
        const int shal = tid >> 7;
        const bool low = c < 64;
#pragma unroll 4
        for (int si = 0; si < 64; si++) {
            int s = shal * 64 + si;
            float a = smf[s * EP_STRIDE + c];
            float b = smf[s * EP_STRIDE + (c ^ 64)];
            int srow = bm + s;
            float cv = cosb[srow * HDIM + c];
            float sv = sinb[srow * HDIM + c];
            float out = (low ? (a * cv - b * sv) : (a * cv + b * sv)) * sc;
            dst[(size_t)srow * EMB + h * HDIM + c] = __float2half_rn(out);
        }
    } else {
        const int c0 = wid * 16;
#pragma unroll 4
        for (int cc = 0; cc < 16; cc++) {
            int d = c0 + cc;
            size_t rowbase = ((size_t)(h * HDIM + d)) * S_LEN + bm;
#pragma unroll
            for (int s4 = 0; s4 < 4; s4++) {
                int s = s4 * 32 + lane;
                vth[rowbase + s] = __float2half_rn(smf[s * EP_STRIDE + d]);
            }
        }
    }
}

// ---------------- Flash attention v2: 128-thr CTA, 64 q-rows, 2 CTAs/SM ---
// k-block 128; K and V single-buffered, separately committed cp.async groups
// pipelined around compute phases. Sibling CTA covers residual stalls.
#define QB_ROW  272
#define KB_ROW  272
#define VB_ROW  272
#define SM_Q    (64 * QB_ROW)           // 17408
#define SM_K    (128 * KB_ROW)          // 34816
#define SM_V    (128 * VB_ROW)          // 34816
#define FA_SMEM (SM_Q + SM_K + SM_V)    // 87040 -> 2 CTAs/SM

__global__ __launch_bounds__(128, 2) void flash_mma(
    const __half* __restrict__ qh, const __half* __restrict__ kh,
    const __half* __restrict__ vth,
    __half* __restrict__ pao)
{
    extern __shared__ char smraw[];
    const uint32_t sQ = s2u(smraw);
    const uint32_t sK = sQ + SM_Q;
    const uint32_t sV = sK + SM_K;

    const int tid  = threadIdx.x;
    const int lane = tid & 31;
    const int w    = tid >> 5;          // 0..3
    const int g    = lane >> 2;
    const int qd   = lane & 3;
    const int l8   = lane & 7;
    const int mt   = lane >> 3;
    const int qbi  = gridDim.x - 1 - blockIdx.x;   // heaviest first (64-row blocks)
    const int h    = blockIdx.y;

    const uint32_t ONES = 0x3C003C00u;

    const uint32_t offAq = (uint32_t)((w * 16 + (mt & 1) * 8 + l8) * QB_ROW + (mt >> 1) * 16);
    uint32_t offBk[8], offBv[8];
#pragma unroll
    for (int j = 0; j < 8; j++)
        offBk[j] = (uint32_t)((j * 16 + (mt >> 1) * 8 + l8) * KB_ROW + (mt & 1) * 16);
#pragma unroll
    for (int j = 0; j < 8; j++)
        offBv[j] = (uint32_t)((j * 16 + (mt >> 1) * 8 + l8) * VB_ROW + (mt & 1) * 16);

    // ---- load Q (64 rows x 128 halves), 8 iters of 128 threads ----
#pragma unroll
    for (int i = 0; i < 8; i++) {
        int e = tid + i * 128;
        int r = (e >> 4) & 63;
        int c = e & 15;
        const __half* s = qh + (size_t)(qbi * 64 + r) * EMB + h * HDIM + c * 8;
        cpa16(sQ + r * QB_ROW + c * 16, s);
    }

    auto load_k = [&](int kb) {
#pragma unroll
        for (int i = 0; i < 16; i++) {
            int e = tid + i * 128;
            int r = (e >> 4) & 127;
            int c = e & 15;
            const __half* s = kh + (size_t)(kb * 128 + r) * EMB + h * HDIM + c * 8;
            cpa16(sK + r * KB_ROW + c * 16, s);
        }
    };
    auto load_v = [&](int kb) {
#pragma unroll
        for (int i = 0; i < 16; i++) {
            int e = tid + i * 128;
            int r = (e >> 4) & 127;
            int c = e & 15;
            const __half* s = vth + (size_t)(h * HDIM + r) * S_LEN + kb * 128 + c * 8;
            cpa16(sV + r * VB_ROW + c * 16, s);
        }
    };

    const int nkb = (qbi >> 1) + 1;
    load_k(0);
    CPA_COMMIT();        // group: K(0)
    load_v(0);
    CPA_COMMIT();        // group: V(0)

    float acco[16][4];
#pragma unroll
    for (int j = 0; j < 16; j++)
#pragma unroll
        for (int t = 0; t < 4; t++) acco[j][t] = 0.f;
    float lacc[4] = {0.f, 0.f, 0.f, 0.f};
    float m0 = -1e30f, m8 = -1e30f;

    const int row0 = qbi * 64 + w * 16 + g;
    const int row8 = row0 + 8;

    for (int kb = 0; kb < nkb; kb++) {
        // invariant entering: in-flight groups = [K(kb), V(kb)]
        CPA_WAIT1();         // K(kb) complete (V(kb) may be in flight)
        __syncthreads();

        // ---- S = Q K^T : 16 x 128 per warp (log2 domain) ----
        float accs[16][4];
#pragma unroll
        for (int j = 0; j < 16; j++)
#pragma unroll
            for (int t = 0; t < 4; t++) accs[j][t] = 0.f;

#pragma unroll
        for (int ks = 0; ks < 8; ks++) {
            uint32_t a[4];
            ldsm4(sQ + offAq + ks * 32, a[0], a[1], a[2], a[3]);
#pragma unroll
            for (int j = 0; j < 8; j++) {
                uint32_t b0, b1, b2, b3;
                ldsm4(sK + offBk[j] + ks * 32, b0, b1, b2, b3);
                mma_f16(accs[j * 2 + 0], a, b0, b1);
                mma_f16(accs[j * 2 + 1], a, b2, b3);
            }
        }
        __syncthreads();     // all warps done reading K

        if (kb + 1 < nkb) load_k(kb + 1);
        CPA_COMMIT();        // group: K(kb+1) (possibly empty)

        // causal mask on the final (diagonal) k-block
        if (kb == nkb - 1) {
#pragma unroll
            for (int jt = 0; jt < 16; jt++) {
                int col = kb * 128 + jt * 8 + 2 * qd;
                if (col     > row0) accs[jt][0] = -1e30f;
                if (col + 1 > row0) accs[jt][1] = -1e30f;
                if (col     > row8) accs[jt][2] = -1e30f;
                if (col + 1 > row8) accs[jt][3] = -1e30f;
            }
        }

        // ---- online max (base-2) ----
        float mx0 = -1e30f, mx8 = -1e30f;
#pragma unroll
        for (int jt = 0; jt < 16; jt++) {
            mx0 = fmaxf(mx0, fmaxf(accs[jt][0], accs[jt][1]));
            mx8 = fmaxf(mx8, fmaxf(accs[jt][2], accs[jt][3]));
        }
        mx0 = fmaxf(mx0, __shfl_xor_sync(0xffffffffu, mx0, 1));
        mx0 = fmaxf(mx0, __shfl_xor_sync(0xffffffffu, mx0, 2));
        mx8 = fmaxf(mx8, __shfl_xor_sync(0xffffffffu, mx8, 1));
        mx8 = fmaxf(mx8, __shfl_xor_sync(0xffffffffu, mx8, 2));

        float nm0 = fmaxf(m0, mx0), nm8 = fmaxf(m8, mx8);
        bool nochg = (nm0 == m0) && (nm8 == m8);
        bool allno = __all_sync(0xffffffffu, nochg);
        if (!allno) {
            float al0 = exp2f(m0 - nm0);
            float al8 = exp2f(m8 - nm8);
#pragma unroll
            for (int j = 0; j < 16; j++) {
                acco[j][0] *= al0; acco[j][1] *= al0;
                acco[j][2] *= al8; acco[j][3] *= al8;
            }
            lacc[0] *= al0; lacc[1] *= al0;
            lacc[2] *= al8; lacc[3] *= al8;
        }
        m0 = nm0; m8 = nm8;

        // ---- P = exp2(S - m) -> fp16 fragments ----
        uint32_t pf[16][2];
#pragma unroll
        for (int jt = 0; jt < 16; jt++) {
            pf[jt][0] = exp2_f16x2(accs[jt][0] - nm0, accs[jt][1] - nm0);
            pf[jt][1] = exp2_f16x2(accs[jt][2] - nm8, accs[jt][3] - nm8);
        }

        // in-flight: [V(kb), K(kb+1)] -> wait V(kb)
        CPA_WAIT1();
        __syncthreads();

        // ---- O += P V ; l += P * 1 ----
#pragma unroll
        for (int t = 0; t < 8; t++) {
            uint32_t a[4];
            a[0] = pf[2 * t][0]; a[1] = pf[2 * t][1];
            a[2] = pf[2 * t + 1][0]; a[3] = pf[2 * t + 1][1];
            mma_f16(lacc, a, ONES, ONES);
#pragma unroll
            for (int jn = 0; jn < 8; jn++) {
                uint32_t b0, b1, b2, b3;
                ldsm4(sV + offBv[jn] + t * 32, b0, b1, b2, b3);
                mma_f16(acco[jn * 2 + 0], a, b0, b1);
                mma_f16(acco[jn * 2 + 1], a, b2, b3);
            }
        }
        __syncthreads();     // all warps done reading V

        if (kb + 1 < nkb) load_v(kb + 1);
        CPA_COMMIT();        // group: V(kb+1) -> invariant restored
    }

    // ---- epilogue: packed fp16 for Wo GEMM ----
    float inv0 = 1.f / lacc[0], inv8 = 1.f / lacc[2];
    const int grow0 = row0;
    const int grow8 = row8;
    const int blk   = grow0 >> 7;
    const int rin0  = grow0 & 127;
    const int rin8  = grow8 & 127;
#pragma unroll
    for (int jt = 0; jt < 16; jt++) {
        int ks = h * 2 + (jt >> 3);
        int c8 = jt & 7;
        size_t chunk0 = ((size_t)(blk * 32 + ks) * 128 + rin0) * 8 + (c8 ^ (rin0 & 7));
        size_t chunk8 = ((size_t)(blk * 32 + ks) * 128 + rin8) * 8 + (c8 ^ (rin8 & 7));
        __half2 v0 = __floats2half2_rn(acco[jt][0] * inv0, acco[jt][1] * inv0);
        __half2 v8 = __floats2half2_rn(acco[jt][2] * inv8, acco[jt][3] * inv8);
        *reinterpret_cast<__half2*>(pao + chunk0 * 8 + qd * 2) = v0;
        *reinterpret_cast<__half2*>(pao + chunk8 * 8 + qd * 2) = v8;
    }
}

// ---------------- launch ----------------
extern "C" void kernel_launch(void* const* d_in, const int* in_sizes, int n_in,
                              void* d_out, int out_size)
{
    const float* x  = (const float*)d_in[0];
    const float* rc = (const float*)d_in[1];
    const float* rs = (const float*)d_in[2];
    const float* Wq = (const float*)d_in[3];
    const float* Wk = (const float*)d_in[4];
    const float* Wv = (const float*)d_in[5];
    const float* Wo = (const float*)d_in[6];
    float* out = (float*)d_out;

    __half *px, *pao, *pwq, *pwk, *pwv, *pwo;
    cudaGetSymbolAddress((void**)&px,  g_px);
    cudaGetSymbolAddress((void**)&pao, g_pao);
    cudaGetSymbolAddress((void**)&pwq, g_pwq);
    cudaGetSymbolAddress((void**)&pwk, g_pwk);
    cudaGetSymbolAddress((void**)&pwv, g_pwv);
    cudaGetSymbolAddress((void**)&pwo, g_pwo);

    __half *qh, *kh, *vth;
    cudaGetSymbolAddress((void**)&qh,  g_qh);
    cudaGetSymbolAddress((void**)&kh,  g_kh);
    cudaGetSymbolAddress((void**)&vth, g_vth);

    cudaFuncSetAttribute(gemm_bulk,
                         cudaFuncAttributeMaxDynamicSharedMemorySize, GB_SMEM);
    cudaFuncSetAttribute(gemm_qkv_fused,
                         cudaFuncAttributeMaxDynamicSharedMemorySize, GB_SMEM);
    cudaFuncSetAttribute(flash_mma,
                         cudaFuncAttributeMaxDynamicSharedMemorySize, FA_SMEM);

    // repack inputs (x + 4 weights in one launch)
    conv_pack_all<<<dim3(EMB, 5), 256>>>(x, Wq, Wk, Wv, Wo,
                                         px, pwq, pwk, pwv, pwo);

    // fused QKV projection + RoPE/transpose epilogue (768 CTAs, 2/SM)
    dim3 gq(EMB / 128, S_LEN / 128, 3);
    gemm_qkv_fused<<<gq, 256, GB_SMEM>>>(px, pwq, pwk, pwv, rc, rs,
                                         qh, kh, vth);

    // flash attention (512 CTAs of 64 q-rows, 2/SM) -> packed fp16 pao
    flash_mma<<<dim3(S_LEN / 64, NHEAD), 128, FA_SMEM>>>(qh, kh, vth, pao);

    // output projection
    dim3 gg(EMB / 128, S_LEN / 128);
    gemm_bulk<<<gg, 256, GB_SMEM>>>(pao, pwo, out);
}